// round 4
// baseline (speedup 1.0000x reference)
#include <cuda_runtime.h>

#define BB 16384
#define HH 50
#define DD 64
#define N_ITEMS 100000
#define N_R 5
#define N_PAIRS (N_ITEMS * N_R)
#define NB 6           // batch rows per main CTA
#define NTHR 320       // main kernel threads
#define TAB_THR 320

// ---------------- persistent device tables ----------------
__device__ float4 g_P[N_ITEMS * 16];      // P[item] = W_r1a @ i2e[item]
__device__ float4 g_otab[N_PAIRS * 16];   // o per (item,r)
__device__ float4 g_a1tab[N_PAIRS * 16];  // att1a @ o per (item,r)
__device__ float  g_uatt[BB * DD];
__device__ float  g_ulin[BB * DD];
__device__ float  g_rproj[N_R * DD];

// ---------------- f32x2 helpers ----------------
typedef unsigned long long ull;
__device__ __forceinline__ ull pk2(float a, float b) {
  ull r; asm("mov.b64 %0, {%1,%2};" : "=l"(r) : "f"(a), "f"(b)); return r;
}
__device__ __forceinline__ void upk2(float& a, float& b, ull v) {
  asm("mov.b64 {%0,%1}, %2;" : "=f"(a), "=f"(b) : "l"(v));
}
__device__ __forceinline__ void ffma2(ull& d, ull a, ull b) {
  asm("fma.rn.f32x2 %0, %1, %2, %0;" : "+l"(d) : "l"(a), "l"(b));
}

// Packed GEMV: ACC[p] (+)= sum_k {W[2p][k],W[2p+1][k]} * IN[k]
// W2K: __shared__ float2, layout [k*32 + p], 16B-aligned.
#define GEMV64_P2(ACC, IN, W2K) do {                                    \
    _Pragma("unroll 4")                                                 \
    for (int k_ = 0; k_ < 64; k_++) {                                   \
      ull hd_ = pk2((IN)[k_], (IN)[k_]);                                \
      const ulonglong2* wr_ = (const ulonglong2*)&(W2K)[k_ * 32];       \
      _Pragma("unroll")                                                 \
      for (int q_ = 0; q_ < 16; q_++) {                                 \
        ulonglong2 w_ = wr_[q_];                                        \
        ffma2((ACC)[2 * q_], hd_, w_.x);                                \
        ffma2((ACC)[2 * q_ + 1], hd_, w_.y);                            \
      }                                                                 \
    }                                                                   \
  } while (0)

// ---------------- K_P: P = i2e @ W_r1a^T ----------------
__global__ __launch_bounds__(256) void k_P(
    const float* __restrict__ i2e, const float* __restrict__ wr1) {
  __shared__ float e_s[64 * 68];
  __shared__ float wt[64 * 68];
  const int tid = threadIdx.x;
  const int base = blockIdx.x * 64;
  float* gP = (float*)g_P;

  for (int i = tid; i < 64 * 64; i += 256) {
    int it = i >> 6, k = i & 63;
    int item = base + it;
    e_s[it * 68 + k] = (item < N_ITEMS) ? i2e[(long)item * 64 + k] : 0.0f;
  }
  for (int i = tid; i < 64 * 64; i += 256) {
    int d = i >> 6, k = i & 63;
    wt[k * 68 + d] = wr1[d * 128 + k];
  }
  __syncthreads();

  const int il = tid >> 3;
  const int dq = tid & 7;
  for (int sb = 0; sb < 2; sb++) {
    int it = sb * 32 + il;
    int item = base + it;
    float acc[8];
#pragma unroll
    for (int i = 0; i < 8; i++) acc[i] = 0.0f;
#pragma unroll
    for (int k = 0; k < 64; k++) {
      float ev = e_s[it * 68 + k];
      float4 w0 = *(const float4*)&wt[k * 68 + dq * 8];
      float4 w1 = *(const float4*)&wt[k * 68 + dq * 8 + 4];
      acc[0] = fmaf(ev, w0.x, acc[0]); acc[1] = fmaf(ev, w0.y, acc[1]);
      acc[2] = fmaf(ev, w0.z, acc[2]); acc[3] = fmaf(ev, w0.w, acc[3]);
      acc[4] = fmaf(ev, w1.x, acc[4]); acc[5] = fmaf(ev, w1.y, acc[5]);
      acc[6] = fmaf(ev, w1.z, acc[6]); acc[7] = fmaf(ev, w1.w, acc[7]);
    }
    if (item < N_ITEMS) {
      float4* dst = (float4*)&gP[(long)item * 64 + dq * 8];
      dst[0] = make_float4(acc[0], acc[1], acc[2], acc[3]);
      dst[1] = make_float4(acc[4], acc[5], acc[6], acc[7]);
    }
  }
}

// ---------------- K_R ----------------
__global__ void k_rproj(const float* __restrict__ wr1,
                        const float* __restrict__ wr1b,
                        const float* __restrict__ r2e) {
  int t = threadIdx.x;
  if (t < N_R * 64) {
    int r = t >> 6, d = t & 63;
    float acc = wr1b[d];
#pragma unroll
    for (int k = 0; k < 64; k++)
      acc = fmaf(wr1[d * 128 + 64 + k], r2e[r * 64 + k], acc);
    g_rproj[r * 64 + d] = acc;
  }
}

// ---------------- K_U ----------------
__global__ __launch_bounds__(256) void k_utab(
    const int* __restrict__ nodes, const float* __restrict__ u2e,
    const float* __restrict__ att1, const float* __restrict__ att1b,
    const float* __restrict__ lin1, const float* __restrict__ lin1b) {
  __shared__ float a_s[64 * 65];
  __shared__ float l_s[64 * 65];
  __shared__ float u_s[4 * 64];
  const int t = threadIdx.x;

  for (int i = t; i < 4096; i += 256) {
    int d = i >> 6, k = i & 63;
    a_s[d * 65 + k] = att1[d * 128 + 64 + k];
    l_s[d * 65 + k] = lin1[d * 128 + k];
  }
  const int b0 = blockIdx.x * 64;
  const int bb = t >> 6, d = t & 63;
  for (int it = 0; it < 16; it++) {
    __syncthreads();
    {
      int b = b0 + it * 4 + bb;
      u_s[t] = u2e[(long)nodes[b] * 64 + d];
    }
    __syncthreads();
    const float* uu = &u_s[bb * 64];
    float au = att1b[d], lu = lin1b[d];
#pragma unroll
    for (int k = 0; k < 64; k++) {
      float uv = uu[k];
      au = fmaf(a_s[d * 65 + k], uv, au);
      lu = fmaf(l_s[d * 65 + k], uv, lu);
    }
    int b = b0 + it * 4 + bb;
    g_uatt[b * 64 + d] = au;
    g_ulin[b * 64 + d] = lu;
  }
}

// ---------------- K_TAB: per-(item,r) o and att1a@o, FFMA2 ----------------
__global__ __launch_bounds__(TAB_THR, 1) void k_tab(
    const float* __restrict__ wr2, const float* __restrict__ wr2b,
    const float* __restrict__ att1) {
  __shared__ __align__(16) float2 s_w2k[64 * 32];  // {wr2[2p][k],wr2[2p+1][k]} at [k*32+p]
  __shared__ __align__(16) float2 s_a2k[64 * 32];  // att1[:, :64] pairs
  __shared__ float2 s_b2p[32];
  __shared__ float  s_rp[N_R * 64];
  const int t = threadIdx.x;

  for (int i = t; i < 2048; i += TAB_THR) {
    int k = i >> 5, p = i & 31;
    s_w2k[i] = make_float2(wr2[(2 * p) * 64 + k], wr2[(2 * p + 1) * 64 + k]);
    s_a2k[i] = make_float2(att1[(2 * p) * 128 + k], att1[(2 * p + 1) * 128 + k]);
  }
  if (t < 32) s_b2p[t] = make_float2(wr2b[2 * t], wr2b[2 * t + 1]);
  for (int i = t; i < N_R * 64; i += TAB_THR) s_rp[i] = g_rproj[i];
  __syncthreads();

  long row = (long)blockIdx.x * TAB_THR + t;
  if (row >= N_PAIRS) return;
  int item = (int)(row / 5);
  int r = (int)(row - item * 5);

  // h = relu(P[item] + rproj[r])
  float h[64];
  {
    const float4* Pp = &g_P[item * 16];
    const float4* rp = (const float4*)&s_rp[r * 64];
#pragma unroll
    for (int i = 0; i < 16; i++) {
      float4 p = Pp[i];
      float4 q = rp[i];
      h[4 * i + 0] = fmaxf(p.x + q.x, 0.0f);
      h[4 * i + 1] = fmaxf(p.y + q.y, 0.0f);
      h[4 * i + 2] = fmaxf(p.z + q.z, 0.0f);
      h[4 * i + 3] = fmaxf(p.w + q.w, 0.0f);
    }
  }

  // o = relu(W_r2 @ h + b2)   (packed pairs)
  ull acc[32];
#pragma unroll
  for (int p = 0; p < 32; p++) acc[p] = *(const ull*)&s_b2p[p];
  GEMV64_P2(acc, h, s_w2k);

  float o[64];
#pragma unroll
  for (int p = 0; p < 32; p++) {
    float x, y; upk2(x, y, acc[p]);
    o[2 * p] = fmaxf(x, 0.0f);
    o[2 * p + 1] = fmaxf(y, 0.0f);
  }
  {
    float4* od = &g_otab[row * 16];
#pragma unroll
    for (int i = 0; i < 16; i++)
      od[i] = make_float4(o[4 * i], o[4 * i + 1], o[4 * i + 2], o[4 * i + 3]);
  }

  // a1p = att1a @ o  (packed pairs, no bias/relu)
  ull acc2[32];
#pragma unroll
  for (int p = 0; p < 32; p++) acc2[p] = 0ull;
  GEMV64_P2(acc2, o, s_a2k);
  {
    float a1p[64];
#pragma unroll
    for (int p = 0; p < 32; p++) upk2(a1p[2 * p], a1p[2 * p + 1], acc2[p]);
    float4* ad = &g_a1tab[row * 16];
#pragma unroll
    for (int i = 0; i < 16; i++)
      ad[i] = make_float4(a1p[4 * i], a1p[4 * i + 1], a1p[4 * i + 2], a1p[4 * i + 3]);
  }
}

// ---------------- K_MAIN ----------------
__global__ __launch_bounds__(NTHR, 1) void k_main(
    const int* __restrict__ hui, const int* __restrict__ hr,
    const float* __restrict__ att2w, const float* __restrict__ att2b_,
    const float* __restrict__ att3w, const float* __restrict__ att3b_,
    const float* __restrict__ lin1,
    float* __restrict__ out) {
  __shared__ __align__(16) float2 s_w2k[64 * 32];   // att2 pairs k-major
  __shared__ float2 s_a2bp[32];
  __shared__ float  s_att3[64];
  __shared__ float  s_lin1b[64 * 65];
  __shared__ float  s_uatt[NB * 64], s_ulin[NB * 64];
  __shared__ float  s_logit[NTHR], s_p[NTHR];
  __shared__ int    s_ir[NTHR];
  __shared__ float  s_inv[NB];
  __shared__ float  s_neigh[NB * 64];
  __shared__ float  s_a3b;

  const int t = threadIdx.x;
  const int b0 = blockIdx.x * NB;
  const int nb = min(NB, BB - b0);
  const int ne = nb * HH;

  for (int i = t; i < 2048; i += NTHR) {
    int k = i >> 5, p = i & 31;
    s_w2k[i] = make_float2(att2w[(2 * p) * 64 + k], att2w[(2 * p + 1) * 64 + k]);
  }
  for (int i = t; i < 4096; i += NTHR) {
    int d = i >> 6, k = i & 63;
    s_lin1b[d * 65 + k] = lin1[d * 128 + 64 + k];
  }
  if (t < 64) s_att3[t] = att3w[t];
  if (t < 32) s_a2bp[t] = make_float2(att2b_[2 * t], att2b_[2 * t + 1]);
  if (t == 0) s_a3b = att3b_[0];
  for (int i = t; i < nb * 64; i += NTHR) {
    s_uatt[i] = g_uatt[b0 * 64 + i];
    s_ulin[i] = g_ulin[b0 * 64 + i];
  }
  __syncthreads();

  // ---- edge phase ----
  if (t < ne) {
    const int bl = t / HH;
    const int gid = (b0 + bl) * HH + (t - bl * HH);
    const int ir = hui[gid] * 5 + hr[gid];
    s_ir[t] = ir;

    float a1[64];
    {
      const float4* A = &g_a1tab[(long)ir * 16];
      const float* ua = &s_uatt[bl * 64];
#pragma unroll
      for (int i = 0; i < 16; i++) {
        float4 p = A[i];
        a1[4 * i + 0] = fmaxf(p.x + ua[4 * i + 0], 0.0f);
        a1[4 * i + 1] = fmaxf(p.y + ua[4 * i + 1], 0.0f);
        a1[4 * i + 2] = fmaxf(p.z + ua[4 * i + 2], 0.0f);
        a1[4 * i + 3] = fmaxf(p.w + ua[4 * i + 3], 0.0f);
      }
    }

    ull acc[32];
#pragma unroll
    for (int p = 0; p < 32; p++) acc[p] = *(const ull*)&s_a2bp[p];
    GEMV64_P2(acc, a1, s_w2k);

    float lg = s_a3b;
#pragma unroll
    for (int p = 0; p < 32; p++) {
      float x, y; upk2(x, y, acc[p]);
      lg = fmaf(s_att3[2 * p], fmaxf(x, 0.0f), lg);
      lg = fmaf(s_att3[2 * p + 1], fmaxf(y, 0.0f), lg);
    }
    s_logit[t] = lg;
  }
  __syncthreads();

  // ---- softmax: one warp per batch row ----
  {
    const int wid = t >> 5, lane = t & 31;
    if (wid < nb) {
      const float* L = &s_logit[wid * HH];
      float v1 = L[lane];
      float v2 = (lane < HH - 32) ? L[32 + lane] : -1e30f;
      float m = fmaxf(v1, v2);
#pragma unroll
      for (int off = 16; off > 0; off >>= 1)
        m = fmaxf(m, __shfl_xor_sync(0xffffffffu, m, off));
      float e1 = __expf(v1 - m);
      float e2 = (lane < HH - 32) ? __expf(v2 - m) : 0.0f;
      s_p[wid * HH + lane] = e1;
      if (lane < HH - 32) s_p[wid * HH + 32 + lane] = e2;
      float s = e1 + e2;
#pragma unroll
      for (int off = 16; off > 0; off >>= 1)
        s += __shfl_xor_sync(0xffffffffu, s, off);
      if (lane == 0) s_inv[wid] = 1.0f / s;
    }
  }
  __syncthreads();

  // ---- neigh[b][d] = (sum_h p * o_tab[ir][d]) * inv ----
  const float* otab_f = (const float*)g_otab;
  for (int oi = t; oi < nb * 64; oi += NTHR) {
    int bl = oi >> 6, d = oi & 63;
    const float* pr = &s_p[bl * HH];
    const int* irr = &s_ir[bl * HH];
    float acc = 0.0f;
#pragma unroll 5
    for (int h = 0; h < HH; h++)
      acc = fmaf(pr[h], otab_f[(long)irr[h] * 64 + d], acc);
    s_neigh[oi] = acc * s_inv[bl];
  }
  __syncthreads();

  // ---- out = relu(ulin + lin1[:,64:] @ neigh) ----
  for (int oi = t; oi < nb * 64; oi += NTHR) {
    int bl = oi >> 6, d = oi & 63;
    float acc = s_ulin[oi];
    const float* ng = &s_neigh[bl * 64];
#pragma unroll
    for (int k = 0; k < 64; k++)
      acc = fmaf(s_lin1b[d * 65 + k], ng[k], acc);
    out[(long)(b0 + bl) * 64 + d] = fmaxf(acc, 0.0f);
  }
}

extern "C" void kernel_launch(void* const* d_in, const int* in_sizes, int n_in,
                              void* d_out, int out_size) {
  const int*   nodes = (const int*)d_in[0];
  const int*   hui   = (const int*)d_in[1];
  const int*   hr    = (const int*)d_in[2];
  const float* u2e   = (const float*)d_in[3];
  const float* i2e   = (const float*)d_in[4];
  const float* r2e   = (const float*)d_in[5];
  const float* wr1   = (const float*)d_in[6];
  const float* wr1b  = (const float*)d_in[7];
  const float* wr2   = (const float*)d_in[8];
  const float* wr2b  = (const float*)d_in[9];
  const float* att1  = (const float*)d_in[10];
  const float* att1b = (const float*)d_in[11];
  const float* att2  = (const float*)d_in[12];
  const float* att2b = (const float*)d_in[13];
  const float* att3  = (const float*)d_in[14];
  const float* att3b = (const float*)d_in[15];
  const float* lin1  = (const float*)d_in[16];
  const float* lin1b = (const float*)d_in[17];
  float* out = (float*)d_out;

  k_P<<<(N_ITEMS + 63) / 64, 256>>>(i2e, wr1);
  k_rproj<<<1, 320>>>(wr1, wr1b, r2e);
  k_utab<<<BB / 64, 256>>>(nodes, u2e, att1, att1b, lin1, lin1b);
  k_tab<<<(N_PAIRS + TAB_THR - 1) / TAB_THR, TAB_THR>>>(wr2, wr2b, att1);
  k_main<<<(BB + NB - 1) / NB, NTHR>>>(hui, hr, att2, att2b, att3, att3b, lin1, out);
}

// round 6
// speedup vs baseline: 1.2790x; 1.2790x over previous
#include <cuda_runtime.h>

#define BB 16384
#define HH 50
#define DD 64
#define N_ITEMS 100000
#define N_R 5
#define N_PAIRS (N_ITEMS * N_R)
#define N_EDGES (BB * HH)
#define TAB_M 128
#define AGG_NB 16

// ---------------- persistent device tables ----------------
__device__ float4 g_P[N_ITEMS * 16];      // W_r1a @ i2e[item]
__device__ float4 g_otab[N_PAIRS * 16];   // o per (item,r)
__device__ float4 g_a1tab[N_PAIRS * 16];  // att1a @ o per (item,r)
__device__ float  g_uatt[BB * DD];
__device__ float  g_ulin[BB * DD];
__device__ float  g_rproj[N_R * DD];
__device__ float  g_logit[N_EDGES];

// ---------------- f32x2 helpers ----------------
typedef unsigned long long ull;
__device__ __forceinline__ ull pk2(float a, float b) {
  ull r; asm("mov.b64 %0, {%1,%2};" : "=l"(r) : "f"(a), "f"(b)); return r;
}
__device__ __forceinline__ void upk2(float& a, float& b, ull v) {
  asm("mov.b64 {%0,%1}, %2;" : "=f"(a), "=f"(b) : "l"(v));
}
__device__ __forceinline__ void ffma2(ull& d, ull a, ull b) {
  asm("fma.rn.f32x2 %0, %1, %2, %0;" : "+l"(d) : "l"(a), "l"(b));
}

// Cooperative GEMM inner loop: 128 threads, tile M=128 x N=64, K=64.
// ACT: smem [64][132] (k-major, act[k*132+m]); WPK: smem float2 pairs [64][34].
// Thread (tm=t&15, tn=t>>4): m0=tm*8, pairs p0=tn*4 (n0=tn*8).
// ACC: ull[32] = [mi][pj] packed over n-pairs.
#define GEMM_TILE(ACC, ACT, WPK, M0, P0) do {                              \
    _Pragma("unroll 4")                                                    \
    for (int k_ = 0; k_ < 64; k_++) {                                      \
      float4 a0_ = *(const float4*)&(ACT)[k_ * 132 + (M0)];                \
      float4 a1_ = *(const float4*)&(ACT)[k_ * 132 + (M0) + 4];            \
      ulonglong2 w0_ = *(const ulonglong2*)&(WPK)[k_ * 34 + (P0)];         \
      ulonglong2 w1_ = *(const ulonglong2*)&(WPK)[k_ * 34 + (P0) + 2];     \
      ull am_[8] = {pk2(a0_.x, a0_.x), pk2(a0_.y, a0_.y),                  \
                    pk2(a0_.z, a0_.z), pk2(a0_.w, a0_.w),                  \
                    pk2(a1_.x, a1_.x), pk2(a1_.y, a1_.y),                  \
                    pk2(a1_.z, a1_.z), pk2(a1_.w, a1_.w)};                 \
      ull wv_[4] = {w0_.x, w0_.y, w1_.x, w1_.y};                           \
      _Pragma("unroll")                                                    \
      for (int mi_ = 0; mi_ < 8; mi_++) {                                  \
        _Pragma("unroll")                                                  \
        for (int pj_ = 0; pj_ < 4; pj_++)                                  \
          ffma2((ACC)[mi_ * 4 + pj_], am_[mi_], wv_[pj_]);                 \
      }                                                                    \
    }                                                                      \
  } while (0)

// ---------------- K_P: P = i2e @ W_r1a^T ----------------
__global__ __launch_bounds__(256) void k_P(
    const float* __restrict__ i2e, const float* __restrict__ wr1) {
  __shared__ float e_s[64 * 68];
  __shared__ float wt[64 * 68];
  const int tid = threadIdx.x;
  const int base = blockIdx.x * 64;
  float* gP = (float*)g_P;

  for (int i = tid; i < 64 * 64; i += 256) {
    int it = i >> 6, k = i & 63;
    int item = base + it;
    e_s[it * 68 + k] = (item < N_ITEMS) ? i2e[(long)item * 64 + k] : 0.0f;
  }
  for (int i = tid; i < 64 * 64; i += 256) {
    int d = i >> 6, k = i & 63;
    wt[k * 68 + d] = wr1[d * 128 + k];
  }
  __syncthreads();

  const int il = tid >> 3;
  const int dq = tid & 7;
  for (int sb = 0; sb < 2; sb++) {
    int it = sb * 32 + il;
    int item = base + it;
    float acc[8];
#pragma unroll
    for (int i = 0; i < 8; i++) acc[i] = 0.0f;
#pragma unroll
    for (int k = 0; k < 64; k++) {
      float ev = e_s[it * 68 + k];
      float4 w0 = *(const float4*)&wt[k * 68 + dq * 8];
      float4 w1 = *(const float4*)&wt[k * 68 + dq * 8 + 4];
      acc[0] = fmaf(ev, w0.x, acc[0]); acc[1] = fmaf(ev, w0.y, acc[1]);
      acc[2] = fmaf(ev, w0.z, acc[2]); acc[3] = fmaf(ev, w0.w, acc[3]);
      acc[4] = fmaf(ev, w1.x, acc[4]); acc[5] = fmaf(ev, w1.y, acc[5]);
      acc[6] = fmaf(ev, w1.z, acc[6]); acc[7] = fmaf(ev, w1.w, acc[7]);
    }
    if (item < N_ITEMS) {
      float4* dst = (float4*)&gP[(long)item * 64 + dq * 8];
      dst[0] = make_float4(acc[0], acc[1], acc[2], acc[3]);
      dst[1] = make_float4(acc[4], acc[5], acc[6], acc[7]);
    }
  }
}

// ---------------- K_R ----------------
__global__ void k_rproj(const float* __restrict__ wr1,
                        const float* __restrict__ wr1b,
                        const float* __restrict__ r2e) {
  int t = threadIdx.x;
  if (t < N_R * 64) {
    int r = t >> 6, d = t & 63;
    float acc = wr1b[d];
#pragma unroll
    for (int k = 0; k < 64; k++)
      acc = fmaf(wr1[d * 128 + 64 + k], r2e[r * 64 + k], acc);
    g_rproj[r * 64 + d] = acc;
  }
}

// ---------------- K_U ----------------
__global__ __launch_bounds__(256) void k_utab(
    const int* __restrict__ nodes, const float* __restrict__ u2e,
    const float* __restrict__ att1, const float* __restrict__ att1b,
    const float* __restrict__ lin1, const float* __restrict__ lin1b) {
  __shared__ float a_s[64 * 65];
  __shared__ float l_s[64 * 65];
  __shared__ float u_s[4 * 64];
  const int t = threadIdx.x;

  for (int i = t; i < 4096; i += 256) {
    int d = i >> 6, k = i & 63;
    a_s[d * 65 + k] = att1[d * 128 + 64 + k];
    l_s[d * 65 + k] = lin1[d * 128 + k];
  }
  const int b0 = blockIdx.x * 64;
  const int bb = t >> 6, d = t & 63;
  for (int it = 0; it < 16; it++) {
    __syncthreads();
    {
      int b = b0 + it * 4 + bb;
      u_s[t] = u2e[(long)nodes[b] * 64 + d];
    }
    __syncthreads();
    const float* uu = &u_s[bb * 64];
    float au = att1b[d], lu = lin1b[d];
#pragma unroll
    for (int k = 0; k < 64; k++) {
      float uv = uu[k];
      au = fmaf(a_s[d * 65 + k], uv, au);
      lu = fmaf(l_s[d * 65 + k], uv, lu);
    }
    int b = b0 + it * 4 + bb;
    g_uatt[b * 64 + d] = au;
    g_ulin[b * 64 + d] = lu;
  }
}

// ---------------- K_TAB: cooperative double-GEMM over 128 pair-rows ----------------
// smem floats: H[0..8448) O[8448..16896) Wp[16896..21248) Ap[21248..25600)
//              rp[25600..25920) b2p[25920..25984)
#define TAB_SMEM_FLOATS 25984
__global__ __launch_bounds__(128) void k_tab(
    const float* __restrict__ wr2, const float* __restrict__ wr2b,
    const float* __restrict__ att1) {
  extern __shared__ float sm[];
  float*  H    = sm;
  float*  O    = sm + 8448;
  float2* Wp   = (float2*)(sm + 16896);
  float2* Ap   = (float2*)(sm + 21248);
  float*  s_rp = sm + 25600;
  ull*    s_b2 = (ull*)(sm + 25920);

  const int t = threadIdx.x;

  for (int i = t; i < 2048; i += 128) {
    int k = i >> 5, p = i & 31;
    Wp[k * 34 + p] = make_float2(wr2[(2 * p) * 64 + k], wr2[(2 * p + 1) * 64 + k]);
    Ap[k * 34 + p] = make_float2(att1[(2 * p) * 128 + k], att1[(2 * p + 1) * 128 + k]);
  }
  for (int i = t; i < N_R * 64; i += 128) s_rp[i] = g_rproj[i];
  if (t < 32) s_b2[t] = pk2(wr2b[2 * t], wr2b[2 * t + 1]);
  __syncthreads();   // s_rp (and Wp/Ap/b2) must be fully staged before any thread reads

  // build H[k][m] = relu(P[item] + rproj[r]), m = thread
  {
    long row = (long)blockIdx.x * TAB_M + t;
    long rc = (row < N_PAIRS) ? row : (N_PAIRS - 1);
    int item = (int)(rc / 5);
    int r = (int)(rc - (long)item * 5);
    const float4* Pp = &g_P[(long)item * 16];
    const float4* rp = (const float4*)&s_rp[r * 64];
#pragma unroll
    for (int i = 0; i < 16; i++) {
      float4 p = Pp[i], q = rp[i];
      H[(4 * i + 0) * 132 + t] = fmaxf(p.x + q.x, 0.0f);
      H[(4 * i + 1) * 132 + t] = fmaxf(p.y + q.y, 0.0f);
      H[(4 * i + 2) * 132 + t] = fmaxf(p.z + q.z, 0.0f);
      H[(4 * i + 3) * 132 + t] = fmaxf(p.w + q.w, 0.0f);
    }
  }
  __syncthreads();

  const int tm = t & 15, tn = t >> 4;
  const int m0 = tm * 8, p0 = tn * 4;
  const long rowm0 = (long)blockIdx.x * TAB_M + m0;

  // GEMM1: o = relu(wr2 @ h + b2)
  ull acc[32];
#pragma unroll
  for (int mi = 0; mi < 8; mi++)
#pragma unroll
    for (int pj = 0; pj < 4; pj++) acc[mi * 4 + pj] = s_b2[p0 + pj];
  GEMM_TILE(acc, H, Wp, m0, p0);

  float ov[8][8];
#pragma unroll
  for (int mi = 0; mi < 8; mi++)
#pragma unroll
    for (int pj = 0; pj < 4; pj++) {
      float x, y; upk2(x, y, acc[mi * 4 + pj]);
      ov[mi][2 * pj]     = fmaxf(x, 0.0f);
      ov[mi][2 * pj + 1] = fmaxf(y, 0.0f);
    }
  // O[n][m] (transposed for GEMM2) + gmem o_tab[m][n]
#pragma unroll
  for (int j = 0; j < 8; j++) {
    int n = 2 * p0 + j;
    *(float4*)&O[n * 132 + m0]     = make_float4(ov[0][j], ov[1][j], ov[2][j], ov[3][j]);
    *(float4*)&O[n * 132 + m0 + 4] = make_float4(ov[4][j], ov[5][j], ov[6][j], ov[7][j]);
  }
  {
    float* ot = (float*)g_otab;
#pragma unroll
    for (int mi = 0; mi < 8; mi++) {
      long rr = rowm0 + mi;
      if (rr < N_PAIRS) {
        *(float4*)&ot[rr * 64 + 2 * p0]     = make_float4(ov[mi][0], ov[mi][1], ov[mi][2], ov[mi][3]);
        *(float4*)&ot[rr * 64 + 2 * p0 + 4] = make_float4(ov[mi][4], ov[mi][5], ov[mi][6], ov[mi][7]);
      }
    }
  }
  __syncthreads();

  // GEMM2: a1p = att1a @ o  (no bias, no relu)
  ull acc2[32];
#pragma unroll
  for (int i = 0; i < 32; i++) acc2[i] = 0ull;
  GEMM_TILE(acc2, O, Ap, m0, p0);

  {
    float* at = (float*)g_a1tab;
#pragma unroll
    for (int mi = 0; mi < 8; mi++) {
      long rr = rowm0 + mi;
      if (rr < N_PAIRS) {
        float v[8];
#pragma unroll
        for (int pj = 0; pj < 4; pj++)
          upk2(v[2 * pj], v[2 * pj + 1], acc2[mi * 4 + pj]);
        *(float4*)&at[rr * 64 + 2 * p0]     = make_float4(v[0], v[1], v[2], v[3]);
        *(float4*)&at[rr * 64 + 2 * p0 + 4] = make_float4(v[4], v[5], v[6], v[7]);
      }
    }
  }
}

// ---------------- K_LOGIT: per-edge att2 GEMM + att3 dot ----------------
// smem floats: A[0..8448) Wp[8448..12800) part[12800..13952) bp[13952..14016)
//              a3[14016..14080) a3b[14080]
#define LOG_SMEM_FLOATS 14096
__global__ __launch_bounds__(128) void k_logit(
    const int* __restrict__ hui, const int* __restrict__ hr,
    const float* __restrict__ att2w, const float* __restrict__ att2b_,
    const float* __restrict__ att3w, const float* __restrict__ att3b_) {
  extern __shared__ float sm[];
  float*  A      = sm;
  float2* Wp     = (float2*)(sm + 8448);
  float*  s_part = sm + 12800;   // [128][9]
  ull*    s_bp   = (ull*)(sm + 13952);
  float*  s_a3   = sm + 14016;

  const int t = threadIdx.x;
  for (int i = t; i < 2048; i += 128) {
    int k = i >> 5, p = i & 31;
    Wp[k * 34 + p] = make_float2(att2w[(2 * p) * 64 + k], att2w[(2 * p + 1) * 64 + k]);
  }
  if (t < 32) s_bp[t] = pk2(att2b_[2 * t], att2b_[2 * t + 1]);
  if (t < 64) s_a3[t] = att3w[t];
  if (t == 0) sm[14080] = att3b_[0];

  // build A[k][m] = relu(a1tab[ir] + uatt[b])   (reads gmem only, no smem race)
  const int e = blockIdx.x * 128 + t;
  {
    int b = e / HH;
    int ir = hui[e] * 5 + hr[e];
    const float4* Ag = &g_a1tab[(long)ir * 16];
    const float4* Ug = (const float4*)&g_uatt[b * 64];
#pragma unroll
    for (int i = 0; i < 16; i++) {
      float4 p = Ag[i], q = Ug[i];
      A[(4 * i + 0) * 132 + t] = fmaxf(p.x + q.x, 0.0f);
      A[(4 * i + 1) * 132 + t] = fmaxf(p.y + q.y, 0.0f);
      A[(4 * i + 2) * 132 + t] = fmaxf(p.z + q.z, 0.0f);
      A[(4 * i + 3) * 132 + t] = fmaxf(p.w + q.w, 0.0f);
    }
  }
  __syncthreads();

  const int tm = t & 15, tn = t >> 4;
  const int m0 = tm * 8, p0 = tn * 4;

  ull acc[32];
#pragma unroll
  for (int mi = 0; mi < 8; mi++)
#pragma unroll
    for (int pj = 0; pj < 4; pj++) acc[mi * 4 + pj] = s_bp[p0 + pj];
  GEMM_TILE(acc, A, Wp, m0, p0);

  // partial logit: sum over this thread's 8 n of att3[n]*relu(c)
#pragma unroll
  for (int mi = 0; mi < 8; mi++) {
    float part = 0.0f;
#pragma unroll
    for (int pj = 0; pj < 4; pj++) {
      float x, y; upk2(x, y, acc[mi * 4 + pj]);
      part = fmaf(s_a3[2 * p0 + 2 * pj],     fmaxf(x, 0.0f), part);
      part = fmaf(s_a3[2 * p0 + 2 * pj + 1], fmaxf(y, 0.0f), part);
    }
    s_part[(m0 + mi) * 9 + tn] = part;
  }
  __syncthreads();

  {
    float lg = sm[14080];
#pragma unroll
    for (int j = 0; j < 8; j++) lg += s_part[t * 9 + j];
    g_logit[e] = lg;
  }
}

// ---------------- K_AGG: softmax + weighted o-sum + final linear ----------------
__global__ __launch_bounds__(256) void k_agg(
    const int* __restrict__ hui, const int* __restrict__ hr,
    const float* __restrict__ lin1, float* __restrict__ out) {
  __shared__ float s_lin[64 * 65];
  __shared__ float s_lg[AGG_NB * HH];
  __shared__ float s_pp[AGG_NB * HH];
  __shared__ int   s_ir[AGG_NB * HH];
  __shared__ float s_inv[AGG_NB];
  __shared__ float s_ng[AGG_NB * 64];
  __shared__ float s_ul[AGG_NB * 64];

  const int t = threadIdx.x;
  const int b0 = blockIdx.x * AGG_NB;

  for (int i = t; i < 4096; i += 256) {
    int d = i >> 6, k = i & 63;
    s_lin[d * 65 + k] = lin1[d * 128 + 64 + k];
  }
  for (int i = t; i < AGG_NB * HH; i += 256) {
    int e = b0 * HH + i;
    s_lg[i] = g_logit[e];
    s_ir[i] = hui[e] * 5 + hr[e];
  }
  for (int i = t; i < AGG_NB * 64; i += 256) s_ul[i] = g_ulin[b0 * 64 + i];
  __syncthreads();

  {
    const int wid = t >> 5, lane = t & 31;
#pragma unroll
    for (int rr = 0; rr < 2; rr++) {
      int rowb = wid * 2 + rr;
      const float* L = &s_lg[rowb * HH];
      float v1 = L[lane];
      float v2 = (lane < HH - 32) ? L[32 + lane] : -1e30f;
      float m = fmaxf(v1, v2);
#pragma unroll
      for (int off = 16; off > 0; off >>= 1)
        m = fmaxf(m, __shfl_xor_sync(0xffffffffu, m, off));
      float e1 = __expf(v1 - m);
      float e2 = (lane < HH - 32) ? __expf(v2 - m) : 0.0f;
      s_pp[rowb * HH + lane] = e1;
      if (lane < HH - 32) s_pp[rowb * HH + 32 + lane] = e2;
      float s = e1 + e2;
#pragma unroll
      for (int off = 16; off > 0; off >>= 1)
        s += __shfl_xor_sync(0xffffffffu, s, off);
      if (lane == 0) s_inv[rowb] = 1.0f / s;
    }
  }
  __syncthreads();

  const float* ot = (const float*)g_otab;
  for (int oi = t; oi < AGG_NB * 64; oi += 256) {
    int bl = oi >> 6, d = oi & 63;
    const float* pr = &s_pp[bl * HH];
    const int* irr = &s_ir[bl * HH];
    float acc = 0.0f;
#pragma unroll 5
    for (int h = 0; h < HH; h++)
      acc = fmaf(pr[h], ot[(long)irr[h] * 64 + d], acc);
    s_ng[oi] = acc * s_inv[bl];
  }
  __syncthreads();

  for (int oi = t; oi < AGG_NB * 64; oi += 256) {
    int bl = oi >> 6, d = oi & 63;
    float acc = s_ul[oi];
    const float* ng = &s_ng[bl * 64];
#pragma unroll
    for (int k = 0; k < 64; k++)
      acc = fmaf(s_lin[d * 65 + k], ng[k], acc);
    out[(long)(b0 + bl) * 64 + d] = fmaxf(acc, 0.0f);
  }
}

extern "C" void kernel_launch(void* const* d_in, const int* in_sizes, int n_in,
                              void* d_out, int out_size) {
  const int*   nodes = (const int*)d_in[0];
  const int*   hui   = (const int*)d_in[1];
  const int*   hr    = (const int*)d_in[2];
  const float* u2e   = (const float*)d_in[3];
  const float* i2e   = (const float*)d_in[4];
  const float* r2e   = (const float*)d_in[5];
  const float* wr1   = (const float*)d_in[6];
  const float* wr1b  = (const float*)d_in[7];
  const float* wr2   = (const float*)d_in[8];
  const float* wr2b  = (const float*)d_in[9];
  const float* att1  = (const float*)d_in[10];
  const float* att1b = (const float*)d_in[11];
  const float* att2  = (const float*)d_in[12];
  const float* att2b = (const float*)d_in[13];
  const float* att3  = (const float*)d_in[14];
  const float* att3b = (const float*)d_in[15];
  const float* lin1  = (const float*)d_in[16];
  const float* lin1b = (const float*)d_in[17];
  float* out = (float*)d_out;

  cudaFuncSetAttribute(k_tab, cudaFuncAttributeMaxDynamicSharedMemorySize,
                       TAB_SMEM_FLOATS * 4);
  cudaFuncSetAttribute(k_logit, cudaFuncAttributeMaxDynamicSharedMemorySize,
                       LOG_SMEM_FLOATS * 4);

  k_P<<<(N_ITEMS + 63) / 64, 256>>>(i2e, wr1);
  k_rproj<<<1, 320>>>(wr1, wr1b, r2e);
  k_utab<<<BB / 64, 256>>>(nodes, u2e, att1, att1b, lin1, lin1b);
  k_tab<<<(N_PAIRS + TAB_M - 1) / TAB_M, 128, TAB_SMEM_FLOATS * 4>>>(wr2, wr2b, att1);
  k_logit<<<N_EDGES / 128, 128, LOG_SMEM_FLOATS * 4>>>(hui, hr, att2, att2b, att3, att3b);
  k_agg<<<BB / AGG_NB, 256>>>(hui, hr, lin1, out);
}

// round 9
// speedup vs baseline: 1.8204x; 1.4233x over previous
#include <cuda_runtime.h>
#include <cuda_bf16.h>
#include <cstdint>

#define BB 16384
#define HH 50
#define N_ITEMS 100000
#define N_R 5
#define N_PAIRS (N_ITEMS * N_R)
#define N_EDGES (BB * HH)
#define AGG_NB 16

// ---------------- persistent device tables ----------------
__device__ float4 g_P[N_ITEMS * 16];       // W_r1a @ i2e[item]
__device__ float4 g_otab[N_PAIRS * 16];    // o per (item,r)
__device__ float4 g_a1tab[N_PAIRS * 16];   // att1a @ o per (item,r)
__device__ float  g_uatt[BB * 64];
__device__ float  g_ulin[BB * 64];
__device__ float  g_rproj[N_R * 64];
__device__ float  g_logit[N_EDGES];

// ---------------- helpers ----------------
__device__ __forceinline__ uint32_t smem_u32(const void* p) {
  uint32_t a;
  asm("{ .reg .u64 t; cvta.to.shared.u64 t, %1; cvt.u32.u64 %0, t; }" : "=r"(a) : "l"(p));
  return a;
}
__device__ __forceinline__ void split2(float x, float& hi, float& lo) {
  __nv_bfloat16 h = __float2bfloat16_rn(x);
  hi = __bfloat162float(h);
  lo = x - hi;
}
__device__ __forceinline__ uint32_t pack_bf16(float a, float b) {
  __nv_bfloat162 h = __floats2bfloat162_rn(a, b);
  return *(uint32_t*)&h;
}
// bf16 tile rows: 64 cols = 128B = 8 chunks of 16B; swizzle chunk ^= (row&7)
__device__ __forceinline__ void st_pair(char* base, int row, int cp, uint32_t v) {
  int col = cp * 2;
  uint32_t off = row * 128 + ((((col >> 3) ^ row) & 7) << 4) + ((col & 7) << 1);
  *(uint32_t*)(base + off) = v;
}
__device__ __forceinline__ void ldsm4(uint32_t& r0, uint32_t& r1, uint32_t& r2,
                                      uint32_t& r3, uint32_t addr) {
  asm volatile("ldmatrix.sync.aligned.m8n8.x4.shared.b16 {%0,%1,%2,%3}, [%4];"
               : "=r"(r0), "=r"(r1), "=r"(r2), "=r"(r3) : "r"(addr));
}
__device__ __forceinline__ void mma16816(float* c, const uint32_t* a, const uint32_t* b) {
  asm volatile(
      "mma.sync.aligned.m16n8k16.row.col.f32.bf16.bf16.f32 "
      "{%0,%1,%2,%3}, {%4,%5,%6,%7}, {%8,%9}, {%0,%1,%2,%3};"
      : "+f"(c[0]), "+f"(c[1]), "+f"(c[2]), "+f"(c[3])
      : "r"(a[0]), "r"(a[1]), "r"(a[2]), "r"(a[3]), "r"(b[0]), "r"(b[1]));
}

// Warp GEMM: C[32x64] += A[32x64] @ B[64x64]^T via 3-term hi/lo bf16.
// aH/aL/bH/bL = smem u32 bases of swizzled bf16 tiles ([row][64] 128B rows).
__device__ __forceinline__ void warp_gemm64(float c[2][8][4], uint32_t aH, uint32_t aL,
                                            uint32_t bH, uint32_t bL, int m0, int lane) {
  const int r = lane & 7, sel = lane >> 3;
  const int arow = r + (sel & 1) * 8, ach = sel >> 1;
  const int brow = r + (sel >> 1) * 8, bch = sel & 1;
#pragma unroll
  for (int mt = 0; mt < 2; mt++)
#pragma unroll
    for (int nt = 0; nt < 8; nt++)
#pragma unroll
      for (int i = 0; i < 4; i++) c[mt][nt][i] = 0.0f;

#pragma unroll
  for (int term = 0; term < 3; term++) {
    uint32_t Ab = (term == 2) ? aL : aH;
    uint32_t Bb = (term == 1) ? bL : bH;
#pragma unroll
    for (int ks = 0; ks < 4; ks++) {
      uint32_t b[4][4];
#pragma unroll
      for (int nb = 0; nb < 4; nb++) {
        int rowb = nb * 16 + brow;
        int ch = 2 * ks + bch;
        ldsm4(b[nb][0], b[nb][1], b[nb][2], b[nb][3],
              Bb + rowb * 128 + (((ch ^ rowb) & 7) << 4));
      }
#pragma unroll
      for (int mt = 0; mt < 2; mt++) {
        int rowa = m0 + mt * 16 + arow;
        int ch = 2 * ks + ach;
        uint32_t a[4];
        ldsm4(a[0], a[1], a[2], a[3],
              Ab + rowa * 128 + (((ch ^ rowa) & 7) << 4));
#pragma unroll
        for (int nt = 0; nt < 8; nt++)
          mma16816(c[mt][nt], a, &b[nt >> 1][(nt & 1) * 2]);
      }
    }
  }
}

// ---------------- K_P: P = i2e @ W_r1a^T ----------------
__global__ __launch_bounds__(256) void k_P(
    const float* __restrict__ i2e, const float* __restrict__ wr1) {
  __shared__ float e_s[64 * 68];
  __shared__ float wt[64 * 68];
  const int tid = threadIdx.x;
  const int base = blockIdx.x * 64;
  float* gP = (float*)g_P;

  for (int i = tid; i < 64 * 64; i += 256) {
    int it = i >> 6, k = i & 63;
    int item = base + it;
    e_s[it * 68 + k] = (item < N_ITEMS) ? i2e[(long)item * 64 + k] : 0.0f;
  }
  for (int i = tid; i < 64 * 64; i += 256) {
    int d = i >> 6, k = i & 63;
    wt[k * 68 + d] = wr1[d * 128 + k];
  }
  __syncthreads();

  const int il = tid >> 3;
  const int dq = tid & 7;
  for (int sb = 0; sb < 2; sb++) {
    int it = sb * 32 + il;
    int item = base + it;
    float acc[8];
#pragma unroll
    for (int i = 0; i < 8; i++) acc[i] = 0.0f;
#pragma unroll
    for (int k = 0; k < 64; k++) {
      float ev = e_s[it * 68 + k];
      float4 w0 = *(const float4*)&wt[k * 68 + dq * 8];
      float4 w1 = *(const float4*)&wt[k * 68 + dq * 8 + 4];
      acc[0] = fmaf(ev, w0.x, acc[0]); acc[1] = fmaf(ev, w0.y, acc[1]);
      acc[2] = fmaf(ev, w0.z, acc[2]); acc[3] = fmaf(ev, w0.w, acc[3]);
      acc[4] = fmaf(ev, w1.x, acc[4]); acc[5] = fmaf(ev, w1.y, acc[5]);
      acc[6] = fmaf(ev, w1.z, acc[6]); acc[7] = fmaf(ev, w1.w, acc[7]);
    }
    if (item < N_ITEMS) {
      float4* dst = (float4*)&gP[(long)item * 64 + dq * 8];
      dst[0] = make_float4(acc[0], acc[1], acc[2], acc[3]);
      dst[1] = make_float4(acc[4], acc[5], acc[6], acc[7]);
    }
  }
}

// ---------------- K_R ----------------
__global__ void k_rproj(const float* __restrict__ wr1,
                        const float* __restrict__ wr1b,
                        const float* __restrict__ r2e) {
  int t = threadIdx.x;
  if (t < N_R * 64) {
    int r = t >> 6, d = t & 63;
    float acc = wr1b[d];
#pragma unroll
    for (int k = 0; k < 64; k++)
      acc = fmaf(wr1[d * 128 + 64 + k], r2e[r * 64 + k], acc);
    g_rproj[r * 64 + d] = acc;
  }
}

// ---------------- K_U ----------------
__global__ __launch_bounds__(256) void k_utab(
    const int* __restrict__ nodes, const float* __restrict__ u2e,
    const float* __restrict__ att1, const float* __restrict__ att1b,
    const float* __restrict__ lin1, const float* __restrict__ lin1b) {
  __shared__ float a_s[64 * 65];
  __shared__ float l_s[64 * 65];
  __shared__ float u_s[4 * 64];
  const int t = threadIdx.x;

  for (int i = t; i < 4096; i += 256) {
    int d = i >> 6, k = i & 63;
    a_s[d * 65 + k] = att1[d * 128 + 64 + k];
    l_s[d * 65 + k] = lin1[d * 128 + k];
  }
  const int b0 = blockIdx.x * 64;
  const int bb = t >> 6, d = t & 63;
  for (int it = 0; it < 16; it++) {
    __syncthreads();
    {
      int b = b0 + it * 4 + bb;
      u_s[t] = u2e[(long)nodes[b] * 64 + d];
    }
    __syncthreads();
    const float* uu = &u_s[bb * 64];
    float au = att1b[d], lu = lin1b[d];
#pragma unroll
    for (int k = 0; k < 64; k++) {
      float uv = uu[k];
      au = fmaf(a_s[d * 65 + k], uv, au);
      lu = fmaf(l_s[d * 65 + k], uv, lu);
    }
    int b = b0 + it * 4 + bb;
    g_uatt[b * 64 + d] = au;
    g_ulin[b * 64 + d] = lu;
  }
}

// ---------------- K_TAB (mma.sync): per-(item,r) o and att1a@o ----------------
// A tile is 128 rows x 128B = 16384 bytes (hi AND lo) — offsets must not overlap.
#define TB_AH 0
#define TB_AL 16384
#define TB_W1H 32768
#define TB_W1L 40960
#define TB_W2H 49152
#define TB_W2L 57344
#define TB_RP 65536
#define TB_B2 66816
#define TB_TOTAL 67072

__global__ __launch_bounds__(128) void k_tab_mma(
    const float* __restrict__ wr2, const float* __restrict__ wr2b,
    const float* __restrict__ att1) {
  extern __shared__ char smc[];
  const int t = threadIdx.x;
  const int lane = t & 31, w = t >> 5;
  uint32_t sb = smem_u32(smc);

  // stage weights (hi/lo bf16 swizzled tiles) + rproj + b2
  for (int i = t; i < 2048; i += 128) {
    int n = i >> 5, c2 = i & 31;
    float h0, l0, h1, l1;
    split2(wr2[n * 64 + 2 * c2], h0, l0);
    split2(wr2[n * 64 + 2 * c2 + 1], h1, l1);
    st_pair(smc + TB_W1H, n, c2, pack_bf16(h0, h1));
    st_pair(smc + TB_W1L, n, c2, pack_bf16(l0, l1));
    split2(att1[n * 128 + 2 * c2], h0, l0);
    split2(att1[n * 128 + 2 * c2 + 1], h1, l1);
    st_pair(smc + TB_W2H, n, c2, pack_bf16(h0, h1));
    st_pair(smc + TB_W2L, n, c2, pack_bf16(l0, l1));
  }
  for (int i = t; i < N_R * 64; i += 128) ((float*)(smc + TB_RP))[i] = g_rproj[i];
  if (t < 64) ((float*)(smc + TB_B2))[t] = wr2b[t];
  __syncthreads();

  // build H row t: h = relu(P[item] + rproj[r]) -> hi/lo bf16 tiles
  long row = (long)blockIdx.x * 128 + t;
  long rc = (row < N_PAIRS) ? row : (N_PAIRS - 1);
  int item = (int)(rc / 5);
  int rr_ = (int)(rc - (long)item * 5);
  {
    const float4* Pp = &g_P[(long)item * 16];
    const float* rp = (const float*)(smc + TB_RP) + rr_ * 64;
#pragma unroll
    for (int i = 0; i < 16; i++) {
      float4 p = Pp[i];
      float v0 = fmaxf(p.x + rp[4 * i + 0], 0.f);
      float v1 = fmaxf(p.y + rp[4 * i + 1], 0.f);
      float v2 = fmaxf(p.z + rp[4 * i + 2], 0.f);
      float v3 = fmaxf(p.w + rp[4 * i + 3], 0.f);
      float h0, l0, h1, l1;
      split2(v0, h0, l0); split2(v1, h1, l1);
      st_pair(smc + TB_AH, t, 2 * i, pack_bf16(h0, h1));
      st_pair(smc + TB_AL, t, 2 * i, pack_bf16(l0, l1));
      split2(v2, h0, l0); split2(v3, h1, l1);
      st_pair(smc + TB_AH, t, 2 * i + 1, pack_bf16(h0, h1));
      st_pair(smc + TB_AL, t, 2 * i + 1, pack_bf16(l0, l1));
    }
  }
  __syncwarp();   // warp w's GEMM reads only rows w*32..w*32+31 (its own threads)

  const int m0 = w * 32;
  const int g = lane >> 2, q = lane & 3;
  const long blk0 = (long)blockIdx.x * 128;

  // GEMM1: o = relu(H @ wr2^T + b2)
  float c[2][8][4];
  warp_gemm64(c, sb + TB_AH, sb + TB_AL, sb + TB_W1H, sb + TB_W1L, m0, lane);

  const float* b2 = (const float*)(smc + TB_B2);
  float* ot = (float*)g_otab;
#pragma unroll
  for (int mt = 0; mt < 2; mt++)
#pragma unroll
    for (int half = 0; half < 2; half++) {
      int lr = m0 + mt * 16 + g + half * 8;
      long rowg = blk0 + lr;
#pragma unroll
      for (int nt = 0; nt < 8; nt++) {
        int col = nt * 8 + q * 2;
        float v0 = fmaxf(c[mt][nt][half * 2 + 0] + b2[col], 0.f);
        float v1 = fmaxf(c[mt][nt][half * 2 + 1] + b2[col + 1], 0.f);
        if (rowg < N_PAIRS)
          *(float2*)&ot[rowg * 64 + col] = make_float2(v0, v1);
        float h0, l0, h1, l1;
        split2(v0, h0, l0); split2(v1, h1, l1);
        st_pair(smc + TB_AH, lr, nt * 4 + q, pack_bf16(h0, h1));
        st_pair(smc + TB_AL, lr, nt * 4 + q, pack_bf16(l0, l1));
      }
    }
  __syncwarp();

  // GEMM2: a1p = O @ att1a^T
  warp_gemm64(c, sb + TB_AH, sb + TB_AL, sb + TB_W2H, sb + TB_W2L, m0, lane);
  float* at = (float*)g_a1tab;
#pragma unroll
  for (int mt = 0; mt < 2; mt++)
#pragma unroll
    for (int half = 0; half < 2; half++) {
      int lr = m0 + mt * 16 + g + half * 8;
      long rowg = blk0 + lr;
      if (rowg < N_PAIRS) {
#pragma unroll
        for (int nt = 0; nt < 8; nt++) {
          int col = nt * 8 + q * 2;
          *(float2*)&at[rowg * 64 + col] =
              make_float2(c[mt][nt][half * 2 + 0], c[mt][nt][half * 2 + 1]);
        }
      }
    }
}

// ---------------- K_LOGIT (mma.sync): per-edge att2 GEMM + att3 dot ----------------
#define LB_AH 0
#define LB_AL 16384
#define LB_WH 32768
#define LB_WL 40960
#define LB_A3 49152
#define LB_A2B 49408
#define LB_A3B 49664
#define LB_TOTAL 49680

__global__ __launch_bounds__(128) void k_logit_mma(
    const int* __restrict__ hui, const int* __restrict__ hr,
    const float* __restrict__ att2w, const float* __restrict__ att2b_,
    const float* __restrict__ att3w, const float* __restrict__ att3b_) {
  extern __shared__ char smc[];
  const int t = threadIdx.x;
  const int lane = t & 31, w = t >> 5;
  uint32_t sb = smem_u32(smc);

  for (int i = t; i < 2048; i += 128) {
    int n = i >> 5, c2 = i & 31;
    float h0, l0, h1, l1;
    split2(att2w[n * 64 + 2 * c2], h0, l0);
    split2(att2w[n * 64 + 2 * c2 + 1], h1, l1);
    st_pair(smc + LB_WH, n, c2, pack_bf16(h0, h1));
    st_pair(smc + LB_WL, n, c2, pack_bf16(l0, l1));
  }
  if (t < 64) {
    ((float*)(smc + LB_A3))[t] = att3w[t];
    ((float*)(smc + LB_A2B))[t] = att2b_[t];
  }
  if (t == 0) *(float*)(smc + LB_A3B) = att3b_[0];
  __syncthreads();

  // build A row t: a1 = relu(a1tab[ir] + uatt[b])
  const int e = blockIdx.x * 128 + t;
  {
    int b = e / HH;
    long ir = (long)hui[e] * 5 + hr[e];
    const float4* Ag = &g_a1tab[ir * 16];
    const float4* Ug = (const float4*)&g_uatt[b * 64];
#pragma unroll
    for (int i = 0; i < 16; i++) {
      float4 p = Ag[i], qv = Ug[i];
      float v0 = fmaxf(p.x + qv.x, 0.f), v1 = fmaxf(p.y + qv.y, 0.f);
      float v2 = fmaxf(p.z + qv.z, 0.f), v3 = fmaxf(p.w + qv.w, 0.f);
      float h0, l0, h1, l1;
      split2(v0, h0, l0); split2(v1, h1, l1);
      st_pair(smc + LB_AH, t, 2 * i, pack_bf16(h0, h1));
      st_pair(smc + LB_AL, t, 2 * i, pack_bf16(l0, l1));
      split2(v2, h0, l0); split2(v3, h1, l1);
      st_pair(smc + LB_AH, t, 2 * i + 1, pack_bf16(h0, h1));
      st_pair(smc + LB_AL, t, 2 * i + 1, pack_bf16(l0, l1));
    }
  }
  __syncwarp();

  const int m0 = w * 32;
  float c[2][8][4];
  warp_gemm64(c, sb + LB_AH, sb + LB_AL, sb + LB_WH, sb + LB_WL, m0, lane);

  const float* a3 = (const float*)(smc + LB_A3);
  const float* a2b = (const float*)(smc + LB_A2B);
  const float a3b = *(const float*)(smc + LB_A3B);
  const int g = lane >> 2, q = lane & 3;
  const int blk0 = blockIdx.x * 128;
#pragma unroll
  for (int mt = 0; mt < 2; mt++)
#pragma unroll
    for (int half = 0; half < 2; half++) {
      int lr = m0 + mt * 16 + g + half * 8;
      float part = 0.0f;
#pragma unroll
      for (int nt = 0; nt < 8; nt++) {
        int col = nt * 8 + q * 2;
        part = fmaf(a3[col], fmaxf(c[mt][nt][half * 2 + 0] + a2b[col], 0.f), part);
        part = fmaf(a3[col + 1], fmaxf(c[mt][nt][half * 2 + 1] + a2b[col + 1], 0.f), part);
      }
      part += __shfl_xor_sync(0xffffffffu, part, 1);
      part += __shfl_xor_sync(0xffffffffu, part, 2);
      if (q == 0) g_logit[blk0 + lr] = part + a3b;
    }
}

// ---------------- K_AGG: softmax + weighted o-sum + final linear ----------------
__global__ __launch_bounds__(256) void k_agg(
    const int* __restrict__ hui, const int* __restrict__ hr,
    const float* __restrict__ lin1, float* __restrict__ out) {
  __shared__ float s_lin[64 * 65];
  __shared__ float s_lg[AGG_NB * HH];
  __shared__ float s_pp[AGG_NB * HH];
  __shared__ int   s_ir[AGG_NB * HH];
  __shared__ float s_inv[AGG_NB];
  __shared__ float s_ng[AGG_NB * 64];
  __shared__ float s_ul[AGG_NB * 64];

  const int t = threadIdx.x;
  const int b0 = blockIdx.x * AGG_NB;

  for (int i = t; i < 4096; i += 256) {
    int d = i >> 6, k = i & 63;
    s_lin[d * 65 + k] = lin1[d * 128 + 64 + k];
  }
  for (int i = t; i < AGG_NB * HH; i += 256) {
    int e = b0 * HH + i;
    s_lg[i] = g_logit[e];
    s_ir[i] = hui[e] * 5 + hr[e];
  }
  for (int i = t; i < AGG_NB * 64; i += 256) s_ul[i] = g_ulin[b0 * 64 + i];
  __syncthreads();

  {
    const int wid = t >> 5, lane = t & 31;
#pragma unroll
    for (int rr = 0; rr < 2; rr++) {
      int rowb = wid * 2 + rr;
      const float* L = &s_lg[rowb * HH];
      float v1 = L[lane];
      float v2 = (lane < HH - 32) ? L[32 + lane] : -1e30f;
      float m = fmaxf(v1, v2);
#pragma unroll
      for (int off = 16; off > 0; off >>= 1)
        m = fmaxf(m, __shfl_xor_sync(0xffffffffu, m, off));
      float e1 = __expf(v1 - m);
      float e2 = (lane < HH - 32) ? __expf(v2 - m) : 0.0f;
      s_pp[rowb * HH + lane] = e1;
      if (lane < HH - 32) s_pp[rowb * HH + 32 + lane] = e2;
      float s = e1 + e2;
#pragma unroll
      for (int off = 16; off > 0; off >>= 1)
        s += __shfl_xor_sync(0xffffffffu, s, off);
      if (lane == 0) s_inv[rowb] = 1.0f / s;
    }
  }
  __syncthreads();

  const float* ot = (const float*)g_otab;
  for (int oi = t; oi < AGG_NB * 64; oi += 256) {
    int bl = oi >> 6, d = oi & 63;
    const float* pr = &s_pp[bl * HH];
    const int* irr = &s_ir[bl * HH];
    float acc = 0.0f;
#pragma unroll 5
    for (int h = 0; h < HH; h++)
      acc = fmaf(pr[h], ot[(long)irr[h] * 64 + d], acc);
    s_ng[oi] = acc * s_inv[bl];
  }
  __syncthreads();

  for (int oi = t; oi < AGG_NB * 64; oi += 256) {
    int bl = oi >> 6, d = oi & 63;
    float acc = s_ul[oi];
    const float* ng = &s_ng[bl * 64];
#pragma unroll
    for (int k = 0; k < 64; k++)
      acc = fmaf(s_lin[d * 65 + k], ng[k], acc);
    out[(long)(b0 + bl) * 64 + d] = fmaxf(acc, 0.0f);
  }
}

extern "C" void kernel_launch(void* const* d_in, const int* in_sizes, int n_in,
                              void* d_out, int out_size) {
  const int*   nodes = (const int*)d_in[0];
  const int*   hui   = (const int*)d_in[1];
  const int*   hr    = (const int*)d_in[2];
  const float* u2e   = (const float*)d_in[3];
  const float* i2e   = (const float*)d_in[4];
  const float* r2e   = (const float*)d_in[5];
  const float* wr1   = (const float*)d_in[6];
  const float* wr1b  = (const float*)d_in[7];
  const float* wr2   = (const float*)d_in[8];
  const float* wr2b  = (const float*)d_in[9];
  const float* att1  = (const float*)d_in[10];
  const float* att1b = (const float*)d_in[11];
  const float* att2  = (const float*)d_in[12];
  const float* att2b = (const float*)d_in[13];
  const float* att3  = (const float*)d_in[14];
  const float* att3b = (const float*)d_in[15];
  const float* lin1  = (const float*)d_in[16];
  const float* lin1b = (const float*)d_in[17];
  float* out = (float*)d_out;

  cudaFuncSetAttribute(k_tab_mma, cudaFuncAttributeMaxDynamicSharedMemorySize, TB_TOTAL);
  cudaFuncSetAttribute(k_logit_mma, cudaFuncAttributeMaxDynamicSharedMemorySize, LB_TOTAL);

  k_P<<<(N_ITEMS + 63) / 64, 256>>>(i2e, wr1);
  k_rproj<<<1, 320>>>(wr1, wr1b, r2e);
  k_utab<<<BB / 64, 256>>>(nodes, u2e, att1, att1b, lin1, lin1b);
  k_tab_mma<<<(N_PAIRS + 127) / 128, 128, TB_TOTAL>>>(wr2, wr2b, att1);
  k_logit_mma<<<N_EDGES / 128, 128, LB_TOTAL>>>(hui, hr, att2, att2b, att3, att3b);
  k_agg<<<BB / AGG_NB, 256>>>(hui, hr, lin1, out);
}

// round 10
// speedup vs baseline: 1.9306x; 1.0605x over previous
#include <cuda_runtime.h>
#include <cuda_bf16.h>
#include <cstdint>

#define BB 16384
#define HH 50
#define N_ITEMS 100000
#define N_R 5
#define N_PAIRS (N_ITEMS * N_R)
#define N_EDGES (BB * HH)
#define AGG_NB 16

// ---------------- persistent device tables ----------------
__device__ float4 g_P[N_ITEMS * 16];       // W_r1a @ i2e[item]
__device__ float4 g_otab[N_PAIRS * 16];    // o per (item,r)
__device__ float4 g_a1tab[N_PAIRS * 16];   // att1a @ o per (item,r)
__device__ float  g_uatt[BB * 64];
__device__ float  g_ulin[BB * 64];
__device__ float  g_rproj[N_R * 64];
__device__ float  g_logit[N_EDGES];

// ---------------- helpers ----------------
__device__ __forceinline__ uint32_t smem_u32(const void* p) {
  uint32_t a;
  asm("{ .reg .u64 t; cvta.to.shared.u64 t, %1; cvt.u32.u64 %0, t; }" : "=r"(a) : "l"(p));
  return a;
}
__device__ __forceinline__ void split2(float x, float& hi, float& lo) {
  __nv_bfloat16 h = __float2bfloat16_rn(x);
  hi = __bfloat162float(h);
  lo = x - hi;
}
__device__ __forceinline__ uint32_t pack_bf16(float a, float b) {
  __nv_bfloat162 h = __floats2bfloat162_rn(a, b);
  return *(uint32_t*)&h;
}
// bf16 tile rows: 64 cols = 128B = 8 chunks of 16B; swizzle chunk ^= (row&7)
__device__ __forceinline__ void st_pair(char* base, int row, int cp, uint32_t v) {
  int col = cp * 2;
  uint32_t off = row * 128 + ((((col >> 3) ^ row) & 7) << 4) + ((col & 7) << 1);
  *(uint32_t*)(base + off) = v;
}
__device__ __forceinline__ void ldsm4(uint32_t& r0, uint32_t& r1, uint32_t& r2,
                                      uint32_t& r3, uint32_t addr) {
  asm volatile("ldmatrix.sync.aligned.m8n8.x4.shared.b16 {%0,%1,%2,%3}, [%4];"
               : "=r"(r0), "=r"(r1), "=r"(r2), "=r"(r3) : "r"(addr));
}
__device__ __forceinline__ void mma16816(float* c, const uint32_t* a, const uint32_t* b) {
  asm volatile(
      "mma.sync.aligned.m16n8k16.row.col.f32.bf16.bf16.f32 "
      "{%0,%1,%2,%3}, {%4,%5,%6,%7}, {%8,%9}, {%0,%1,%2,%3};"
      : "+f"(c[0]), "+f"(c[1]), "+f"(c[2]), "+f"(c[3])
      : "r"(a[0]), "r"(a[1]), "r"(a[2]), "r"(a[3]), "r"(b[0]), "r"(b[1]));
}

// Warp GEMM: C[32x32] += A[32rows x 64k] @ B[32rows x 64k]^T, 3-term hi/lo bf16.
// A rows m0..m0+31, B (weight) rows n0..n0+31.
__device__ __forceinline__ void warp_gemm_32x32(float c[2][4][4], uint32_t aH, uint32_t aL,
                                                uint32_t bH, uint32_t bL, int m0, int n0,
                                                int lane) {
  const int r = lane & 7, sel = lane >> 3;
  const int arow = r + (sel & 1) * 8, ach = sel >> 1;
  const int brow = r + (sel >> 1) * 8, bch = sel & 1;
#pragma unroll
  for (int mt = 0; mt < 2; mt++)
#pragma unroll
    for (int nt = 0; nt < 4; nt++)
#pragma unroll
      for (int i = 0; i < 4; i++) c[mt][nt][i] = 0.0f;

#pragma unroll
  for (int term = 0; term < 3; term++) {
    uint32_t Ab = (term == 2) ? aL : aH;
    uint32_t Bb = (term == 1) ? bL : bH;
#pragma unroll
    for (int ks = 0; ks < 4; ks++) {
      uint32_t b[2][4];
#pragma unroll
      for (int nb = 0; nb < 2; nb++) {
        int rowb = n0 + nb * 16 + brow;
        int ch = 2 * ks + bch;
        ldsm4(b[nb][0], b[nb][1], b[nb][2], b[nb][3],
              Bb + rowb * 128 + (((ch ^ rowb) & 7) << 4));
      }
#pragma unroll
      for (int mt = 0; mt < 2; mt++) {
        int rowa = m0 + mt * 16 + arow;
        int ch = 2 * ks + ach;
        uint32_t a[4];
        ldsm4(a[0], a[1], a[2], a[3],
              Ab + rowa * 128 + (((ch ^ rowa) & 7) << 4));
#pragma unroll
        for (int nt = 0; nt < 4; nt++)
          mma16816(c[mt][nt], a, &b[nt >> 1][(nt & 1) * 2]);
      }
    }
  }
}

// ---------------- K_P: P = i2e @ W_r1a^T ----------------
__global__ __launch_bounds__(256) void k_P(
    const float* __restrict__ i2e, const float* __restrict__ wr1) {
  __shared__ float e_s[64 * 68];
  __shared__ float wt[64 * 68];
  const int tid = threadIdx.x;
  const int base = blockIdx.x * 64;
  float* gP = (float*)g_P;

  for (int i = tid; i < 64 * 64; i += 256) {
    int it = i >> 6, k = i & 63;
    int item = base + it;
    e_s[it * 68 + k] = (item < N_ITEMS) ? i2e[(long)item * 64 + k] : 0.0f;
  }
  for (int i = tid; i < 64 * 64; i += 256) {
    int d = i >> 6, k = i & 63;
    wt[k * 68 + d] = wr1[d * 128 + k];
  }
  __syncthreads();

  const int il = tid >> 3;
  const int dq = tid & 7;
  for (int sb = 0; sb < 2; sb++) {
    int it = sb * 32 + il;
    int item = base + it;
    float acc[8];
#pragma unroll
    for (int i = 0; i < 8; i++) acc[i] = 0.0f;
#pragma unroll
    for (int k = 0; k < 64; k++) {
      float ev = e_s[it * 68 + k];
      float4 w0 = *(const float4*)&wt[k * 68 + dq * 8];
      float4 w1 = *(const float4*)&wt[k * 68 + dq * 8 + 4];
      acc[0] = fmaf(ev, w0.x, acc[0]); acc[1] = fmaf(ev, w0.y, acc[1]);
      acc[2] = fmaf(ev, w0.z, acc[2]); acc[3] = fmaf(ev, w0.w, acc[3]);
      acc[4] = fmaf(ev, w1.x, acc[4]); acc[5] = fmaf(ev, w1.y, acc[5]);
      acc[6] = fmaf(ev, w1.z, acc[6]); acc[7] = fmaf(ev, w1.w, acc[7]);
    }
    if (item < N_ITEMS) {
      float4* dst = (float4*)&gP[(long)item * 64 + dq * 8];
      dst[0] = make_float4(acc[0], acc[1], acc[2], acc[3]);
      dst[1] = make_float4(acc[4], acc[5], acc[6], acc[7]);
    }
  }
}

// ---------------- K_R ----------------
__global__ void k_rproj(const float* __restrict__ wr1,
                        const float* __restrict__ wr1b,
                        const float* __restrict__ r2e) {
  int t = threadIdx.x;
  if (t < N_R * 64) {
    int r = t >> 6, d = t & 63;
    float acc = wr1b[d];
#pragma unroll
    for (int k = 0; k < 64; k++)
      acc = fmaf(wr1[d * 128 + 64 + k], r2e[r * 64 + k], acc);
    g_rproj[r * 64 + d] = acc;
  }
}

// ---------------- K_U ----------------
__global__ __launch_bounds__(256) void k_utab(
    const int* __restrict__ nodes, const float* __restrict__ u2e,
    const float* __restrict__ att1, const float* __restrict__ att1b,
    const float* __restrict__ lin1, const float* __restrict__ lin1b) {
  __shared__ float a_s[64 * 65];
  __shared__ float l_s[64 * 65];
  __shared__ float u_s[4 * 64];
  const int t = threadIdx.x;

  for (int i = t; i < 4096; i += 256) {
    int d = i >> 6, k = i & 63;
    a_s[d * 65 + k] = att1[d * 128 + 64 + k];
    l_s[d * 65 + k] = lin1[d * 128 + k];
  }
  const int b0 = blockIdx.x * 64;
  const int bb = t >> 6, d = t & 63;
  for (int it = 0; it < 16; it++) {
    __syncthreads();
    {
      int b = b0 + it * 4 + bb;
      u_s[t] = u2e[(long)nodes[b] * 64 + d];
    }
    __syncthreads();
    const float* uu = &u_s[bb * 64];
    float au = att1b[d], lu = lin1b[d];
#pragma unroll
    for (int k = 0; k < 64; k++) {
      float uv = uu[k];
      au = fmaf(a_s[d * 65 + k], uv, au);
      lu = fmaf(l_s[d * 65 + k], uv, lu);
    }
    int b = b0 + it * 4 + bb;
    g_uatt[b * 64 + d] = au;
    g_ulin[b * 64 + d] = lu;
  }
}

// ---------------- K_TAB (mma.sync, 256 thr, N-split warp tiles) ----------------
#define TB_AH 0
#define TB_AL 16384
#define TB_W1H 32768
#define TB_W1L 40960
#define TB_W2H 49152
#define TB_W2L 57344
#define TB_RP 65536
#define TB_B2 66816
#define TB_TOTAL 67072

__global__ __launch_bounds__(256, 2) void k_tab_mma(
    const float* __restrict__ wr2, const float* __restrict__ wr2b,
    const float* __restrict__ att1) {
  extern __shared__ char smc[];
  const int t = threadIdx.x;
  const int lane = t & 31, w = t >> 5;
  uint32_t sb = smem_u32(smc);

  // stage weights (hi/lo bf16 swizzled tiles) + rproj + b2
  for (int i = t; i < 2048; i += 256) {
    int n = i >> 5, c2 = i & 31;
    float h0, l0, h1, l1;
    split2(wr2[n * 64 + 2 * c2], h0, l0);
    split2(wr2[n * 64 + 2 * c2 + 1], h1, l1);
    st_pair(smc + TB_W1H, n, c2, pack_bf16(h0, h1));
    st_pair(smc + TB_W1L, n, c2, pack_bf16(l0, l1));
    split2(att1[n * 128 + 2 * c2], h0, l0);
    split2(att1[n * 128 + 2 * c2 + 1], h1, l1);
    st_pair(smc + TB_W2H, n, c2, pack_bf16(h0, h1));
    st_pair(smc + TB_W2L, n, c2, pack_bf16(l0, l1));
  }
  for (int i = t; i < N_R * 64; i += 256) ((float*)(smc + TB_RP))[i] = g_rproj[i];
  if (t < 64) ((float*)(smc + TB_B2))[t] = wr2b[t];
  __syncthreads();

  // build H: 2 threads per row (each does one 32-col half)
  const int rowi = t & 127;
  const int chalf = t >> 7;
  const long blk0 = (long)blockIdx.x * 128;
  long row = blk0 + rowi;
  long rc = (row < N_PAIRS) ? row : (N_PAIRS - 1);
  int item = (int)(rc / 5);
  int rr_ = (int)(rc - (long)item * 5);
  {
    const float4* Pp = &g_P[(long)item * 16 + chalf * 8];
    const float* rp = (const float*)(smc + TB_RP) + rr_ * 64 + chalf * 32;
#pragma unroll
    for (int i = 0; i < 8; i++) {
      float4 p = Pp[i];
      float v0 = fmaxf(p.x + rp[4 * i + 0], 0.f);
      float v1 = fmaxf(p.y + rp[4 * i + 1], 0.f);
      float v2 = fmaxf(p.z + rp[4 * i + 2], 0.f);
      float v3 = fmaxf(p.w + rp[4 * i + 3], 0.f);
      int cp = chalf * 16 + 2 * i;
      float h0, l0, h1, l1;
      split2(v0, h0, l0); split2(v1, h1, l1);
      st_pair(smc + TB_AH, rowi, cp, pack_bf16(h0, h1));
      st_pair(smc + TB_AL, rowi, cp, pack_bf16(l0, l1));
      split2(v2, h0, l0); split2(v3, h1, l1);
      st_pair(smc + TB_AH, rowi, cp + 1, pack_bf16(h0, h1));
      st_pair(smc + TB_AL, rowi, cp + 1, pack_bf16(l0, l1));
    }
  }
  __syncthreads();

  const int mh = w & 3, nh = w >> 2;
  const int m0 = mh * 32, n0 = nh * 32;
  const int g = lane >> 2, q = lane & 3;

  // GEMM1: o = relu(H @ wr2^T + b2)
  float c[2][4][4];
  warp_gemm_32x32(c, sb + TB_AH, sb + TB_AL, sb + TB_W1H, sb + TB_W1L, m0, n0, lane);
  __syncthreads();   // all warps done reading H before overwriting A tiles

  const float* b2 = (const float*)(smc + TB_B2);
  float* ot = (float*)g_otab;
#pragma unroll
  for (int mt = 0; mt < 2; mt++)
#pragma unroll
    for (int half = 0; half < 2; half++) {
      int lr = m0 + mt * 16 + g + half * 8;
      long rowg = blk0 + lr;
#pragma unroll
      for (int nt = 0; nt < 4; nt++) {
        int col = n0 + nt * 8 + q * 2;
        float v0 = fmaxf(c[mt][nt][half * 2 + 0] + b2[col], 0.f);
        float v1 = fmaxf(c[mt][nt][half * 2 + 1] + b2[col + 1], 0.f);
        if (rowg < N_PAIRS)
          *(float2*)&ot[rowg * 64 + col] = make_float2(v0, v1);
        float h0, l0, h1, l1;
        split2(v0, h0, l0); split2(v1, h1, l1);
        st_pair(smc + TB_AH, lr, col >> 1, pack_bf16(h0, h1));
        st_pair(smc + TB_AL, lr, col >> 1, pack_bf16(l0, l1));
      }
    }
  __syncthreads();   // O tiles complete before GEMM2 reads full K

  // GEMM2: a1p = O @ att1a^T
  warp_gemm_32x32(c, sb + TB_AH, sb + TB_AL, sb + TB_W2H, sb + TB_W2L, m0, n0, lane);
  float* at = (float*)g_a1tab;
#pragma unroll
  for (int mt = 0; mt < 2; mt++)
#pragma unroll
    for (int half = 0; half < 2; half++) {
      int lr = m0 + mt * 16 + g + half * 8;
      long rowg = blk0 + lr;
      if (rowg < N_PAIRS) {
#pragma unroll
        for (int nt = 0; nt < 4; nt++) {
          int col = n0 + nt * 8 + q * 2;
          *(float2*)&at[rowg * 64 + col] =
              make_float2(c[mt][nt][half * 2 + 0], c[mt][nt][half * 2 + 1]);
        }
      }
    }
}

// ---------------- K_LOGIT (mma.sync, 256 thr, N-split) ----------------
#define LB_AH 0
#define LB_AL 16384
#define LB_WH 32768
#define LB_WL 40960
#define LB_A3 49152
#define LB_A2B 49408
#define LB_A3B 49664
#define LB_PART 49680
#define LB_TOTAL 50704

__global__ __launch_bounds__(256, 2) void k_logit_mma(
    const int* __restrict__ hui, const int* __restrict__ hr,
    const float* __restrict__ att2w, const float* __restrict__ att2b_,
    const float* __restrict__ att3w, const float* __restrict__ att3b_) {
  extern __shared__ char smc[];
  const int t = threadIdx.x;
  const int lane = t & 31, w = t >> 5;
  uint32_t sb = smem_u32(smc);

  for (int i = t; i < 2048; i += 256) {
    int n = i >> 5, c2 = i & 31;
    float h0, l0, h1, l1;
    split2(att2w[n * 64 + 2 * c2], h0, l0);
    split2(att2w[n * 64 + 2 * c2 + 1], h1, l1);
    st_pair(smc + LB_WH, n, c2, pack_bf16(h0, h1));
    st_pair(smc + LB_WL, n, c2, pack_bf16(l0, l1));
  }
  if (t < 64) {
    ((float*)(smc + LB_A3))[t] = att3w[t];
    ((float*)(smc + LB_A2B))[t] = att2b_[t];
  }
  if (t == 0) *(float*)(smc + LB_A3B) = att3b_[0];

  // build A: 2 threads per row (each does one 32-col half)
  const int rowi = t & 127;
  const int chalf = t >> 7;
  const int e = blockIdx.x * 128 + rowi;
  {
    int b = e / HH;
    long ir = (long)hui[e] * 5 + hr[e];
    const float4* Ag = &g_a1tab[ir * 16 + chalf * 8];
    const float4* Ug = (const float4*)&g_uatt[b * 64] + chalf * 8;
#pragma unroll
    for (int i = 0; i < 8; i++) {
      float4 p = Ag[i], qv = Ug[i];
      float v0 = fmaxf(p.x + qv.x, 0.f), v1 = fmaxf(p.y + qv.y, 0.f);
      float v2 = fmaxf(p.z + qv.z, 0.f), v3 = fmaxf(p.w + qv.w, 0.f);
      int cp = chalf * 16 + 2 * i;
      float h0, l0, h1, l1;
      split2(v0, h0, l0); split2(v1, h1, l1);
      st_pair(smc + LB_AH, rowi, cp, pack_bf16(h0, h1));
      st_pair(smc + LB_AL, rowi, cp, pack_bf16(l0, l1));
      split2(v2, h0, l0); split2(v3, h1, l1);
      st_pair(smc + LB_AH, rowi, cp + 1, pack_bf16(h0, h1));
      st_pair(smc + LB_AL, rowi, cp + 1, pack_bf16(l0, l1));
    }
  }
  __syncthreads();

  const int mh = w & 3, nh = w >> 2;
  const int m0 = mh * 32, n0 = nh * 32;
  const int g = lane >> 2, q = lane & 3;

  float c[2][4][4];
  warp_gemm_32x32(c, sb + LB_AH, sb + LB_AL, sb + LB_WH, sb + LB_WL, m0, n0, lane);

  const float* a3 = (const float*)(smc + LB_A3);
  const float* a2b = (const float*)(smc + LB_A2B);
  const float a3b = *(const float*)(smc + LB_A3B);
  float* part = (float*)(smc + LB_PART);
#pragma unroll
  for (int mt = 0; mt < 2; mt++)
#pragma unroll
    for (int half = 0; half < 2; half++) {
      int lr = m0 + mt * 16 + g + half * 8;
      float pt = 0.0f;
#pragma unroll
      for (int nt = 0; nt < 4; nt++) {
        int col = n0 + nt * 8 + q * 2;
        pt = fmaf(a3[col], fmaxf(c[mt][nt][half * 2 + 0] + a2b[col], 0.f), pt);
        pt = fmaf(a3[col + 1], fmaxf(c[mt][nt][half * 2 + 1] + a2b[col + 1], 0.f), pt);
      }
      pt += __shfl_xor_sync(0xffffffffu, pt, 1);
      pt += __shfl_xor_sync(0xffffffffu, pt, 2);
      if (q == 0) part[lr * 2 + nh] = pt;
    }
  __syncthreads();

  if (t < 128)
    g_logit[blockIdx.x * 128 + t] = part[t * 2] + part[t * 2 + 1] + a3b;
}

// ---------------- K_AGG: softmax + weighted o-sum + final linear ----------------
__global__ __launch_bounds__(256) void k_agg(
    const int* __restrict__ hui, const int* __restrict__ hr,
    const float* __restrict__ lin1, float* __restrict__ out) {
  __shared__ float s_lin[64 * 65];
  __shared__ float s_lg[AGG_NB * HH];
  __shared__ float s_pp[AGG_NB * HH];
  __shared__ int   s_ir[AGG_NB * HH];
  __shared__ float s_inv[AGG_NB];
  __shared__ float s_ng[AGG_NB * 64];
  __shared__ float s_ul[AGG_NB * 64];

  const int t = threadIdx.x;
  const int b0 = blockIdx.x * AGG_NB;

  for (int i = t; i < 4096; i += 256) {
    int d = i >> 6, k = i & 63;
    s_lin[d * 65 + k] = lin1[d * 128 + 64 + k];
  }
  for (int i = t; i < AGG_NB * HH; i += 256) {
    int e = b0 * HH + i;
    s_lg[i] = g_logit[e];
    s_ir[i] = hui[e] * 5 + hr[e];
  }
  for (int i = t; i < AGG_NB * 64; i += 256) s_ul[i] = g_ulin[b0 * 64 + i];
  __syncthreads();

  {
    const int wid = t >> 5, lane = t & 31;
#pragma unroll
    for (int rr = 0; rr < 2; rr++) {
      int rowb = wid * 2 + rr;
      const float* L = &s_lg[rowb * HH];
      float v1 = L[lane];
      float v2 = (lane < HH - 32) ? L[32 + lane] : -1e30f;
      float m = fmaxf(v1, v2);
#pragma unroll
      for (int off = 16; off > 0; off >>= 1)
        m = fmaxf(m, __shfl_xor_sync(0xffffffffu, m, off));
      float e1 = __expf(v1 - m);
      float e2 = (lane < HH - 32) ? __expf(v2 - m) : 0.0f;
      s_pp[rowb * HH + lane] = e1;
      if (lane < HH - 32) s_pp[rowb * HH + 32 + lane] = e2;
      float s = e1 + e2;
#pragma unroll
      for (int off = 16; off > 0; off >>= 1)
        s += __shfl_xor_sync(0xffffffffu, s, off);
      if (lane == 0) s_inv[rowb] = 1.0f / s;
    }
  }
  __syncthreads();

  const float* ot = (const float*)g_otab;
  for (int oi = t; oi < AGG_NB * 64; oi += 256) {
    int bl = oi >> 6, d = oi & 63;
    const float* pr = &s_pp[bl * HH];
    const int* irr = &s_ir[bl * HH];
    float acc = 0.0f;
#pragma unroll 5
    for (int h = 0; h < HH; h++)
      acc = fmaf(pr[h], ot[(long)irr[h] * 64 + d], acc);
    s_ng[oi] = acc * s_inv[bl];
  }
  __syncthreads();

  for (int oi = t; oi < AGG_NB * 64; oi += 256) {
    int bl = oi >> 6, d = oi & 63;
    float acc = s_ul[oi];
    const float* ng = &s_ng[bl * 64];
#pragma unroll
    for (int k = 0; k < 64; k++)
      acc = fmaf(s_lin[d * 65 + k], ng[k], acc);
    out[(long)(b0 + bl) * 64 + d] = fmaxf(acc, 0.0f);
  }
}

extern "C" void kernel_launch(void* const* d_in, const int* in_sizes, int n_in,
                              void* d_out, int out_size) {
  const int*   nodes = (const int*)d_in[0];
  const int*   hui   = (const int*)d_in[1];
  const int*   hr    = (const int*)d_in[2];
  const float* u2e   = (const float*)d_in[3];
  const float* i2e   = (const float*)d_in[4];
  const float* r2e   = (const float*)d_in[5];
  const float* wr1   = (const float*)d_in[6];
  const float* wr1b  = (const float*)d_in[7];
  const float* wr2   = (const float*)d_in[8];
  const float* wr2b  = (const float*)d_in[9];
  const float* att1  = (const float*)d_in[10];
  const float* att1b = (const float*)d_in[11];
  const float* att2  = (const float*)d_in[12];
  const float* att2b = (const float*)d_in[13];
  const float* att3  = (const float*)d_in[14];
  const float* att3b = (const float*)d_in[15];
  const float* lin1  = (const float*)d_in[16];
  const float* lin1b = (const float*)d_in[17];
  float* out = (float*)d_out;

  cudaFuncSetAttribute(k_tab_mma, cudaFuncAttributeMaxDynamicSharedMemorySize, TB_TOTAL);
  cudaFuncSetAttribute(k_logit_mma, cudaFuncAttributeMaxDynamicSharedMemorySize, LB_TOTAL);

  k_P<<<(N_ITEMS + 63) / 64, 256>>>(i2e, wr1);
  k_rproj<<<1, 320>>>(wr1, wr1b, r2e);
  k_utab<<<BB / 64, 256>>>(nodes, u2e, att1, att1b, lin1, lin1b);
  k_tab_mma<<<(N_PAIRS + 127) / 128, 256, TB_TOTAL>>>(wr2, wr2b, att1);
  k_logit_mma<<<N_EDGES / 128, 256, LB_TOTAL>>>(hui, hr, att2, att2b, att3, att3b);
  k_agg<<<BB / AGG_NB, 256>>>(hui, hr, lin1, out);
}

// round 11
// speedup vs baseline: 2.1394x; 1.1081x over previous
#include <cuda_runtime.h>
#include <cuda_bf16.h>
#include <cstdint>

#define BB 16384
#define HH 50
#define N_ITEMS 100000
#define N_R 5
#define N_PAIRS (N_ITEMS * N_R)
#define N_EDGES (BB * HH)
#define AGG_NB 16
#define N_TAB_TILES ((N_PAIRS + 127) / 128)
#define N_LOG_TILES (N_EDGES / 128)
#define PERSIST_GRID 296

// ---------------- persistent device tables ----------------
__device__ float4 g_P[N_ITEMS * 16];       // W_r1a @ i2e[item]
__device__ float4 g_otab[N_PAIRS * 16];    // o per (item,r)
__device__ float4 g_a1tab[N_PAIRS * 16];   // att1a @ o per (item,r)
__device__ float  g_uatt[BB * 64];
__device__ float  g_ulin[BB * 64];
__device__ float  g_rproj[N_R * 64];
__device__ float  g_logit[N_EDGES];

// ---------------- helpers ----------------
__device__ __forceinline__ uint32_t smem_u32(const void* p) {
  uint32_t a;
  asm("{ .reg .u64 t; cvta.to.shared.u64 t, %1; cvt.u32.u64 %0, t; }" : "=r"(a) : "l"(p));
  return a;
}
__device__ __forceinline__ void split2(float x, float& hi, float& lo) {
  __nv_bfloat16 h = __float2bfloat16_rn(x);
  hi = __bfloat162float(h);
  lo = x - hi;
}
__device__ __forceinline__ uint32_t pack_bf16(float a, float b) {
  __nv_bfloat162 h = __floats2bfloat162_rn(a, b);
  return *(uint32_t*)&h;
}
// bf16 tile rows: 64 cols = 128B = 8 chunks of 16B; swizzle chunk ^= (row&7)
__device__ __forceinline__ void st_pair(char* base, int row, int cp, uint32_t v) {
  int col = cp * 2;
  uint32_t off = row * 128 + ((((col >> 3) ^ row) & 7) << 4) + ((col & 7) << 1);
  *(uint32_t*)(base + off) = v;
}
// 8-byte store of 4 bf16 cols (col4 % 4 == 0 -> 8B aligned within chunk)
__device__ __forceinline__ void st_quad(char* base, int row, int col4,
                                        uint32_t v0, uint32_t v1) {
  uint32_t off = row * 128 + ((((col4 >> 3) ^ row) & 7) << 4) + ((col4 & 7) << 1);
  *(uint2*)(base + off) = make_uint2(v0, v1);
}
__device__ __forceinline__ void ldsm4(uint32_t& r0, uint32_t& r1, uint32_t& r2,
                                      uint32_t& r3, uint32_t addr) {
  asm volatile("ldmatrix.sync.aligned.m8n8.x4.shared.b16 {%0,%1,%2,%3}, [%4];"
               : "=r"(r0), "=r"(r1), "=r"(r2), "=r"(r3) : "r"(addr));
}
__device__ __forceinline__ void mma16816(float* c, const uint32_t* a, const uint32_t* b) {
  asm volatile(
      "mma.sync.aligned.m16n8k16.row.col.f32.bf16.bf16.f32 "
      "{%0,%1,%2,%3}, {%4,%5,%6,%7}, {%8,%9}, {%0,%1,%2,%3};"
      : "+f"(c[0]), "+f"(c[1]), "+f"(c[2]), "+f"(c[3])
      : "r"(a[0]), "r"(a[1]), "r"(a[2]), "r"(a[3]), "r"(b[0]), "r"(b[1]));
}

// Warp GEMM: C[32x32] += A[32rows x 64k] @ B[32rows x 64k]^T, 3-term hi/lo bf16.
__device__ __forceinline__ void warp_gemm_32x32(float c[2][4][4], uint32_t aH, uint32_t aL,
                                                uint32_t bH, uint32_t bL, int m0, int n0,
                                                int lane) {
  const int r = lane & 7, sel = lane >> 3;
  const int arow = r + (sel & 1) * 8, ach = sel >> 1;
  const int brow = r + (sel >> 1) * 8, bch = sel & 1;
#pragma unroll
  for (int mt = 0; mt < 2; mt++)
#pragma unroll
    for (int nt = 0; nt < 4; nt++)
#pragma unroll
      for (int i = 0; i < 4; i++) c[mt][nt][i] = 0.0f;

#pragma unroll
  for (int term = 0; term < 3; term++) {
    uint32_t Ab = (term == 2) ? aL : aH;
    uint32_t Bb = (term == 1) ? bL : bH;
#pragma unroll
    for (int ks = 0; ks < 4; ks++) {
      uint32_t b[2][4];
#pragma unroll
      for (int nb = 0; nb < 2; nb++) {
        int rowb = n0 + nb * 16 + brow;
        int ch = 2 * ks + bch;
        ldsm4(b[nb][0], b[nb][1], b[nb][2], b[nb][3],
              Bb + rowb * 128 + (((ch ^ rowb) & 7) << 4));
      }
#pragma unroll
      for (int mt = 0; mt < 2; mt++) {
        int rowa = m0 + mt * 16 + arow;
        int ch = 2 * ks + ach;
        uint32_t a[4];
        ldsm4(a[0], a[1], a[2], a[3],
              Ab + rowa * 128 + (((ch ^ rowa) & 7) << 4));
#pragma unroll
        for (int nt = 0; nt < 4; nt++)
          mma16816(c[mt][nt], a, &b[nt >> 1][(nt & 1) * 2]);
      }
    }
  }
}

// ---------------- K_P: P = i2e @ W_r1a^T ----------------
__global__ __launch_bounds__(256) void k_P(
    const float* __restrict__ i2e, const float* __restrict__ wr1) {
  __shared__ float e_s[64 * 68];
  __shared__ float wt[64 * 68];
  const int tid = threadIdx.x;
  const int base = blockIdx.x * 64;
  float* gP = (float*)g_P;

  for (int i = tid; i < 64 * 64; i += 256) {
    int it = i >> 6, k = i & 63;
    int item = base + it;
    e_s[it * 68 + k] = (item < N_ITEMS) ? i2e[(long)item * 64 + k] : 0.0f;
  }
  for (int i = tid; i < 64 * 64; i += 256) {
    int d = i >> 6, k = i & 63;
    wt[k * 68 + d] = wr1[d * 128 + k];
  }
  __syncthreads();

  const int il = tid >> 3;
  const int dq = tid & 7;
  for (int sb = 0; sb < 2; sb++) {
    int it = sb * 32 + il;
    int item = base + it;
    float acc[8];
#pragma unroll
    for (int i = 0; i < 8; i++) acc[i] = 0.0f;
#pragma unroll
    for (int k = 0; k < 64; k++) {
      float ev = e_s[it * 68 + k];
      float4 w0 = *(const float4*)&wt[k * 68 + dq * 8];
      float4 w1 = *(const float4*)&wt[k * 68 + dq * 8 + 4];
      acc[0] = fmaf(ev, w0.x, acc[0]); acc[1] = fmaf(ev, w0.y, acc[1]);
      acc[2] = fmaf(ev, w0.z, acc[2]); acc[3] = fmaf(ev, w0.w, acc[3]);
      acc[4] = fmaf(ev, w1.x, acc[4]); acc[5] = fmaf(ev, w1.y, acc[5]);
      acc[6] = fmaf(ev, w1.z, acc[6]); acc[7] = fmaf(ev, w1.w, acc[7]);
    }
    if (item < N_ITEMS) {
      float4* dst = (float4*)&gP[(long)item * 64 + dq * 8];
      dst[0] = make_float4(acc[0], acc[1], acc[2], acc[3]);
      dst[1] = make_float4(acc[4], acc[5], acc[6], acc[7]);
    }
  }
}

// ---------------- K_R ----------------
__global__ void k_rproj(const float* __restrict__ wr1,
                        const float* __restrict__ wr1b,
                        const float* __restrict__ r2e) {
  int t = threadIdx.x;
  if (t < N_R * 64) {
    int r = t >> 6, d = t & 63;
    float acc = wr1b[d];
#pragma unroll
    for (int k = 0; k < 64; k++)
      acc = fmaf(wr1[d * 128 + 64 + k], r2e[r * 64 + k], acc);
    g_rproj[r * 64 + d] = acc;
  }
}

// ---------------- K_U ----------------
__global__ __launch_bounds__(256) void k_utab(
    const int* __restrict__ nodes, const float* __restrict__ u2e,
    const float* __restrict__ att1, const float* __restrict__ att1b,
    const float* __restrict__ lin1, const float* __restrict__ lin1b) {
  __shared__ float a_s[64 * 65];
  __shared__ float l_s[64 * 65];
  __shared__ float u_s[4 * 64];
  const int t = threadIdx.x;

  for (int i = t; i < 4096; i += 256) {
    int d = i >> 6, k = i & 63;
    a_s[d * 65 + k] = att1[d * 128 + 64 + k];
    l_s[d * 65 + k] = lin1[d * 128 + k];
  }
  const int b0 = blockIdx.x * 64;
  const int bb = t >> 6, d = t & 63;
  for (int it = 0; it < 16; it++) {
    __syncthreads();
    {
      int b = b0 + it * 4 + bb;
      u_s[t] = u2e[(long)nodes[b] * 64 + d];
    }
    __syncthreads();
    const float* uu = &u_s[bb * 64];
    float au = att1b[d], lu = lin1b[d];
#pragma unroll
    for (int k = 0; k < 64; k++) {
      float uv = uu[k];
      au = fmaf(a_s[d * 65 + k], uv, au);
      lu = fmaf(l_s[d * 65 + k], uv, lu);
    }
    int b = b0 + it * 4 + bb;
    g_uatt[b * 64 + d] = au;
    g_ulin[b * 64 + d] = lu;
  }
}

// ---------------- K_TAB (mma.sync, persistent, separate O tiles) ----------------
#define TB_AH 0
#define TB_AL 16384
#define TB_OH 32768
#define TB_OL 49152
#define TB_W1H 65536
#define TB_W1L 73728
#define TB_W2H 81920
#define TB_W2L 90112
#define TB_RP 98304
#define TB_B2 99584
#define TB_TOTAL 99840

__global__ __launch_bounds__(256, 2) void k_tab_mma(
    const float* __restrict__ wr2, const float* __restrict__ wr2b,
    const float* __restrict__ att1) {
  extern __shared__ char smc[];
  const int t = threadIdx.x;
  const int lane = t & 31, w = t >> 5;
  uint32_t sb = smem_u32(smc);

  // stage weights ONCE per CTA
  for (int i = t; i < 2048; i += 256) {
    int n = i >> 5, c2 = i & 31;
    float h0, l0, h1, l1;
    split2(wr2[n * 64 + 2 * c2], h0, l0);
    split2(wr2[n * 64 + 2 * c2 + 1], h1, l1);
    st_pair(smc + TB_W1H, n, c2, pack_bf16(h0, h1));
    st_pair(smc + TB_W1L, n, c2, pack_bf16(l0, l1));
    split2(att1[n * 128 + 2 * c2], h0, l0);
    split2(att1[n * 128 + 2 * c2 + 1], h1, l1);
    st_pair(smc + TB_W2H, n, c2, pack_bf16(h0, h1));
    st_pair(smc + TB_W2L, n, c2, pack_bf16(l0, l1));
  }
  for (int i = t; i < N_R * 64; i += 256) ((float*)(smc + TB_RP))[i] = g_rproj[i];
  if (t < 64) ((float*)(smc + TB_B2))[t] = wr2b[t];
  __syncthreads();

  const int rowi = t & 127;
  const int chalf = t >> 7;
  const int mh = w & 3, nh = w >> 2;
  const int m0 = mh * 32, n0 = nh * 32;
  const int g = lane >> 2, q = lane & 3;
  const float* b2 = (const float*)(smc + TB_B2);
  float* ot = (float*)g_otab;
  float* at = (float*)g_a1tab;

  for (int tile = blockIdx.x; tile < N_TAB_TILES; tile += gridDim.x) {
    const long blk0 = (long)tile * 128;
    // build H: 2 threads per row (each one 32-col half), 8B packed stores
    {
      long row = blk0 + rowi;
      long rc = (row < N_PAIRS) ? row : (N_PAIRS - 1);
      int item = (int)(rc / 5);
      int rr_ = (int)(rc - (long)item * 5);
      const float4* Pp = &g_P[(long)item * 16 + chalf * 8];
      const float* rp = (const float*)(smc + TB_RP) + rr_ * 64 + chalf * 32;
#pragma unroll
      for (int i = 0; i < 8; i++) {
        float4 p = Pp[i];
        float v0 = fmaxf(p.x + rp[4 * i + 0], 0.f);
        float v1 = fmaxf(p.y + rp[4 * i + 1], 0.f);
        float v2 = fmaxf(p.z + rp[4 * i + 2], 0.f);
        float v3 = fmaxf(p.w + rp[4 * i + 3], 0.f);
        int col4 = chalf * 32 + 4 * i;
        float h0, l0, h1, l1, h2, l2, h3, l3;
        split2(v0, h0, l0); split2(v1, h1, l1);
        split2(v2, h2, l2); split2(v3, h3, l3);
        st_quad(smc + TB_AH, rowi, col4, pack_bf16(h0, h1), pack_bf16(h2, h3));
        st_quad(smc + TB_AL, rowi, col4, pack_bf16(l0, l1), pack_bf16(l2, l3));
      }
    }
    __syncthreads();   // H complete (also: all warps done with prev GEMM2)

    // GEMM1: o = relu(H @ wr2^T + b2)
    float c[2][4][4];
    warp_gemm_32x32(c, sb + TB_AH, sb + TB_AL, sb + TB_W1H, sb + TB_W1L, m0, n0, lane);

    // epilogue 1 -> O tiles (separate smem) + otab gmem
#pragma unroll
    for (int mt = 0; mt < 2; mt++)
#pragma unroll
      for (int half = 0; half < 2; half++) {
        int lr = m0 + mt * 16 + g + half * 8;
        long rowg = blk0 + lr;
#pragma unroll
        for (int nt = 0; nt < 4; nt++) {
          int col = n0 + nt * 8 + q * 2;
          float v0 = fmaxf(c[mt][nt][half * 2 + 0] + b2[col], 0.f);
          float v1 = fmaxf(c[mt][nt][half * 2 + 1] + b2[col + 1], 0.f);
          if (rowg < N_PAIRS)
            *(float2*)&ot[rowg * 64 + col] = make_float2(v0, v1);
          float h0, l0, h1, l1;
          split2(v0, h0, l0); split2(v1, h1, l1);
          st_pair(smc + TB_OH, lr, col >> 1, pack_bf16(h0, h1));
          st_pair(smc + TB_OL, lr, col >> 1, pack_bf16(l0, l1));
        }
      }
    __syncthreads();   // O tiles complete before GEMM2

    // GEMM2: a1p = O @ att1a^T
    warp_gemm_32x32(c, sb + TB_OH, sb + TB_OL, sb + TB_W2H, sb + TB_W2L, m0, n0, lane);
#pragma unroll
    for (int mt = 0; mt < 2; mt++)
#pragma unroll
      for (int half = 0; half < 2; half++) {
        int lr = m0 + mt * 16 + g + half * 8;
        long rowg = blk0 + lr;
        if (rowg < N_PAIRS) {
#pragma unroll
          for (int nt = 0; nt < 4; nt++) {
            int col = n0 + nt * 8 + q * 2;
            *(float2*)&at[rowg * 64 + col] =
                make_float2(c[mt][nt][half * 2 + 0], c[mt][nt][half * 2 + 1]);
          }
        }
      }
    // next iteration's build-sync provides the A/O WAR protection
  }
}

// ---------------- K_LOGIT (mma.sync, persistent) ----------------
#define LB_AH 0
#define LB_AL 16384
#define LB_WH 32768
#define LB_WL 40960
#define LB_A3 49152
#define LB_A2B 49408
#define LB_A3B 49664
#define LB_PART 49680
#define LB_TOTAL 50704

__global__ __launch_bounds__(256, 2) void k_logit_mma(
    const int* __restrict__ hui, const int* __restrict__ hr,
    const float* __restrict__ att2w, const float* __restrict__ att2b_,
    const float* __restrict__ att3w, const float* __restrict__ att3b_) {
  extern __shared__ char smc[];
  const int t = threadIdx.x;
  const int lane = t & 31, w = t >> 5;
  uint32_t sb = smem_u32(smc);

  for (int i = t; i < 2048; i += 256) {
    int n = i >> 5, c2 = i & 31;
    float h0, l0, h1, l1;
    split2(att2w[n * 64 + 2 * c2], h0, l0);
    split2(att2w[n * 64 + 2 * c2 + 1], h1, l1);
    st_pair(smc + LB_WH, n, c2, pack_bf16(h0, h1));
    st_pair(smc + LB_WL, n, c2, pack_bf16(l0, l1));
  }
  if (t < 64) {
    ((float*)(smc + LB_A3))[t] = att3w[t];
    ((float*)(smc + LB_A2B))[t] = att2b_[t];
  }
  if (t == 0) *(float*)(smc + LB_A3B) = att3b_[0];
  __syncthreads();

  const int rowi = t & 127;
  const int chalf = t >> 7;
  const int mh = w & 3, nh = w >> 2;
  const int m0 = mh * 32, n0 = nh * 32;
  const int g = lane >> 2, q = lane & 3;
  const float* a3 = (const float*)(smc + LB_A3);
  const float* a2b = (const float*)(smc + LB_A2B);
  const float a3b = *(const float*)(smc + LB_A3B);
  float* part = (float*)(smc + LB_PART);

  for (int tile = blockIdx.x; tile < N_LOG_TILES; tile += gridDim.x) {
    // build A: 2 threads per row, 8B packed stores
    {
      const int e = tile * 128 + rowi;
      int b = e / HH;
      long ir = (long)hui[e] * 5 + hr[e];
      const float4* Ag = &g_a1tab[ir * 16 + chalf * 8];
      const float4* Ug = (const float4*)&g_uatt[b * 64] + chalf * 8;
#pragma unroll
      for (int i = 0; i < 8; i++) {
        float4 p = Ag[i], qv = Ug[i];
        float v0 = fmaxf(p.x + qv.x, 0.f), v1 = fmaxf(p.y + qv.y, 0.f);
        float v2 = fmaxf(p.z + qv.z, 0.f), v3 = fmaxf(p.w + qv.w, 0.f);
        int col4 = chalf * 32 + 4 * i;
        float h0, l0, h1, l1, h2, l2, h3, l3;
        split2(v0, h0, l0); split2(v1, h1, l1);
        split2(v2, h2, l2); split2(v3, h3, l3);
        st_quad(smc + LB_AH, rowi, col4, pack_bf16(h0, h1), pack_bf16(h2, h3));
        st_quad(smc + LB_AL, rowi, col4, pack_bf16(l0, l1), pack_bf16(l2, l3));
      }
    }
    __syncthreads();

    float c[2][4][4];
    warp_gemm_32x32(c, sb + LB_AH, sb + LB_AL, sb + LB_WH, sb + LB_WL, m0, n0, lane);

#pragma unroll
    for (int mt = 0; mt < 2; mt++)
#pragma unroll
      for (int half = 0; half < 2; half++) {
        int lr = m0 + mt * 16 + g + half * 8;
        float pt = 0.0f;
#pragma unroll
        for (int nt = 0; nt < 4; nt++) {
          int col = n0 + nt * 8 + q * 2;
          pt = fmaf(a3[col], fmaxf(c[mt][nt][half * 2 + 0] + a2b[col], 0.f), pt);
          pt = fmaf(a3[col + 1], fmaxf(c[mt][nt][half * 2 + 1] + a2b[col + 1], 0.f), pt);
        }
        pt += __shfl_xor_sync(0xffffffffu, pt, 1);
        pt += __shfl_xor_sync(0xffffffffu, pt, 2);
        if (q == 0) part[lr * 2 + nh] = pt;
      }
    __syncthreads();

    if (t < 128)
      g_logit[tile * 128 + t] = part[t * 2] + part[t * 2 + 1] + a3b;
    // next build's __syncthreads protects part/A reuse
  }
}

// ---------------- K_AGG: softmax + weighted o-sum + final linear ----------------
__global__ __launch_bounds__(256) void k_agg(
    const int* __restrict__ hui, const int* __restrict__ hr,
    const float* __restrict__ lin1, float* __restrict__ out) {
  __shared__ float s_lin[64 * 65];
  __shared__ float s_lg[AGG_NB * HH];
  __shared__ float s_pp[AGG_NB * HH];
  __shared__ int   s_ir[AGG_NB * HH];
  __shared__ float s_inv[AGG_NB];
  __shared__ float s_ng[AGG_NB * 64];
  __shared__ float s_ul[AGG_NB * 64];

  const int t = threadIdx.x;
  const int b0 = blockIdx.x * AGG_NB;

  for (int i = t; i < 4096; i += 256) {
    int d = i >> 6, k = i & 63;
    s_lin[d * 65 + k] = lin1[d * 128 + 64 + k];
  }
  for (int i = t; i < AGG_NB * HH; i += 256) {
    int e = b0 * HH + i;
    s_lg[i] = g_logit[e];
    s_ir[i] = hui[e] * 5 + hr[e];
  }
  for (int i = t; i < AGG_NB * 64; i += 256) s_ul[i] = g_ulin[b0 * 64 + i];
  __syncthreads();

  {
    const int wid = t >> 5, lane = t & 31;
#pragma unroll
    for (int rr = 0; rr < 2; rr++) {
      int rowb = wid * 2 + rr;
      const float* L = &s_lg[rowb * HH];
      float v1 = L[lane];
      float v2 = (lane < HH - 32) ? L[32 + lane] : -1e30f;
      float m = fmaxf(v1, v2);
#pragma unroll
      for (int off = 16; off > 0; off >>= 1)
        m = fmaxf(m, __shfl_xor_sync(0xffffffffu, m, off));
      float e1 = __expf(v1 - m);
      float e2 = (lane < HH - 32) ? __expf(v2 - m) : 0.0f;
      s_pp[rowb * HH + lane] = e1;
      if (lane < HH - 32) s_pp[rowb * HH + 32 + lane] = e2;
      float s = e1 + e2;
#pragma unroll
      for (int off = 16; off > 0; off >>= 1)
        s += __shfl_xor_sync(0xffffffffu, s, off);
      if (lane == 0) s_inv[rowb] = 1.0f / s;
    }
  }
  __syncthreads();

  const float* ot = (const float*)g_otab;
  for (int oi = t; oi < AGG_NB * 64; oi += 256) {
    int bl = oi >> 6, d = oi & 63;
    const float* pr = &s_pp[bl * HH];
    const int* irr = &s_ir[bl * HH];
    float acc = 0.0f;
#pragma unroll 10
    for (int h = 0; h < HH; h++)
      acc = fmaf(pr[h], ot[(long)irr[h] * 64 + d], acc);
    s_ng[oi] = acc * s_inv[bl];
  }
  __syncthreads();

  for (int oi = t; oi < AGG_NB * 64; oi += 256) {
    int bl = oi >> 6, d = oi & 63;
    float acc = s_ul[oi];
    const float* ng = &s_ng[bl * 64];
#pragma unroll
    for (int k = 0; k < 64; k++)
      acc = fmaf(s_lin[d * 65 + k], ng[k], acc);
    out[(long)(b0 + bl) * 64 + d] = fmaxf(acc, 0.0f);
  }
}

extern "C" void kernel_launch(void* const* d_in, const int* in_sizes, int n_in,
                              void* d_out, int out_size) {
  const int*   nodes = (const int*)d_in[0];
  const int*   hui   = (const int*)d_in[1];
  const int*   hr    = (const int*)d_in[2];
  const float* u2e   = (const float*)d_in[3];
  const float* i2e   = (const float*)d_in[4];
  const float* r2e   = (const float*)d_in[5];
  const float* wr1   = (const float*)d_in[6];
  const float* wr1b  = (const float*)d_in[7];
  const float* wr2   = (const float*)d_in[8];
  const float* wr2b  = (const float*)d_in[9];
  const float* att1  = (const float*)d_in[10];
  const float* att1b = (const float*)d_in[11];
  const float* att2  = (const float*)d_in[12];
  const float* att2b = (const float*)d_in[13];
  const float* att3  = (const float*)d_in[14];
  const float* att3b = (const float*)d_in[15];
  const float* lin1  = (const float*)d_in[16];
  const float* lin1b = (const float*)d_in[17];
  float* out = (float*)d_out;

  cudaFuncSetAttribute(k_tab_mma, cudaFuncAttributeMaxDynamicSharedMemorySize, TB_TOTAL);
  cudaFuncSetAttribute(k_logit_mma, cudaFuncAttributeMaxDynamicSharedMemorySize, LB_TOTAL);

  k_P<<<(N_ITEMS + 63) / 64, 256>>>(i2e, wr1);
  k_rproj<<<1, 320>>>(wr1, wr1b, r2e);
  k_utab<<<BB / 64, 256>>>(nodes, u2e, att1, att1b, lin1, lin1b);
  k_tab_mma<<<PERSIST_GRID, 256, TB_TOTAL>>>(wr2, wr2b, att1);
  k_logit_mma<<<PERSIST_GRID, 256, LB_TOTAL>>>(hui, hr, att2, att2b, att3, att3b);
  k_agg<<<BB / AGG_NB, 256>>>(hui, hr, lin1, out);
}

// round 12
// speedup vs baseline: 2.1734x; 1.0159x over previous
#include <cuda_runtime.h>
#include <cuda_bf16.h>
#include <cstdint>

#define BB 16384
#define HH 50
#define N_ITEMS 100000
#define N_R 5
#define N_PAIRS (N_ITEMS * N_R)
#define N_EDGES (BB * HH)
#define AGG_NB 16
#define N_TAB_TILES ((N_PAIRS + 127) / 128)
#define N_LOG_TILES (N_EDGES / 128)
#define PERSIST_GRID 296

// ---------------- persistent device tables ----------------
__device__ float4 g_P[N_ITEMS * 16];       // W_r1a @ i2e[item]
__device__ float4 g_otab[N_PAIRS * 16];    // o per (item,r)
__device__ float4 g_a1tab[N_PAIRS * 16];   // att1a @ o per (item,r)
__device__ float  g_uatt[BB * 64];
__device__ float  g_ulin[BB * 64];
__device__ float  g_rproj[N_R * 64];
__device__ float  g_logit[N_EDGES];

// ---------------- helpers ----------------
__device__ __forceinline__ uint32_t smem_u32(const void* p) {
  uint32_t a;
  asm("{ .reg .u64 t; cvta.to.shared.u64 t, %1; cvt.u32.u64 %0, t; }" : "=r"(a) : "l"(p));
  return a;
}
__device__ __forceinline__ void split2(float x, float& hi, float& lo) {
  __nv_bfloat16 h = __float2bfloat16_rn(x);
  hi = __bfloat162float(h);
  lo = x - hi;
}
__device__ __forceinline__ uint32_t pack_bf16(float a, float b) {
  __nv_bfloat162 h = __floats2bfloat162_rn(a, b);
  return *(uint32_t*)&h;
}
// bf16 tile rows: 64 cols = 128B = 8 chunks of 16B; swizzle chunk ^= (row&7)
__device__ __forceinline__ void st_pair(char* base, int row, int cp, uint32_t v) {
  int col = cp * 2;
  uint32_t off = row * 128 + ((((col >> 3) ^ row) & 7) << 4) + ((col & 7) << 1);
  *(uint32_t*)(base + off) = v;
}
// 8-byte store of 4 bf16 cols (col4 % 4 == 0 -> 8B aligned within chunk)
__device__ __forceinline__ void st_quad(char* base, int row, int col4,
                                        uint32_t v0, uint32_t v1) {
  uint32_t off = row * 128 + ((((col4 >> 3) ^ row) & 7) << 4) + ((col4 & 7) << 1);
  *(uint2*)(base + off) = make_uint2(v0, v1);
}
__device__ __forceinline__ void ldsm4(uint32_t& r0, uint32_t& r1, uint32_t& r2,
                                      uint32_t& r3, uint32_t addr) {
  asm volatile("ldmatrix.sync.aligned.m8n8.x4.shared.b16 {%0,%1,%2,%3}, [%4];"
               : "=r"(r0), "=r"(r1), "=r"(r2), "=r"(r3) : "r"(addr));
}
__device__ __forceinline__ void mma16816(float* c, const uint32_t* a, const uint32_t* b) {
  asm volatile(
      "mma.sync.aligned.m16n8k16.row.col.f32.bf16.bf16.f32 "
      "{%0,%1,%2,%3}, {%4,%5,%6,%7}, {%8,%9}, {%0,%1,%2,%3};"
      : "+f"(c[0]), "+f"(c[1]), "+f"(c[2]), "+f"(c[3])
      : "r"(a[0]), "r"(a[1]), "r"(a[2]), "r"(a[3]), "r"(b[0]), "r"(b[1]));
}

// Warp GEMM: C[32x32] += A[32rows x 64k] @ B[32rows x 64k]^T, 3-term hi/lo bf16.
// k-step outermost: Ah/Bh fragments loaded ONCE per k-step and reused across
// the hh / hl / lh terms (8 ldsm4 per k-step instead of 12).
__device__ __forceinline__ void warp_gemm_32x32(float c[2][4][4], uint32_t aH, uint32_t aL,
                                                uint32_t bH, uint32_t bL, int m0, int n0,
                                                int lane) {
  const int r = lane & 7, sel = lane >> 3;
  const int arow = r + (sel & 1) * 8, ach = sel >> 1;
  const int brow = r + (sel >> 1) * 8, bch = sel & 1;
#pragma unroll
  for (int mt = 0; mt < 2; mt++)
#pragma unroll
    for (int nt = 0; nt < 4; nt++)
#pragma unroll
      for (int i = 0; i < 4; i++) c[mt][nt][i] = 0.0f;

#pragma unroll
  for (int ks = 0; ks < 4; ks++) {
    const int cha = 2 * ks + ach;
    const int chb = 2 * ks + bch;
    uint32_t ah[2][4], al[2][4], bh[2][4], bl[2][4];
#pragma unroll
    for (int mt = 0; mt < 2; mt++) {
      int rowa = m0 + mt * 16 + arow;
      ldsm4(ah[mt][0], ah[mt][1], ah[mt][2], ah[mt][3],
            aH + rowa * 128 + (((cha ^ rowa) & 7) << 4));
    }
#pragma unroll
    for (int nb = 0; nb < 2; nb++) {
      int rowb = n0 + nb * 16 + brow;
      ldsm4(bh[nb][0], bh[nb][1], bh[nb][2], bh[nb][3],
            bH + rowb * 128 + (((chb ^ rowb) & 7) << 4));
    }
    // hh
#pragma unroll
    for (int mt = 0; mt < 2; mt++)
#pragma unroll
      for (int nt = 0; nt < 4; nt++)
        mma16816(c[mt][nt], ah[mt], &bh[nt >> 1][(nt & 1) * 2]);
    // hl
#pragma unroll
    for (int nb = 0; nb < 2; nb++) {
      int rowb = n0 + nb * 16 + brow;
      ldsm4(bl[nb][0], bl[nb][1], bl[nb][2], bl[nb][3],
            bL + rowb * 128 + (((chb ^ rowb) & 7) << 4));
    }
#pragma unroll
    for (int mt = 0; mt < 2; mt++)
#pragma unroll
      for (int nt = 0; nt < 4; nt++)
        mma16816(c[mt][nt], ah[mt], &bl[nt >> 1][(nt & 1) * 2]);
    // lh
#pragma unroll
    for (int mt = 0; mt < 2; mt++) {
      int rowa = m0 + mt * 16 + arow;
      ldsm4(al[mt][0], al[mt][1], al[mt][2], al[mt][3],
            aL + rowa * 128 + (((cha ^ rowa) & 7) << 4));
    }
#pragma unroll
    for (int mt = 0; mt < 2; mt++)
#pragma unroll
      for (int nt = 0; nt < 4; nt++)
        mma16816(c[mt][nt], al[mt], &bh[nt >> 1][(nt & 1) * 2]);
  }
}

// ---------------- K_P: P = i2e @ W_r1a^T ----------------
__global__ __launch_bounds__(256) void k_P(
    const float* __restrict__ i2e, const float* __restrict__ wr1) {
  __shared__ float e_s[64 * 68];
  __shared__ float wt[64 * 68];
  const int tid = threadIdx.x;
  const int base = blockIdx.x * 64;
  float* gP = (float*)g_P;

  for (int i = tid; i < 64 * 64; i += 256) {
    int it = i >> 6, k = i & 63;
    int item = base + it;
    e_s[it * 68 + k] = (item < N_ITEMS) ? i2e[(long)item * 64 + k] : 0.0f;
  }
  for (int i = tid; i < 64 * 64; i += 256) {
    int d = i >> 6, k = i & 63;
    wt[k * 68 + d] = wr1[d * 128 + k];
  }
  __syncthreads();

  const int il = tid >> 3;
  const int dq = tid & 7;
  for (int sb = 0; sb < 2; sb++) {
    int it = sb * 32 + il;
    int item = base + it;
    float acc[8];
#pragma unroll
    for (int i = 0; i < 8; i++) acc[i] = 0.0f;
#pragma unroll
    for (int k = 0; k < 64; k++) {
      float ev = e_s[it * 68 + k];
      float4 w0 = *(const float4*)&wt[k * 68 + dq * 8];
      float4 w1 = *(const float4*)&wt[k * 68 + dq * 8 + 4];
      acc[0] = fmaf(ev, w0.x, acc[0]); acc[1] = fmaf(ev, w0.y, acc[1]);
      acc[2] = fmaf(ev, w0.z, acc[2]); acc[3] = fmaf(ev, w0.w, acc[3]);
      acc[4] = fmaf(ev, w1.x, acc[4]); acc[5] = fmaf(ev, w1.y, acc[5]);
      acc[6] = fmaf(ev, w1.z, acc[6]); acc[7] = fmaf(ev, w1.w, acc[7]);
    }
    if (item < N_ITEMS) {
      float4* dst = (float4*)&gP[(long)item * 64 + dq * 8];
      dst[0] = make_float4(acc[0], acc[1], acc[2], acc[3]);
      dst[1] = make_float4(acc[4], acc[5], acc[6], acc[7]);
    }
  }
}

// ---------------- K_R ----------------
__global__ void k_rproj(const float* __restrict__ wr1,
                        const float* __restrict__ wr1b,
                        const float* __restrict__ r2e) {
  int t = threadIdx.x;
  if (t < N_R * 64) {
    int r = t >> 6, d = t & 63;
    float acc = wr1b[d];
#pragma unroll
    for (int k = 0; k < 64; k++)
      acc = fmaf(wr1[d * 128 + 64 + k], r2e[r * 64 + k], acc);
    g_rproj[r * 64 + d] = acc;
  }
}

// ---------------- K_U ----------------
__global__ __launch_bounds__(256) void k_utab(
    const int* __restrict__ nodes, const float* __restrict__ u2e,
    const float* __restrict__ att1, const float* __restrict__ att1b,
    const float* __restrict__ lin1, const float* __restrict__ lin1b) {
  __shared__ float a_s[64 * 65];
  __shared__ float l_s[64 * 65];
  __shared__ float u_s[4 * 64];
  const int t = threadIdx.x;

  for (int i = t; i < 4096; i += 256) {
    int d = i >> 6, k = i & 63;
    a_s[d * 65 + k] = att1[d * 128 + 64 + k];
    l_s[d * 65 + k] = lin1[d * 128 + k];
  }
  const int b0 = blockIdx.x * 64;
  const int bb = t >> 6, d = t & 63;
  for (int it = 0; it < 16; it++) {
    __syncthreads();
    {
      int b = b0 + it * 4 + bb;
      u_s[t] = u2e[(long)nodes[b] * 64 + d];
    }
    __syncthreads();
    const float* uu = &u_s[bb * 64];
    float au = att1b[d], lu = lin1b[d];
#pragma unroll
    for (int k = 0; k < 64; k++) {
      float uv = uu[k];
      au = fmaf(a_s[d * 65 + k], uv, au);
      lu = fmaf(l_s[d * 65 + k], uv, lu);
    }
    int b = b0 + it * 4 + bb;
    g_uatt[b * 64 + d] = au;
    g_ulin[b * 64 + d] = lu;
  }
}

// ---------------- K_TAB (mma.sync, persistent, separate O tiles) ----------------
#define TB_AH 0
#define TB_AL 16384
#define TB_OH 32768
#define TB_OL 49152
#define TB_W1H 65536
#define TB_W1L 73728
#define TB_W2H 81920
#define TB_W2L 90112
#define TB_RP 98304
#define TB_B2 99584
#define TB_TOTAL 99840

__global__ __launch_bounds__(256, 2) void k_tab_mma(
    const float* __restrict__ wr2, const float* __restrict__ wr2b,
    const float* __restrict__ att1) {
  extern __shared__ char smc[];
  const int t = threadIdx.x;
  const int lane = t & 31, w = t >> 5;
  uint32_t sb = smem_u32(smc);

  // stage weights ONCE per CTA
  for (int i = t; i < 2048; i += 256) {
    int n = i >> 5, c2 = i & 31;
    float h0, l0, h1, l1;
    split2(wr2[n * 64 + 2 * c2], h0, l0);
    split2(wr2[n * 64 + 2 * c2 + 1], h1, l1);
    st_pair(smc + TB_W1H, n, c2, pack_bf16(h0, h1));
    st_pair(smc + TB_W1L, n, c2, pack_bf16(l0, l1));
    split2(att1[n * 128 + 2 * c2], h0, l0);
    split2(att1[n * 128 + 2 * c2 + 1], h1, l1);
    st_pair(smc + TB_W2H, n, c2, pack_bf16(h0, h1));
    st_pair(smc + TB_W2L, n, c2, pack_bf16(l0, l1));
  }
  for (int i = t; i < N_R * 64; i += 256) ((float*)(smc + TB_RP))[i] = g_rproj[i];
  if (t < 64) ((float*)(smc + TB_B2))[t] = wr2b[t];
  __syncthreads();

  const int rowi = t & 127;
  const int chalf = t >> 7;
  const int mh = w & 3, nh = w >> 2;
  const int m0 = mh * 32, n0 = nh * 32;
  const int g = lane >> 2, q = lane & 3;
  const float* b2 = (const float*)(smc + TB_B2);
  float* ot = (float*)g_otab;
  float* at = (float*)g_a1tab;

  for (int tile = blockIdx.x; tile < N_TAB_TILES; tile += gridDim.x) {
    const long blk0 = (long)tile * 128;
    // build H: 2 threads per row (each one 32-col half), 8B packed stores
    {
      long row = blk0 + rowi;
      long rc = (row < N_PAIRS) ? row : (N_PAIRS - 1);
      int item = (int)(rc / 5);
      int rr_ = (int)(rc - (long)item * 5);
      const float4* Pp = &g_P[(long)item * 16 + chalf * 8];
      const float* rp = (const float*)(smc + TB_RP) + rr_ * 64 + chalf * 32;
#pragma unroll
      for (int i = 0; i < 8; i++) {
        float4 p = Pp[i];
        float v0 = fmaxf(p.x + rp[4 * i + 0], 0.f);
        float v1 = fmaxf(p.y + rp[4 * i + 1], 0.f);
        float v2 = fmaxf(p.z + rp[4 * i + 2], 0.f);
        float v3 = fmaxf(p.w + rp[4 * i + 3], 0.f);
        int col4 = chalf * 32 + 4 * i;
        float h0, l0, h1, l1, h2, l2, h3, l3;
        split2(v0, h0, l0); split2(v1, h1, l1);
        split2(v2, h2, l2); split2(v3, h3, l3);
        st_quad(smc + TB_AH, rowi, col4, pack_bf16(h0, h1), pack_bf16(h2, h3));
        st_quad(smc + TB_AL, rowi, col4, pack_bf16(l0, l1), pack_bf16(l2, l3));
      }
    }
    __syncthreads();   // H complete (also: all warps done with prev GEMM2)

    // GEMM1: o = relu(H @ wr2^T + b2)
    float c[2][4][4];
    warp_gemm_32x32(c, sb + TB_AH, sb + TB_AL, sb + TB_W1H, sb + TB_W1L, m0, n0, lane);

    // epilogue 1 -> O tiles (separate smem) + otab gmem
#pragma unroll
    for (int mt = 0; mt < 2; mt++)
#pragma unroll
      for (int half = 0; half < 2; half++) {
        int lr = m0 + mt * 16 + g + half * 8;
        long rowg = blk0 + lr;
#pragma unroll
        for (int nt = 0; nt < 4; nt++) {
          int col = n0 + nt * 8 + q * 2;
          float v0 = fmaxf(c[mt][nt][half * 2 + 0] + b2[col], 0.f);
          float v1 = fmaxf(c[mt][nt][half * 2 + 1] + b2[col + 1], 0.f);
          if (rowg < N_PAIRS)
            *(float2*)&ot[rowg * 64 + col] = make_float2(v0, v1);
          float h0, l0, h1, l1;
          split2(v0, h0, l0); split2(v1, h1, l1);
          st_pair(smc + TB_OH, lr, col >> 1, pack_bf16(h0, h1));
          st_pair(smc + TB_OL, lr, col >> 1, pack_bf16(l0, l1));
        }
      }
    __syncthreads();   // O tiles complete before GEMM2

    // GEMM2: a1p = O @ att1a^T
    warp_gemm_32x32(c, sb + TB_OH, sb + TB_OL, sb + TB_W2H, sb + TB_W2L, m0, n0, lane);
#pragma unroll
    for (int mt = 0; mt < 2; mt++)
#pragma unroll
      for (int half = 0; half < 2; half++) {
        int lr = m0 + mt * 16 + g + half * 8;
        long rowg = blk0 + lr;
        if (rowg < N_PAIRS) {
#pragma unroll
          for (int nt = 0; nt < 4; nt++) {
            int col = n0 + nt * 8 + q * 2;
            *(float2*)&at[rowg * 64 + col] =
                make_float2(c[mt][nt][half * 2 + 0], c[mt][nt][half * 2 + 1]);
          }
        }
      }
    // next iteration's build-sync provides the A/O WAR protection
  }
}

// ---------------- K_LOGIT (mma.sync, persistent) ----------------
#define LB_AH 0
#define LB_AL 16384
#define LB_WH 32768
#define LB_WL 40960
#define LB_A3 49152
#define LB_A2B 49408
#define LB_A3B 49664
#define LB_PART 49680
#define LB_TOTAL 50704

__global__ __launch_bounds__(256, 2) void k_logit_mma(
    const int* __restrict__ hui, const int* __restrict__ hr,
    const float* __restrict__ att2w, const float* __restrict__ att2b_,
    const float* __restrict__ att3w, const float* __restrict__ att3b_) {
  extern __shared__ char smc[];
  const int t = threadIdx.x;
  const int lane = t & 31, w = t >> 5;
  uint32_t sb = smem_u32(smc);

  for (int i = t; i < 2048; i += 256) {
    int n = i >> 5, c2 = i & 31;
    float h0, l0, h1, l1;
    split2(att2w[n * 64 + 2 * c2], h0, l0);
    split2(att2w[n * 64 + 2 * c2 + 1], h1, l1);
    st_pair(smc + LB_WH, n, c2, pack_bf16(h0, h1));
    st_pair(smc + LB_WL, n, c2, pack_bf16(l0, l1));
  }
  if (t < 64) {
    ((float*)(smc + LB_A3))[t] = att3w[t];
    ((float*)(smc + LB_A2B))[t] = att2b_[t];
  }
  if (t == 0) *(float*)(smc + LB_A3B) = att3b_[0];
  __syncthreads();

  const int rowi = t & 127;
  const int chalf = t >> 7;
  const int mh = w & 3, nh = w >> 2;
  const int m0 = mh * 32, n0 = nh * 32;
  const int g = lane >> 2, q = lane & 3;
  const float* a3 = (const float*)(smc + LB_A3);
  const float* a2b = (const float*)(smc + LB_A2B);
  const float a3b = *(const float*)(smc + LB_A3B);
  float* part = (float*)(smc + LB_PART);

  for (int tile = blockIdx.x; tile < N_LOG_TILES; tile += gridDim.x) {
    // build A: 2 threads per row, 8B packed stores
    {
      const int e = tile * 128 + rowi;
      int b = e / HH;
      long ir = (long)hui[e] * 5 + hr[e];
      const float4* Ag = &g_a1tab[ir * 16 + chalf * 8];
      const float4* Ug = (const float4*)&g_uatt[b * 64] + chalf * 8;
#pragma unroll
      for (int i = 0; i < 8; i++) {
        float4 p = Ag[i], qv = Ug[i];
        float v0 = fmaxf(p.x + qv.x, 0.f), v1 = fmaxf(p.y + qv.y, 0.f);
        float v2 = fmaxf(p.z + qv.z, 0.f), v3 = fmaxf(p.w + qv.w, 0.f);
        int col4 = chalf * 32 + 4 * i;
        float h0, l0, h1, l1, h2, l2, h3, l3;
        split2(v0, h0, l0); split2(v1, h1, l1);
        split2(v2, h2, l2); split2(v3, h3, l3);
        st_quad(smc + LB_AH, rowi, col4, pack_bf16(h0, h1), pack_bf16(h2, h3));
        st_quad(smc + LB_AL, rowi, col4, pack_bf16(l0, l1), pack_bf16(l2, l3));
      }
    }
    __syncthreads();

    float c[2][4][4];
    warp_gemm_32x32(c, sb + LB_AH, sb + LB_AL, sb + LB_WH, sb + LB_WL, m0, n0, lane);

#pragma unroll
    for (int mt = 0; mt < 2; mt++)
#pragma unroll
      for (int half = 0; half < 2; half++) {
        int lr = m0 + mt * 16 + g + half * 8;
        float pt = 0.0f;
#pragma unroll
        for (int nt = 0; nt < 4; nt++) {
          int col = n0 + nt * 8 + q * 2;
          pt = fmaf(a3[col], fmaxf(c[mt][nt][half * 2 + 0] + a2b[col], 0.f), pt);
          pt = fmaf(a3[col + 1], fmaxf(c[mt][nt][half * 2 + 1] + a2b[col + 1], 0.f), pt);
        }
        pt += __shfl_xor_sync(0xffffffffu, pt, 1);
        pt += __shfl_xor_sync(0xffffffffu, pt, 2);
        if (q == 0) part[lr * 2 + nh] = pt;
      }
    __syncthreads();

    if (t < 128)
      g_logit[tile * 128 + t] = part[t * 2] + part[t * 2 + 1] + a3b;
    // next build's __syncthreads protects part/A reuse
  }
}

// ---------------- K_AGG: softmax + weighted o-sum + final linear ----------------
__global__ __launch_bounds__(256) void k_agg(
    const int* __restrict__ hui, const int* __restrict__ hr,
    const float* __restrict__ lin1, float* __restrict__ out) {
  __shared__ float s_lin[64 * 65];
  __shared__ float s_lg[AGG_NB * HH];
  __shared__ float s_pp[AGG_NB * HH];
  __shared__ int   s_ir[AGG_NB * HH];
  __shared__ float s_inv[AGG_NB];
  __shared__ float s_ng[AGG_NB * 64];
  __shared__ float s_ul[AGG_NB * 64];

  const int t = threadIdx.x;
  const int b0 = blockIdx.x * AGG_NB;

  for (int i = t; i < 4096; i += 256) {
    int d = i >> 6, k = i & 63;
    s_lin[d * 65 + k] = lin1[d * 128 + 64 + k];
  }
  for (int i = t; i < AGG_NB * HH; i += 256) {
    int e = b0 * HH + i;
    s_lg[i] = g_logit[e];
    s_ir[i] = hui[e] * 5 + hr[e];
  }
  for (int i = t; i < AGG_NB * 64; i += 256) s_ul[i] = g_ulin[b0 * 64 + i];
  __syncthreads();

  {
    const int wid = t >> 5, lane = t & 31;
#pragma unroll
    for (int rr = 0; rr < 2; rr++) {
      int rowb = wid * 2 + rr;
      const float* L = &s_lg[rowb * HH];
      float v1 = L[lane];
      float v2 = (lane < HH - 32) ? L[32 + lane] : -1e30f;
      float m = fmaxf(v1, v2);
#pragma unroll
      for (int off = 16; off > 0; off >>= 1)
        m = fmaxf(m, __shfl_xor_sync(0xffffffffu, m, off));
      float e1 = __expf(v1 - m);
      float e2 = (lane < HH - 32) ? __expf(v2 - m) : 0.0f;
      s_pp[rowb * HH + lane] = e1;
      if (lane < HH - 32) s_pp[rowb * HH + 32 + lane] = e2;
      float s = e1 + e2;
#pragma unroll
      for (int off = 16; off > 0; off >>= 1)
        s += __shfl_xor_sync(0xffffffffu, s, off);
      if (lane == 0) s_inv[rowb] = 1.0f / s;
    }
  }
  __syncthreads();

  const float* ot = (const float*)g_otab;
  for (int oi = t; oi < AGG_NB * 64; oi += 256) {
    int bl = oi >> 6, d = oi & 63;
    const float* pr = &s_pp[bl * HH];
    const int* irr = &s_ir[bl * HH];
    float acc = 0.0f;
#pragma unroll 10
    for (int h = 0; h < HH; h++)
      acc = fmaf(pr[h], ot[(long)irr[h] * 64 + d], acc);
    s_ng[oi] = acc * s_inv[bl];
  }
  __syncthreads();

  for (int oi = t; oi < AGG_NB * 64; oi += 256) {
    int bl = oi >> 6, d = oi & 63;
    float acc = s_ul[oi];
    const float* ng = &s_ng[bl * 64];
#pragma unroll
    for (int k = 0; k < 64; k++)
      acc = fmaf(s_lin[d * 65 + k], ng[k], acc);
    out[(long)(b0 + bl) * 64 + d] = fmaxf(acc, 0.0f);
  }
}

extern "C" void kernel_launch(void* const* d_in, const int* in_sizes, int n_in,
                              void* d_out, int out_size) {
  const int*   nodes = (const int*)d_in[0];
  const int*   hui   = (const int*)d_in[1];
  const int*   hr    = (const int*)d_in[2];
  const float* u2e   = (const float*)d_in[3];
  const float* i2e   = (const float*)d_in[4];
  const float* r2e   = (const float*)d_in[5];
  const float* wr1   = (const float*)d_in[6];
  const float* wr1b  = (const float*)d_in[7];
  const float* wr2   = (const float*)d_in[8];
  const float* wr2b  = (const float*)d_in[9];
  const float* att1  = (const float*)d_in[10];
  const float* att1b = (const float*)d_in[11];
  const float* att2  = (const float*)d_in[12];
  const float* att2b = (const float*)d_in[13];
  const float* att3  = (const float*)d_in[14];
  const float* att3b = (const float*)d_in[15];
  const float* lin1  = (const float*)d_in[16];
  const float* lin1b = (const float*)d_in[17];
  float* out = (float*)d_out;

  cudaFuncSetAttribute(k_tab_mma, cudaFuncAttributeMaxDynamicSharedMemorySize, TB_TOTAL);
  cudaFuncSetAttribute(k_logit_mma, cudaFuncAttributeMaxDynamicSharedMemorySize, LB_TOTAL);

  k_P<<<(N_ITEMS + 63) / 64, 256>>>(i2e, wr1);
  k_rproj<<<1, 320>>>(wr1, wr1b, r2e);
  k_utab<<<BB / 64, 256>>>(nodes, u2e, att1, att1b, lin1, lin1b);
  k_tab_mma<<<PERSIST_GRID, 256, TB_TOTAL>>>(wr2, wr2b, att1);
  k_logit_mma<<<PERSIST_GRID, 256, LB_TOTAL>>>(hui, hr, att2, att2b, att3, att3b);
  k_agg<<<BB / AGG_NB, 256>>>(hui, hr, lin1, out);
}

// round 13
// speedup vs baseline: 3.6783x; 1.6924x over previous
#include <cuda_runtime.h>
#include <cuda_bf16.h>
#include <cstdint>

#define BB 16384
#define HH 50
#define N_ITEMS 100000
#define N_R 5
#define N_PAIRS (N_ITEMS * N_R)
#define N_EDGES (BB * HH)
#define AGG_NB 16
#define N_TAB_TILES ((N_PAIRS + 127) / 128)
#define N_LOG_TILES (N_EDGES / 128)
#define N_P_TILES ((N_ITEMS + 127) / 128)
#define PERSIST_GRID 296

// ---------------- persistent device tables ----------------
__device__ float4 g_P[N_ITEMS * 16];       // W_r1a @ i2e[item]
__device__ float4 g_otab[N_PAIRS * 16];    // o per (item,r)
__device__ float4 g_a1tab[N_PAIRS * 16];   // att1a @ o per (item,r)
__device__ float  g_uatt[BB * 64];
__device__ float  g_ulin[BB * 64];
__device__ float  g_rproj[N_R * 64];
__device__ float  g_logit[N_EDGES];

// ---------------- helpers ----------------
__device__ __forceinline__ uint32_t smem_u32(const void* p) {
  uint32_t a;
  asm("{ .reg .u64 t; cvta.to.shared.u64 t, %1; cvt.u32.u64 %0, t; }" : "=r"(a) : "l"(p));
  return a;
}
__device__ __forceinline__ void split2(float x, float& hi, float& lo) {
  __nv_bfloat16 h = __float2bfloat16_rn(x);
  hi = __bfloat162float(h);
  lo = x - hi;
}
__device__ __forceinline__ uint32_t pack_bf16(float a, float b) {
  __nv_bfloat162 h = __floats2bfloat162_rn(a, b);
  return *(uint32_t*)&h;
}
// bf16 tile rows: 64 cols = 128B = 8 chunks of 16B; swizzle chunk ^= (row&7)
__device__ __forceinline__ void st_pair(char* base, int row, int cp, uint32_t v) {
  int col = cp * 2;
  uint32_t off = row * 128 + ((((col >> 3) ^ row) & 7) << 4) + ((col & 7) << 1);
  *(uint32_t*)(base + off) = v;
}
// 8-byte store of 4 bf16 cols (col4 % 4 == 0 -> 8B aligned within chunk)
__device__ __forceinline__ void st_quad(char* base, int row, int col4,
                                        uint32_t v0, uint32_t v1) {
  uint32_t off = row * 128 + ((((col4 >> 3) ^ row) & 7) << 4) + ((col4 & 7) << 1);
  *(uint2*)(base + off) = make_uint2(v0, v1);
}
__device__ __forceinline__ void ldsm4(uint32_t& r0, uint32_t& r1, uint32_t& r2,
                                      uint32_t& r3, uint32_t addr) {
  asm volatile("ldmatrix.sync.aligned.m8n8.x4.shared.b16 {%0,%1,%2,%3}, [%4];"
               : "=r"(r0), "=r"(r1), "=r"(r2), "=r"(r3) : "r"(addr));
}
__device__ __forceinline__ void mma16816(float* c, const uint32_t* a, const uint32_t* b) {
  asm volatile(
      "mma.sync.aligned.m16n8k16.row.col.f32.bf16.bf16.f32 "
      "{%0,%1,%2,%3}, {%4,%5,%6,%7}, {%8,%9}, {%0,%1,%2,%3};"
      : "+f"(c[0]), "+f"(c[1]), "+f"(c[2]), "+f"(c[3])
      : "r"(a[0]), "r"(a[1]), "r"(a[2]), "r"(a[3]), "r"(b[0]), "r"(b[1]));
}

// Warp GEMM: C[32x32] += A[32rows x 64k] @ B[32rows x 64k]^T, 3-term hi/lo bf16.
// k-step outermost: Ah/Bh fragments loaded ONCE per k-step (8 ldsm4/k-step).
__device__ __forceinline__ void warp_gemm_32x32(float c[2][4][4], uint32_t aH, uint32_t aL,
                                                uint32_t bH, uint32_t bL, int m0, int n0,
                                                int lane) {
  const int r = lane & 7, sel = lane >> 3;
  const int arow = r + (sel & 1) * 8, ach = sel >> 1;
  const int brow = r + (sel >> 1) * 8, bch = sel & 1;
#pragma unroll
  for (int mt = 0; mt < 2; mt++)
#pragma unroll
    for (int nt = 0; nt < 4; nt++)
#pragma unroll
      for (int i = 0; i < 4; i++) c[mt][nt][i] = 0.0f;

#pragma unroll
  for (int ks = 0; ks < 4; ks++) {
    const int cha = 2 * ks + ach;
    const int chb = 2 * ks + bch;
    uint32_t ah[2][4], al[2][4], bh[2][4], bl[2][4];
#pragma unroll
    for (int mt = 0; mt < 2; mt++) {
      int rowa = m0 + mt * 16 + arow;
      ldsm4(ah[mt][0], ah[mt][1], ah[mt][2], ah[mt][3],
            aH + rowa * 128 + (((cha ^ rowa) & 7) << 4));
    }
#pragma unroll
    for (int nb = 0; nb < 2; nb++) {
      int rowb = n0 + nb * 16 + brow;
      ldsm4(bh[nb][0], bh[nb][1], bh[nb][2], bh[nb][3],
            bH + rowb * 128 + (((chb ^ rowb) & 7) << 4));
    }
#pragma unroll
    for (int mt = 0; mt < 2; mt++)
#pragma unroll
      for (int nt = 0; nt < 4; nt++)
        mma16816(c[mt][nt], ah[mt], &bh[nt >> 1][(nt & 1) * 2]);
#pragma unroll
    for (int nb = 0; nb < 2; nb++) {
      int rowb = n0 + nb * 16 + brow;
      ldsm4(bl[nb][0], bl[nb][1], bl[nb][2], bl[nb][3],
            bL + rowb * 128 + (((chb ^ rowb) & 7) << 4));
    }
#pragma unroll
    for (int mt = 0; mt < 2; mt++)
#pragma unroll
      for (int nt = 0; nt < 4; nt++)
        mma16816(c[mt][nt], ah[mt], &bl[nt >> 1][(nt & 1) * 2]);
#pragma unroll
    for (int mt = 0; mt < 2; mt++) {
      int rowa = m0 + mt * 16 + arow;
      ldsm4(al[mt][0], al[mt][1], al[mt][2], al[mt][3],
            aL + rowa * 128 + (((cha ^ rowa) & 7) << 4));
    }
#pragma unroll
    for (int mt = 0; mt < 2; mt++)
#pragma unroll
      for (int nt = 0; nt < 4; nt++)
        mma16816(c[mt][nt], al[mt], &bh[nt >> 1][(nt & 1) * 2]);
  }
}

// ---------------- K_P (mma.sync): P = i2e @ W_r1a^T ----------------
#define PB_AH 0
#define PB_AL 16384
#define PB_WH 32768
#define PB_WL 40960
#define PB_TOTAL 49152

__global__ __launch_bounds__(256, 2) void k_P_mma(
    const float* __restrict__ i2e, const float* __restrict__ wr1) {
  extern __shared__ char smc[];
  const int t = threadIdx.x;
  const int lane = t & 31, w = t >> 5;
  uint32_t sb = smem_u32(smc);

  // stage wr1a (= wr1[d][0:64]) hi/lo ONCE per CTA
  for (int i = t; i < 2048; i += 256) {
    int n = i >> 5, c2 = i & 31;
    float h0, l0, h1, l1;
    split2(wr1[n * 128 + 2 * c2], h0, l0);
    split2(wr1[n * 128 + 2 * c2 + 1], h1, l1);
    st_pair(smc + PB_WH, n, c2, pack_bf16(h0, h1));
    st_pair(smc + PB_WL, n, c2, pack_bf16(l0, l1));
  }
  __syncthreads();

  const int rowi = t & 127;
  const int chalf = t >> 7;
  const int mh = w & 3, nh = w >> 2;
  const int m0 = mh * 32, n0 = nh * 32;
  const int g = lane >> 2, q = lane & 3;
  float* gP = (float*)g_P;

  for (int tile = blockIdx.x; tile < N_P_TILES; tile += gridDim.x) {
    const long blk0 = (long)tile * 128;
    {
      long row = blk0 + rowi;
      long rc = (row < N_ITEMS) ? row : (N_ITEMS - 1);
      const float4* Ep = (const float4*)&i2e[rc * 64] + chalf * 8;
#pragma unroll
      for (int i = 0; i < 8; i++) {
        float4 p = Ep[i];
        int col4 = chalf * 32 + 4 * i;
        float h0, l0, h1, l1, h2, l2, h3, l3;
        split2(p.x, h0, l0); split2(p.y, h1, l1);
        split2(p.z, h2, l2); split2(p.w, h3, l3);
        st_quad(smc + PB_AH, rowi, col4, pack_bf16(h0, h1), pack_bf16(h2, h3));
        st_quad(smc + PB_AL, rowi, col4, pack_bf16(l0, l1), pack_bf16(l2, l3));
      }
    }
    __syncthreads();

    float c[2][4][4];
    warp_gemm_32x32(c, sb + PB_AH, sb + PB_AL, sb + PB_WH, sb + PB_WL, m0, n0, lane);
#pragma unroll
    for (int mt = 0; mt < 2; mt++)
#pragma unroll
      for (int half = 0; half < 2; half++) {
        int lr = m0 + mt * 16 + g + half * 8;
        long rowg = blk0 + lr;
        if (rowg < N_ITEMS) {
#pragma unroll
          for (int nt = 0; nt < 4; nt++) {
            int col = n0 + nt * 8 + q * 2;
            *(float2*)&gP[rowg * 64 + col] =
                make_float2(c[mt][nt][half * 2 + 0], c[mt][nt][half * 2 + 1]);
          }
        }
      }
    __syncthreads();   // all reads of A done before next tile's build
  }
}

// ---------------- K_R ----------------
__global__ void k_rproj(const float* __restrict__ wr1,
                        const float* __restrict__ wr1b,
                        const float* __restrict__ r2e) {
  int t = threadIdx.x;
  if (t < N_R * 64) {
    int r = t >> 6, d = t & 63;
    float acc = wr1b[d];
#pragma unroll
    for (int k = 0; k < 64; k++)
      acc = fmaf(wr1[d * 128 + 64 + k], r2e[r * 64 + k], acc);
    g_rproj[r * 64 + d] = acc;
  }
}

// ---------------- K_U ----------------
__global__ __launch_bounds__(256) void k_utab(
    const int* __restrict__ nodes, const float* __restrict__ u2e,
    const float* __restrict__ att1, const float* __restrict__ att1b,
    const float* __restrict__ lin1, const float* __restrict__ lin1b) {
  __shared__ float a_s[64 * 65];
  __shared__ float l_s[64 * 65];
  __shared__ float u_s[4 * 64];
  const int t = threadIdx.x;

  for (int i = t; i < 4096; i += 256) {
    int d = i >> 6, k = i & 63;
    a_s[d * 65 + k] = att1[d * 128 + 64 + k];
    l_s[d * 65 + k] = lin1[d * 128 + k];
  }
  const int b0 = blockIdx.x * 64;
  const int bb = t >> 6, d = t & 63;
  for (int it = 0; it < 16; it++) {
    __syncthreads();
    {
      int b = b0 + it * 4 + bb;
      u_s[t] = u2e[(long)nodes[b] * 64 + d];
    }
    __syncthreads();
    const float* uu = &u_s[bb * 64];
    float au = att1b[d], lu = lin1b[d];
#pragma unroll
    for (int k = 0; k < 64; k++) {
      float uv = uu[k];
      au = fmaf(a_s[d * 65 + k], uv, au);
      lu = fmaf(l_s[d * 65 + k], uv, lu);
    }
    int b = b0 + it * 4 + bb;
    g_uatt[b * 64 + d] = au;
    g_ulin[b * 64 + d] = lu;
  }
}

// ---------------- K_TAB (mma.sync, persistent, separate O tiles) ----------------
#define TB_AH 0
#define TB_AL 16384
#define TB_OH 32768
#define TB_OL 49152
#define TB_W1H 65536
#define TB_W1L 73728
#define TB_W2H 81920
#define TB_W2L 90112
#define TB_RP 98304
#define TB_B2 99584
#define TB_TOTAL 99840

__global__ __launch_bounds__(256, 2) void k_tab_mma(
    const float* __restrict__ wr2, const float* __restrict__ wr2b,
    const float* __restrict__ att1) {
  extern __shared__ char smc[];
  const int t = threadIdx.x;
  const int lane = t & 31, w = t >> 5;
  uint32_t sb = smem_u32(smc);

  for (int i = t; i < 2048; i += 256) {
    int n = i >> 5, c2 = i & 31;
    float h0, l0, h1, l1;
    split2(wr2[n * 64 + 2 * c2], h0, l0);
    split2(wr2[n * 64 + 2 * c2 + 1], h1, l1);
    st_pair(smc + TB_W1H, n, c2, pack_bf16(h0, h1));
    st_pair(smc + TB_W1L, n, c2, pack_bf16(l0, l1));
    split2(att1[n * 128 + 2 * c2], h0, l0);
    split2(att1[n * 128 + 2 * c2 + 1], h1, l1);
    st_pair(smc + TB_W2H, n, c2, pack_bf16(h0, h1));
    st_pair(smc + TB_W2L, n, c2, pack_bf16(l0, l1));
  }
  for (int i = t; i < N_R * 64; i += 256) ((float*)(smc + TB_RP))[i] = g_rproj[i];
  if (t < 64) ((float*)(smc + TB_B2))[t] = wr2b[t];
  __syncthreads();

  const int rowi = t & 127;
  const int chalf = t >> 7;
  const int mh = w & 3, nh = w >> 2;
  const int m0 = mh * 32, n0 = nh * 32;
  const int g = lane >> 2, q = lane & 3;
  const float* b2 = (const float*)(smc + TB_B2);
  float* ot = (float*)g_otab;
  float* at = (float*)g_a1tab;

  for (int tile = blockIdx.x; tile < N_TAB_TILES; tile += gridDim.x) {
    const long blk0 = (long)tile * 128;
    {
      long row = blk0 + rowi;
      long rc = (row < N_PAIRS) ? row : (N_PAIRS - 1);
      int item = (int)(rc / 5);
      int rr_ = (int)(rc - (long)item * 5);
      const float4* Pp = &g_P[(long)item * 16 + chalf * 8];
      const float* rp = (const float*)(smc + TB_RP) + rr_ * 64 + chalf * 32;
#pragma unroll
      for (int i = 0; i < 8; i++) {
        float4 p = Pp[i];
        float v0 = fmaxf(p.x + rp[4 * i + 0], 0.f);
        float v1 = fmaxf(p.y + rp[4 * i + 1], 0.f);
        float v2 = fmaxf(p.z + rp[4 * i + 2], 0.f);
        float v3 = fmaxf(p.w + rp[4 * i + 3], 0.f);
        int col4 = chalf * 32 + 4 * i;
        float h0, l0, h1, l1, h2, l2, h3, l3;
        split2(v0, h0, l0); split2(v1, h1, l1);
        split2(v2, h2, l2); split2(v3, h3, l3);
        st_quad(smc + TB_AH, rowi, col4, pack_bf16(h0, h1), pack_bf16(h2, h3));
        st_quad(smc + TB_AL, rowi, col4, pack_bf16(l0, l1), pack_bf16(l2, l3));
      }
    }
    __syncthreads();

    float c[2][4][4];
    warp_gemm_32x32(c, sb + TB_AH, sb + TB_AL, sb + TB_W1H, sb + TB_W1L, m0, n0, lane);

#pragma unroll
    for (int mt = 0; mt < 2; mt++)
#pragma unroll
      for (int half = 0; half < 2; half++) {
        int lr = m0 + mt * 16 + g + half * 8;
        long rowg = blk0 + lr;
#pragma unroll
        for (int nt = 0; nt < 4; nt++) {
          int col = n0 + nt * 8 + q * 2;
          float v0 = fmaxf(c[mt][nt][half * 2 + 0] + b2[col], 0.f);
          float v1 = fmaxf(c[mt][nt][half * 2 + 1] + b2[col + 1], 0.f);
          if (rowg < N_PAIRS)
            *(float2*)&ot[rowg * 64 + col] = make_float2(v0, v1);
          float h0, l0, h1, l1;
          split2(v0, h0, l0); split2(v1, h1, l1);
          st_pair(smc + TB_OH, lr, col >> 1, pack_bf16(h0, h1));
          st_pair(smc + TB_OL, lr, col >> 1, pack_bf16(l0, l1));
        }
      }
    __syncthreads();

    warp_gemm_32x32(c, sb + TB_OH, sb + TB_OL, sb + TB_W2H, sb + TB_W2L, m0, n0, lane);
#pragma unroll
    for (int mt = 0; mt < 2; mt++)
#pragma unroll
      for (int half = 0; half < 2; half++) {
        int lr = m0 + mt * 16 + g + half * 8;
        long rowg = blk0 + lr;
        if (rowg < N_PAIRS) {
#pragma unroll
          for (int nt = 0; nt < 4; nt++) {
            int col = n0 + nt * 8 + q * 2;
            *(float2*)&at[rowg * 64 + col] =
                make_float2(c[mt][nt][half * 2 + 0], c[mt][nt][half * 2 + 1]);
          }
        }
      }
  }
}

// ---------------- K_LOGIT (mma.sync, persistent) ----------------
#define LB_AH 0
#define LB_AL 16384
#define LB_WH 32768
#define LB_WL 40960
#define LB_A3 49152
#define LB_A2B 49408
#define LB_A3B 49664
#define LB_PART 49680
#define LB_TOTAL 50704

__global__ __launch_bounds__(256, 2) void k_logit_mma(
    const int* __restrict__ hui, const int* __restrict__ hr,
    const float* __restrict__ att2w, const float* __restrict__ att2b_,
    const float* __restrict__ att3w, const float* __restrict__ att3b_) {
  extern __shared__ char smc[];
  const int t = threadIdx.x;
  const int lane = t & 31, w = t >> 5;
  uint32_t sb = smem_u32(smc);

  for (int i = t; i < 2048; i += 256) {
    int n = i >> 5, c2 = i & 31;
    float h0, l0, h1, l1;
    split2(att2w[n * 64 + 2 * c2], h0, l0);
    split2(att2w[n * 64 + 2 * c2 + 1], h1, l1);
    st_pair(smc + LB_WH, n, c2, pack_bf16(h0, h1));
    st_pair(smc + LB_WL, n, c2, pack_bf16(l0, l1));
  }
  if (t < 64) {
    ((float*)(smc + LB_A3))[t] = att3w[t];
    ((float*)(smc + LB_A2B))[t] = att2b_[t];
  }
  if (t == 0) *(float*)(smc + LB_A3B) = att3b_[0];
  __syncthreads();

  const int rowi = t & 127;
  const int chalf = t >> 7;
  const int mh = w & 3, nh = w >> 2;
  const int m0 = mh * 32, n0 = nh * 32;
  const int g = lane >> 2, q = lane & 3;
  const float* a3 = (const float*)(smc + LB_A3);
  const float* a2b = (const float*)(smc + LB_A2B);
  const float a3b = *(const float*)(smc + LB_A3B);
  float* part = (float*)(smc + LB_PART);

  for (int tile = blockIdx.x; tile < N_LOG_TILES; tile += gridDim.x) {
    {
      const int e = tile * 128 + rowi;
      int b = e / HH;
      long ir = (long)hui[e] * 5 + hr[e];
      const float4* Ag = &g_a1tab[ir * 16 + chalf * 8];
      const float4* Ug = (const float4*)&g_uatt[b * 64] + chalf * 8;
#pragma unroll
      for (int i = 0; i < 8; i++) {
        float4 p = Ag[i], qv = Ug[i];
        float v0 = fmaxf(p.x + qv.x, 0.f), v1 = fmaxf(p.y + qv.y, 0.f);
        float v2 = fmaxf(p.z + qv.z, 0.f), v3 = fmaxf(p.w + qv.w, 0.f);
        int col4 = chalf * 32 + 4 * i;
        float h0, l0, h1, l1, h2, l2, h3, l3;
        split2(v0, h0, l0); split2(v1, h1, l1);
        split2(v2, h2, l2); split2(v3, h3, l3);
        st_quad(smc + LB_AH, rowi, col4, pack_bf16(h0, h1), pack_bf16(h2, h3));
        st_quad(smc + LB_AL, rowi, col4, pack_bf16(l0, l1), pack_bf16(l2, l3));
      }
    }
    __syncthreads();

    float c[2][4][4];
    warp_gemm_32x32(c, sb + LB_AH, sb + LB_AL, sb + LB_WH, sb + LB_WL, m0, n0, lane);

#pragma unroll
    for (int mt = 0; mt < 2; mt++)
#pragma unroll
      for (int half = 0; half < 2; half++) {
        int lr = m0 + mt * 16 + g + half * 8;
        float pt = 0.0f;
#pragma unroll
        for (int nt = 0; nt < 4; nt++) {
          int col = n0 + nt * 8 + q * 2;
          pt = fmaf(a3[col], fmaxf(c[mt][nt][half * 2 + 0] + a2b[col], 0.f), pt);
          pt = fmaf(a3[col + 1], fmaxf(c[mt][nt][half * 2 + 1] + a2b[col + 1], 0.f), pt);
        }
        pt += __shfl_xor_sync(0xffffffffu, pt, 1);
        pt += __shfl_xor_sync(0xffffffffu, pt, 2);
        if (q == 0) part[lr * 2 + nh] = pt;
      }
    __syncthreads();

    if (t < 128)
      g_logit[tile * 128 + t] = part[t * 2] + part[t * 2 + 1] + a3b;
  }
}

// ---------------- K_AGG: softmax + weighted o-sum + final linear ----------------
__global__ __launch_bounds__(256) void k_agg(
    const int* __restrict__ hui, const int* __restrict__ hr,
    const float* __restrict__ lin1, float* __restrict__ out) {
  __shared__ float s_lin[64 * 65];
  __shared__ float s_lg[AGG_NB * HH];
  __shared__ float s_pp[AGG_NB * HH];
  __shared__ int   s_ir[AGG_NB * HH];
  __shared__ float s_inv[AGG_NB];
  __shared__ float s_ng[AGG_NB * 64];
  __shared__ float s_ul[AGG_NB * 64];

  const int t = threadIdx.x;
  const int b0 = blockIdx.x * AGG_NB;

  for (int i = t; i < 4096; i += 256) {
    int d = i >> 6, k = i & 63;
    s_lin[d * 65 + k] = lin1[d * 128 + 64 + k];
  }
  for (int i = t; i < AGG_NB * HH; i += 256) {
    int e = b0 * HH + i;
    s_lg[i] = g_logit[e];
    s_ir[i] = hui[e] * 5 + hr[e];
  }
  for (int i = t; i < AGG_NB * 64; i += 256) s_ul[i] = g_ulin[b0 * 64 + i];
  __syncthreads();

  {
    const int wid = t >> 5, lane = t & 31;
#pragma unroll
    for (int rr = 0; rr < 2; rr++) {
      int rowb = wid * 2 + rr;
      const float* L = &s_lg[rowb * HH];
      float v1 = L[lane];
      float v2 = (lane < HH - 32) ? L[32 + lane] : -1e30f;
      float m = fmaxf(v1, v2);
#pragma unroll
      for (int off = 16; off > 0; off >>= 1)
        m = fmaxf(m, __shfl_xor_sync(0xffffffffu, m, off));
      float e1 = __expf(v1 - m);
      float e2 = (lane < HH - 32) ? __expf(v2 - m) : 0.0f;
      s_pp[rowb * HH + lane] = e1;
      if (lane < HH - 32) s_pp[rowb * HH + 32 + lane] = e2;
      float s = e1 + e2;
#pragma unroll
      for (int off = 16; off > 0; off >>= 1)
        s += __shfl_xor_sync(0xffffffffu, s, off);
      if (lane == 0) s_inv[rowb] = 1.0f / s;
    }
  }
  __syncthreads();

  // neigh: each thread owns a d-PAIR (float2 loads -> 2x payload per load)
  const float2* ot2 = (const float2*)g_otab;
  for (int oi = t; oi < AGG_NB * 32; oi += 256) {
    int bl = oi >> 5, dp = oi & 31;
    const float* pr = &s_pp[bl * HH];
    const int* irr = &s_ir[bl * HH];
    float ax = 0.0f, ay = 0.0f;
#pragma unroll 10
    for (int h = 0; h < HH; h++) {
      float2 v = ot2[(long)irr[h] * 32 + dp];
      float p = pr[h];
      ax = fmaf(p, v.x, ax);
      ay = fmaf(p, v.y, ay);
    }
    float inv = s_inv[bl];
    s_ng[bl * 64 + dp * 2] = ax * inv;
    s_ng[bl * 64 + dp * 2 + 1] = ay * inv;
  }
  __syncthreads();

  for (int oi = t; oi < AGG_NB * 64; oi += 256) {
    int bl = oi >> 6, d = oi & 63;
    float acc = s_ul[oi];
    const float* ng = &s_ng[bl * 64];
#pragma unroll
    for (int k = 0; k < 64; k++)
      acc = fmaf(s_lin[d * 65 + k], ng[k], acc);
    out[(long)(b0 + bl) * 64 + d] = fmaxf(acc, 0.0f);
  }
}

extern "C" void kernel_launch(void* const* d_in, const int* in_sizes, int n_in,
                              void* d_out, int out_size) {
  const int*   nodes = (const int*)d_in[0];
  const int*   hui   = (const int*)d_in[1];
  const int*   hr    = (const int*)d_in[2];
  const float* u2e   = (const float*)d_in[3];
  const float* i2e   = (const float*)d_in[4];
  const float* r2e   = (const float*)d_in[5];
  const float* wr1   = (const float*)d_in[6];
  const float* wr1b  = (const float*)d_in[7];
  const float* wr2   = (const float*)d_in[8];
  const float* wr2b  = (const float*)d_in[9];
  const float* att1  = (const float*)d_in[10];
  const float* att1b = (const float*)d_in[11];
  const float* att2  = (const float*)d_in[12];
  const float* att2b = (const float*)d_in[13];
  const float* att3  = (const float*)d_in[14];
  const float* att3b = (const float*)d_in[15];
  const float* lin1  = (const float*)d_in[16];
  const float* lin1b = (const float*)d_in[17];
  float* out = (float*)d_out;

  cudaFuncSetAttribute(k_P_mma, cudaFuncAttributeMaxDynamicSharedMemorySize, PB_TOTAL);
  cudaFuncSetAttribute(k_tab_mma, cudaFuncAttributeMaxDynamicSharedMemorySize, TB_TOTAL);
  cudaFuncSetAttribute(k_logit_mma, cudaFuncAttributeMaxDynamicSharedMemorySize, LB_TOTAL);

  k_P_mma<<<PERSIST_GRID, 256, PB_TOTAL>>>(i2e, wr1);
  k_rproj<<<1, 320>>>(wr1, wr1b, r2e);
  k_utab<<<BB / 64, 256>>>(nodes, u2e, att1, att1b, lin1, lin1b);
  k_tab_mma<<<PERSIST_GRID, 256, TB_TOTAL>>>(wr2, wr2b, att1);
  k_logit_mma<<<PERSIST_GRID, 256, LB_TOTAL>>>(hui, hr, att2, att2b, att3, att3b);
  k_agg<<<BB / AGG_NB, 256>>>(hui, hr, lin1, out);
}

// round 15
// speedup vs baseline: 3.8363x; 1.0430x over previous
#include <cuda_runtime.h>
#include <cuda_bf16.h>
#include <cstdint>

#define BB 16384
#define HH 50
#define N_ITEMS 100000
#define N_R 5
#define N_PAIRS (N_ITEMS * N_R)
#define N_EDGES (BB * HH)
#define AGG_NB 16
#define N_TAB_TILES ((N_PAIRS + 127) / 128)
#define N_LOG_TILES (N_EDGES / 128)
#define N_P_TILES ((N_ITEMS + 127) / 128)
#define PERSIST_GRID 296

// ---------------- persistent device tables ----------------
__device__ float4 g_P[N_ITEMS * 16];       // W_r1a @ i2e[item]
__device__ float4 g_otab[N_PAIRS * 16];    // o per (item,r)
__device__ float4 g_a1tab[N_PAIRS * 16];   // att1a @ o per (item,r)
__device__ float  g_uatt[BB * 64];
__device__ float  g_ulin[BB * 64];
__device__ float  g_rproj[N_R * 64];
__device__ float  g_logit[N_EDGES];

// ---------------- helpers ----------------
__device__ __forceinline__ uint32_t smem_u32(const void* p) {
  uint32_t a;
  asm("{ .reg .u64 t; cvta.to.shared.u64 t, %1; cvt.u32.u64 %0, t; }" : "=r"(a) : "l"(p));
  return a;
}
__device__ __forceinline__ void split2(float x, float& hi, float& lo) {
  __nv_bfloat16 h = __float2bfloat16_rn(x);
  hi = __bfloat162float(h);
  lo = x - hi;
}
__device__ __forceinline__ uint32_t pack_bf16(float a, float b) {
  __nv_bfloat162 h = __floats2bfloat162_rn(a, b);
  return *(uint32_t*)&h;
}
// bf16 tile rows: 64 cols = 128B = 8 chunks of 16B; swizzle chunk ^= (row&7)
__device__ __forceinline__ void st_pair(char* base, int row, int cp, uint32_t v) {
  int col = cp * 2;
  uint32_t off = row * 128 + ((((col >> 3) ^ row) & 7) << 4) + ((col & 7) << 1);
  *(uint32_t*)(base + off) = v;
}
// 16-byte store of one full swizzle chunk (8 bf16 cols, col8 % 8 == 0)
__device__ __forceinline__ void st_oct(char* base, int row, int col8,
                                       uint32_t v0, uint32_t v1,
                                       uint32_t v2, uint32_t v3) {
  uint32_t off = row * 128 + ((((col8 >> 3) ^ row) & 7) << 4);
  *(uint4*)(base + off) = make_uint4(v0, v1, v2, v3);
}
__device__ __forceinline__ void ldsm4(uint32_t& r0, uint32_t& r1, uint32_t& r2,
                                      uint32_t& r3, uint32_t addr) {
  asm volatile("ldmatrix.sync.aligned.m8n8.x4.shared.b16 {%0,%1,%2,%3}, [%4];"
               : "=r"(r0), "=r"(r1), "=r"(r2), "=r"(r3) : "r"(addr));
}
__device__ __forceinline__ void stmat4(uint32_t addr, const uint32_t* r) {
  asm volatile("stmatrix.sync.aligned.m8n8.x4.shared.b16 [%0], {%1,%2,%3,%4};"
               :: "r"(addr), "r"(r[0]), "r"(r[1]), "r"(r[2]), "r"(r[3]) : "memory");
}
__device__ __forceinline__ void mma16816(float* c, const uint32_t* a, const uint32_t* b) {
  asm volatile(
      "mma.sync.aligned.m16n8k16.row.col.f32.bf16.bf16.f32 "
      "{%0,%1,%2,%3}, {%4,%5,%6,%7}, {%8,%9}, {%0,%1,%2,%3};"
      : "+f"(c[0]), "+f"(c[1]), "+f"(c[2]), "+f"(c[3])
      : "r"(a[0]), "r"(a[1]), "r"(a[2]), "r"(a[3]), "r"(b[0]), "r"(b[1]));
}

// Warp GEMM: C[32x32] += A[32rows x 64k] @ B[32rows x 64k]^T, 3-term hi/lo bf16.
// k-step outermost: Ah/Bh fragments loaded ONCE per k-step (8 ldsm4/k-step).
__device__ __forceinline__ void warp_gemm_32x32(float c[2][4][4], uint32_t aH, uint32_t aL,
                                                uint32_t bH, uint32_t bL, int m0, int n0,
                                                int lane) {
  const int r = lane & 7, sel = lane >> 3;
  const int arow = r + (sel & 1) * 8, ach = sel >> 1;
  const int brow = r + (sel >> 1) * 8, bch = sel & 1;
#pragma unroll
  for (int mt = 0; mt < 2; mt++)
#pragma unroll
    for (int nt = 0; nt < 4; nt++)
#pragma unroll
      for (int i = 0; i < 4; i++) c[mt][nt][i] = 0.0f;

#pragma unroll
  for (int ks = 0; ks < 4; ks++) {
    const int cha = 2 * ks + ach;
    const int chb = 2 * ks + bch;
    uint32_t ah[2][4], al[2][4], bh[2][4], bl[2][4];
#pragma unroll
    for (int mt = 0; mt < 2; mt++) {
      int rowa = m0 + mt * 16 + arow;
      ldsm4(ah[mt][0], ah[mt][1], ah[mt][2], ah[mt][3],
            aH + rowa * 128 + (((cha ^ rowa) & 7) << 4));
    }
#pragma unroll
    for (int nb = 0; nb < 2; nb++) {
      int rowb = n0 + nb * 16 + brow;
      ldsm4(bh[nb][0], bh[nb][1], bh[nb][2], bh[nb][3],
            bH + rowb * 128 + (((chb ^ rowb) & 7) << 4));
    }
#pragma unroll
    for (int mt = 0; mt < 2; mt++)
#pragma unroll
      for (int nt = 0; nt < 4; nt++)
        mma16816(c[mt][nt], ah[mt], &bh[nt >> 1][(nt & 1) * 2]);
#pragma unroll
    for (int nb = 0; nb < 2; nb++) {
      int rowb = n0 + nb * 16 + brow;
      ldsm4(bl[nb][0], bl[nb][1], bl[nb][2], bl[nb][3],
            bL + rowb * 128 + (((chb ^ rowb) & 7) << 4));
    }
#pragma unroll
    for (int mt = 0; mt < 2; mt++)
#pragma unroll
      for (int nt = 0; nt < 4; nt++)
        mma16816(c[mt][nt], ah[mt], &bl[nt >> 1][(nt & 1) * 2]);
#pragma unroll
    for (int mt = 0; mt < 2; mt++) {
      int rowa = m0 + mt * 16 + arow;
      ldsm4(al[mt][0], al[mt][1], al[mt][2], al[mt][3],
            aL + rowa * 128 + (((cha ^ rowa) & 7) << 4));
    }
#pragma unroll
    for (int mt = 0; mt < 2; mt++)
#pragma unroll
      for (int nt = 0; nt < 4; nt++)
        mma16816(c[mt][nt], al[mt], &bh[nt >> 1][(nt & 1) * 2]);
  }
}

// Split 8 floats and store one hi + one lo 16B chunk.
__device__ __forceinline__ void build_oct(char* hiB, char* loB, int row, int col8,
                                          const float* v) {
  float h[8], l[8];
#pragma unroll
  for (int j = 0; j < 8; j++) split2(v[j], h[j], l[j]);
  st_oct(hiB, row, col8, pack_bf16(h[0], h[1]), pack_bf16(h[2], h[3]),
         pack_bf16(h[4], h[5]), pack_bf16(h[6], h[7]));
  st_oct(loB, row, col8, pack_bf16(l[0], l[1]), pack_bf16(l[2], l[3]),
         pack_bf16(l[4], l[5]), pack_bf16(l[6], l[7]));
}

// ---------------- K_P (mma.sync): P = i2e @ W_r1a^T ----------------
#define PB_AH 0
#define PB_AL 16384
#define PB_WH 32768
#define PB_WL 40960
#define PB_TOTAL 49152

__global__ __launch_bounds__(256, 2) void k_P_mma(
    const float* __restrict__ i2e, const float* __restrict__ wr1) {
  extern __shared__ char smc[];
  const int t = threadIdx.x;
  const int lane = t & 31, w = t >> 5;
  uint32_t sb = smem_u32(smc);

  for (int i = t; i < 2048; i += 256) {
    int n = i >> 5, c2 = i & 31;
    float h0, l0, h1, l1;
    split2(wr1[n * 128 + 2 * c2], h0, l0);
    split2(wr1[n * 128 + 2 * c2 + 1], h1, l1);
    st_pair(smc + PB_WH, n, c2, pack_bf16(h0, h1));
    st_pair(smc + PB_WL, n, c2, pack_bf16(l0, l1));
  }
  __syncthreads();

  const int rowi = t & 127;
  const int chalf = t >> 7;
  const int mh = w & 3, nh = w >> 2;
  const int m0 = mh * 32, n0 = nh * 32;
  const int g = lane >> 2, q = lane & 3;
  float* gP = (float*)g_P;

  for (int tile = blockIdx.x; tile < N_P_TILES; tile += gridDim.x) {
    const long blk0 = (long)tile * 128;
    {
      long row = blk0 + rowi;
      long rc = (row < N_ITEMS) ? row : (N_ITEMS - 1);
      const float4* Ep = (const float4*)&i2e[rc * 64] + chalf * 8;
#pragma unroll
      for (int i = 0; i < 4; i++) {
        float4 p0 = Ep[2 * i], p1 = Ep[2 * i + 1];
        float v[8] = {p0.x, p0.y, p0.z, p0.w, p1.x, p1.y, p1.z, p1.w};
        build_oct(smc + PB_AH, smc + PB_AL, rowi, chalf * 32 + 8 * i, v);
      }
    }
    __syncthreads();

    float c[2][4][4];
    warp_gemm_32x32(c, sb + PB_AH, sb + PB_AL, sb + PB_WH, sb + PB_WL, m0, n0, lane);
#pragma unroll
    for (int mt = 0; mt < 2; mt++)
#pragma unroll
      for (int half = 0; half < 2; half++) {
        int lr = m0 + mt * 16 + g + half * 8;
        long rowg = blk0 + lr;
        if (rowg < N_ITEMS) {
#pragma unroll
          for (int nt = 0; nt < 4; nt++) {
            int col = n0 + nt * 8 + q * 2;
            *(float2*)&gP[rowg * 64 + col] =
                make_float2(c[mt][nt][half * 2 + 0], c[mt][nt][half * 2 + 1]);
          }
        }
      }
    __syncthreads();
  }
}

// ---------------- K_R ----------------
__global__ void k_rproj(const float* __restrict__ wr1,
                        const float* __restrict__ wr1b,
                        const float* __restrict__ r2e) {
  int t = threadIdx.x;
  if (t < N_R * 64) {
    int r = t >> 6, d = t & 63;
    float acc = wr1b[d];
#pragma unroll
    for (int k = 0; k < 64; k++)
      acc = fmaf(wr1[d * 128 + 64 + k], r2e[r * 64 + k], acc);
    g_rproj[r * 64 + d] = acc;
  }
}

// ---------------- K_U ----------------
__global__ __launch_bounds__(256) void k_utab(
    const int* __restrict__ nodes, const float* __restrict__ u2e,
    const float* __restrict__ att1, const float* __restrict__ att1b,
    const float* __restrict__ lin1, const float* __restrict__ lin1b) {
  __shared__ float a_s[64 * 65];
  __shared__ float l_s[64 * 65];
  __shared__ float u_s[4 * 64];
  const int t = threadIdx.x;

  for (int i = t; i < 4096; i += 256) {
    int d = i >> 6, k = i & 63;
    a_s[d * 65 + k] = att1[d * 128 + 64 + k];
    l_s[d * 65 + k] = lin1[d * 128 + k];
  }
  const int b0 = blockIdx.x * 64;
  const int bb = t >> 6, d = t & 63;
  for (int it = 0; it < 16; it++) {
    __syncthreads();
    {
      int b = b0 + it * 4 + bb;
      u_s[t] = u2e[(long)nodes[b] * 64 + d];
    }
    __syncthreads();
    const float* uu = &u_s[bb * 64];
    float au = att1b[d], lu = lin1b[d];
#pragma unroll
    for (int k = 0; k < 64; k++) {
      float uv = uu[k];
      au = fmaf(a_s[d * 65 + k], uv, au);
      lu = fmaf(l_s[d * 65 + k], uv, lu);
    }
    int b = b0 + it * 4 + bb;
    g_uatt[b * 64 + d] = au;
    g_ulin[b * 64 + d] = lu;
  }
}

// ---------------- K_TAB (mma.sync, persistent, stmatrix epilogue) ----------------
#define TB_AH 0
#define TB_AL 16384
#define TB_OH 32768
#define TB_OL 49152
#define TB_W1H 65536
#define TB_W1L 73728
#define TB_W2H 81920
#define TB_W2L 90112
#define TB_RP 98304
#define TB_B2 99584
#define TB_TOTAL 99840

__global__ __launch_bounds__(256, 2) void k_tab_mma(
    const float* __restrict__ wr2, const float* __restrict__ wr2b,
    const float* __restrict__ att1) {
  extern __shared__ char smc[];
  const int t = threadIdx.x;
  const int lane = t & 31, w = t >> 5;
  uint32_t sb = smem_u32(smc);

  for (int i = t; i < 2048; i += 256) {
    int n = i >> 5, c2 = i & 31;
    float h0, l0, h1, l1;
    split2(wr2[n * 64 + 2 * c2], h0, l0);
    split2(wr2[n * 64 + 2 * c2 + 1], h1, l1);
    st_pair(smc + TB_W1H, n, c2, pack_bf16(h0, h1));
    st_pair(smc + TB_W1L, n, c2, pack_bf16(l0, l1));
    split2(att1[n * 128 + 2 * c2], h0, l0);
    split2(att1[n * 128 + 2 * c2 + 1], h1, l1);
    st_pair(smc + TB_W2H, n, c2, pack_bf16(h0, h1));
    st_pair(smc + TB_W2L, n, c2, pack_bf16(l0, l1));
  }
  for (int i = t; i < N_R * 64; i += 256) ((float*)(smc + TB_RP))[i] = g_rproj[i];
  if (t < 64) ((float*)(smc + TB_B2))[t] = wr2b[t];
  __syncthreads();

  const int rowi = t & 127;
  const int chalf = t >> 7;
  const int mh = w & 3, nh = w >> 2;
  const int m0 = mh * 32, n0 = nh * 32;
  const int g = lane >> 2, q = lane & 3;
  const float* b2 = (const float*)(smc + TB_B2);
  float* ot = (float*)g_otab;
  float* at = (float*)g_a1tab;
  // stmatrix per-lane address components (x4: lane/8 = matrix index = nt)
  const int sm_nt = lane >> 3, sm_r = lane & 7;

  for (int tile = blockIdx.x; tile < N_TAB_TILES; tile += gridDim.x) {
    const long blk0 = (long)tile * 128;
    {
      long row = blk0 + rowi;
      long rc = (row < N_PAIRS) ? row : (N_PAIRS - 1);
      int item = (int)(rc / 5);
      int rr_ = (int)(rc - (long)item * 5);
      const float4* Pp = &g_P[(long)item * 16 + chalf * 8];
      const float* rp = (const float*)(smc + TB_RP) + rr_ * 64 + chalf * 32;
#pragma unroll
      for (int i = 0; i < 4; i++) {
        float4 p0 = Pp[2 * i], p1 = Pp[2 * i + 1];
        const float* rpp = rp + 8 * i;
        float v[8] = {fmaxf(p0.x + rpp[0], 0.f), fmaxf(p0.y + rpp[1], 0.f),
                      fmaxf(p0.z + rpp[2], 0.f), fmaxf(p0.w + rpp[3], 0.f),
                      fmaxf(p1.x + rpp[4], 0.f), fmaxf(p1.y + rpp[5], 0.f),
                      fmaxf(p1.z + rpp[6], 0.f), fmaxf(p1.w + rpp[7], 0.f)};
        build_oct(smc + TB_AH, smc + TB_AL, rowi, chalf * 32 + 8 * i, v);
      }
    }
    __syncthreads();

    float c[2][4][4];
    warp_gemm_32x32(c, sb + TB_AH, sb + TB_AL, sb + TB_W1H, sb + TB_W1L, m0, n0, lane);

    // epilogue 1: gmem otab + stmatrix into O tiles
#pragma unroll
    for (int mt = 0; mt < 2; mt++)
#pragma unroll
      for (int half = 0; half < 2; half++) {
        int lr = m0 + mt * 16 + g + half * 8;
        long rowg = blk0 + lr;
        uint32_t hi4[4], lo4[4];
#pragma unroll
        for (int nt = 0; nt < 4; nt++) {
          int col = n0 + nt * 8 + q * 2;
          float v0 = fmaxf(c[mt][nt][half * 2 + 0] + b2[col], 0.f);
          float v1 = fmaxf(c[mt][nt][half * 2 + 1] + b2[col + 1], 0.f);
          if (rowg < N_PAIRS)
            *(float2*)&ot[rowg * 64 + col] = make_float2(v0, v1);
          float h0, l0, h1, l1;
          split2(v0, h0, l0); split2(v1, h1, l1);
          hi4[nt] = pack_bf16(h0, h1);
          lo4[nt] = pack_bf16(l0, l1);
        }
        int srow = m0 + mt * 16 + half * 8 + sm_r;
        int ch = (n0 >> 3) + sm_nt;
        uint32_t off = srow * 128 + (((ch ^ srow) & 7) << 4);
        stmat4(sb + TB_OH + off, hi4);
        stmat4(sb + TB_OL + off, lo4);
      }
    __syncthreads();

    warp_gemm_32x32(c, sb + TB_OH, sb + TB_OL, sb + TB_W2H, sb + TB_W2L, m0, n0, lane);
#pragma unroll
    for (int mt = 0; mt < 2; mt++)
#pragma unroll
      for (int half = 0; half < 2; half++) {
        int lr = m0 + mt * 16 + g + half * 8;
        long rowg = blk0 + lr;
        if (rowg < N_PAIRS) {
#pragma unroll
          for (int nt = 0; nt < 4; nt++) {
            int col = n0 + nt * 8 + q * 2;
            *(float2*)&at[rowg * 64 + col] =
                make_float2(c[mt][nt][half * 2 + 0], c[mt][nt][half * 2 + 1]);
          }
        }
      }
  }
}

// ---------------- K_LOGIT (mma.sync, persistent) ----------------
#define LB_AH 0
#define LB_AL 16384
#define LB_WH 32768
#define LB_WL 40960
#define LB_A3 49152
#define LB_A2B 49408
#define LB_A3B 49664
#define LB_PART 49680
#define LB_TOTAL 50704

__global__ __launch_bounds__(256, 2) void k_logit_mma(
    const int* __restrict__ hui, const int* __restrict__ hr,
    const float* __restrict__ att2w, const float* __restrict__ att2b_,
    const float* __restrict__ att3w, const float* __restrict__ att3b_) {
  extern __shared__ char smc[];
  const int t = threadIdx.x;
  const int lane = t & 31, w = t >> 5;
  uint32_t sb = smem_u32(smc);

  for (int i = t; i < 2048; i += 256) {
    int n = i >> 5, c2 = i & 31;
    float h0, l0, h1, l1;
    split2(att2w[n * 64 + 2 * c2], h0, l0);
    split2(att2w[n * 64 + 2 * c2 + 1], h1, l1);
    st_pair(smc + LB_WH, n, c2, pack_bf16(h0, h1));
    st_pair(smc + LB_WL, n, c2, pack_bf16(l0, l1));
  }
  if (t < 64) {
    ((float*)(smc + LB_A3))[t] = att3w[t];
    ((float*)(smc + LB_A2B))[t] = att2b_[t];
  }
  if (t == 0) *(float*)(smc + LB_A3B) = att3b_[0];
  __syncthreads();

  const int rowi = t & 127;
  const int chalf = t >> 7;
  const int mh = w & 3, nh = w >> 2;
  const int m0 = mh * 32, n0 = nh * 32;
  const int g = lane >> 2, q = lane & 3;
  const float* a3 = (const float*)(smc + LB_A3);
  const float* a2b = (const float*)(smc + LB_A2B);
  const float a3b = *(const float*)(smc + LB_A3B);
  float* part = (float*)(smc + LB_PART);

  for (int tile = blockIdx.x; tile < N_LOG_TILES; tile += gridDim.x) {
    {
      const int e = tile * 128 + rowi;
      int b = e / HH;
      long ir = (long)hui[e] * 5 + hr[e];
      const float4* Ag = &g_a1tab[ir * 16 + chalf * 8];
      const float4* Ug = (const float4*)&g_uatt[b * 64] + chalf * 8;
#pragma unroll
      for (int i = 0; i < 4; i++) {
        float4 p0 = Ag[2 * i], p1 = Ag[2 * i + 1];
        float4 q0 = Ug[2 * i], q1 = Ug[2 * i + 1];
        float v[8] = {fmaxf(p0.x + q0.x, 0.f), fmaxf(p0.y + q0.y, 0.f),
                      fmaxf(p0.z + q0.z, 0.f), fmaxf(p0.w + q0.w, 0.f),
                      fmaxf(p1.x + q1.x, 0.f), fmaxf(p1.y + q1.y, 0.f),
                      fmaxf(p1.z + q1.z, 0.f), fmaxf(p1.w + q1.w, 0.f)};
        build_oct(smc + LB_AH, smc + LB_AL, rowi, chalf * 32 + 8 * i, v);
      }
    }
    __syncthreads();

    float c[2][4][4];
    warp_gemm_32x32(c, sb + LB_AH, sb + LB_AL, sb + LB_WH, sb + LB_WL, m0, n0, lane);

#pragma unroll
    for (int mt = 0; mt < 2; mt++)
#pragma unroll
      for (int half = 0; half < 2; half++) {
        int lr = m0 + mt * 16 + g + half * 8;
        float pt = 0.0f;
#pragma unroll
        for (int nt = 0; nt < 4; nt++) {
          int col = n0 + nt * 8 + q * 2;
          pt = fmaf(a3[col], fmaxf(c[mt][nt][half * 2 + 0] + a2b[col], 0.f), pt);
          pt = fmaf(a3[col + 1], fmaxf(c[mt][nt][half * 2 + 1] + a2b[col + 1], 0.f), pt);
        }
        pt += __shfl_xor_sync(0xffffffffu, pt, 1);
        pt += __shfl_xor_sync(0xffffffffu, pt, 2);
        if (q == 0) part[lr * 2 + nh] = pt;
      }
    __syncthreads();

    if (t < 128)
      g_logit[tile * 128 + t] = part[t * 2] + part[t * 2 + 1] + a3b;
  }
}

// ---------------- K_AGG: softmax + weighted o-sum + final linear ----------------
__global__ __launch_bounds__(256) void k_agg(
    const int* __restrict__ hui, const int* __restrict__ hr,
    const float* __restrict__ lin1, float* __restrict__ out) {
  __shared__ float s_lin[64 * 65];
  __shared__ float s_lg[AGG_NB * HH];
  __shared__ float s_pp[AGG_NB * HH];
  __shared__ int   s_ir[AGG_NB * HH];
  __shared__ float s_inv[AGG_NB];
  __shared__ float s_ng[AGG_NB * 64];
  __shared__ float s_ul[AGG_NB * 64];

  const int t = threadIdx.x;
  const int b0 = blockIdx.x * AGG_NB;

  for (int i = t; i < 4096; i += 256) {
    int d = i >> 6, k = i & 63;
    s_lin[d * 65 + k] = lin1[d * 128 + 64 + k];
  }
  for (int i = t; i < AGG_NB * HH; i += 256) {
    int e = b0 * HH + i;
    s_lg[i] = g_logit[e];
    s_ir[i] = hui[e] * 5 + hr[e];
  }
  for (int i = t; i < AGG_NB * 64; i += 256) s_ul[i] = g_ulin[b0 * 64 + i];
  __syncthreads();

  {
    const int wid = t >> 5, lane = t & 31;
#pragma unroll
    for (int rr = 0; rr < 2; rr++) {
      int rowb = wid * 2 + rr;
      const float* L = &s_lg[rowb * HH];
      float v1 = L[lane];
      float v2 = (lane < HH - 32) ? L[32 + lane] : -1e30f;
      float m = fmaxf(v1, v2);
#pragma unroll
      for (int off = 16; off > 0; off >>= 1)
        m = fmaxf(m, __shfl_xor_sync(0xffffffffu, m, off));
      float e1 = __expf(v1 - m);
      float e2 = (lane < HH - 32) ? __expf(v2 - m) : 0.0f;
      s_pp[rowb * HH + lane] = e1;
      if (lane < HH - 32) s_pp[rowb * HH + 32 + lane] = e2;
      float s = e1 + e2;
#pragma unroll
      for (int off = 16; off > 0; off >>= 1)
        s += __shfl_xor_sync(0xffffffffu, s, off);
      if (lane == 0) s_inv[rowb] = 1.0f / s;
    }
  }
  __syncthreads();

  const float2* ot2 = (const float2*)g_otab;
  for (int oi = t; oi < AGG_NB * 32; oi += 256) {
    int bl = oi >> 5, dp = oi & 31;
    const float* pr = &s_pp[bl * HH];
    const int* irr = &s_ir[bl * HH];
    float ax = 0.0f, ay = 0.0f;
#pragma unroll 10
    for (int h = 0; h < HH; h++) {
      float2 v = ot2[(long)irr[h] * 32 + dp];
      float p = pr[h];
      ax = fmaf(p, v.x, ax);
      ay = fmaf(p, v.y, ay);
    }
    float inv = s_inv[bl];
    s_ng[bl * 64 + dp * 2] = ax * inv;
    s_ng[bl * 64 + dp * 2 + 1] = ay * inv;
  }
  __syncthreads();

  for (int oi = t; oi < AGG_NB * 64; oi += 256) {
    int bl = oi >> 6, d = oi & 63;
    float acc = s_ul[oi];
    const float* ng = &s_ng[bl * 64];
#pragma unroll
    for (int k = 0; k < 64; k++)
      acc = fmaf(s_lin[d * 65 + k], ng[k], acc);
    out[(long)(b0 + bl) * 64 + d] = fmaxf(acc, 0.0f);
  }
}

extern "C" void kernel_launch(void* const* d_in, const int* in_sizes, int n_in,
                              void* d_out, int out_size) {
  const int*   nodes = (const int*)d_in[0];
  const int*   hui   = (const int*)d_in[1];
  const int*   hr    = (const int*)d_in[2];
  const float* u2e   = (const float*)d_in[3];
  const float* i2e   = (const float*)d_in[4];
  const float* r2e   = (const float*)d_in[5];
  const float* wr1   = (const float*)d_in[6];
  const float* wr1b  = (const float*)d_in[7];
  const float* wr2   = (const float*)d_in[8];
  const float* wr2b  = (const float*)d_in[9];
  const float* att1  = (const float*)d_in[10];
  const float* att1b = (const float*)d_in[11];
  const float* att2  = (const float*)d_in[12];
  const float* att2b = (const float*)d_in[13];
  const float* att3  = (const float*)d_in[14];
  const float* att3b = (const float*)d_in[15];
  const float* lin1  = (const float*)d_in[16];
  const float* lin1b = (const float*)d_in[17];
  float* out = (float*)d_out;

  cudaFuncSetAttribute(k_P_mma, cudaFuncAttributeMaxDynamicSharedMemorySize, PB_TOTAL);
  cudaFuncSetAttribute(k_tab_mma, cudaFuncAttributeMaxDynamicSharedMemorySize, TB_TOTAL);
  cudaFuncSetAttribute(k_logit_mma, cudaFuncAttributeMaxDynamicSharedMemorySize, LB_TOTAL);

  k_P_mma<<<PERSIST_GRID, 256, PB_TOTAL>>>(i2e, wr1);
  k_rproj<<<1, 320>>>(wr1, wr1b, r2e);
  k_utab<<<BB / 64, 256>>>(nodes, u2e, att1, att1b, lin1, lin1b);
  k_tab_mma<<<PERSIST_GRID, 256, TB_TOTAL>>>(wr2, wr2b, att1);
  k_logit_mma<<<PERSIST_GRID, 256, LB_TOTAL>>>(hui, hr, att2, att2b, att3, att3b);
  k_agg<<<BB / AGG_NB, 256>>>(hui, hr, lin1, out);
}

// round 16
// speedup vs baseline: 3.8599x; 1.0062x over previous
#include <cuda_runtime.h>
#include <cuda_bf16.h>
#include <cstdint>

#define BB 16384
#define HH 50
#define N_ITEMS 100000
#define N_R 5
#define N_PAIRS (N_ITEMS * N_R)
#define N_EDGES (BB * HH)
#define AGG_NB 16
#define N_TAB_TILES ((N_PAIRS + 127) / 128)
#define N_LOG_TILES (N_EDGES / 128)
#define N_P_TILES ((N_ITEMS + 127) / 128)
#define PERSIST_GRID 296

// ---------------- persistent device tables ----------------
__device__ float4 g_P[N_ITEMS * 16];       // W_r1a @ i2e[item]
__device__ float4 g_otab[N_PAIRS * 16];    // o per (item,r)
__device__ float4 g_a1tab[N_PAIRS * 16];   // att1a @ o per (item,r)
__device__ float  g_uatt[BB * 64];
__device__ float  g_ulin[BB * 64];
__device__ float  g_rproj[N_R * 64];
__device__ float  g_logit[N_EDGES];

// ---------------- helpers ----------------
__device__ __forceinline__ uint32_t smem_u32(const void* p) {
  uint32_t a;
  asm("{ .reg .u64 t; cvta.to.shared.u64 t, %1; cvt.u32.u64 %0, t; }" : "=r"(a) : "l"(p));
  return a;
}
__device__ __forceinline__ void split2(float x, float& hi, float& lo) {
  __nv_bfloat16 h = __float2bfloat16_rn(x);
  hi = __bfloat162float(h);
  lo = x - hi;
}
__device__ __forceinline__ uint32_t pack_bf16(float a, float b) {
  __nv_bfloat162 h = __floats2bfloat162_rn(a, b);
  return *(uint32_t*)&h;
}
// bf16 tile rows: 64 cols = 128B = 8 chunks of 16B; swizzle chunk ^= (row&7)
__device__ __forceinline__ void st_pair(char* base, int row, int cp, uint32_t v) {
  int col = cp * 2;
  uint32_t off = row * 128 + ((((col >> 3) ^ row) & 7) << 4) + ((col & 7) << 1);
  *(uint32_t*)(base + off) = v;
}
// 16-byte store of one full swizzle chunk (8 bf16 cols, col8 % 8 == 0)
__device__ __forceinline__ void st_oct(char* base, int row, int col8,
                                       uint32_t v0, uint32_t v1,
                                       uint32_t v2, uint32_t v3) {
  uint32_t off = row * 128 + ((((col8 >> 3) ^ row) & 7) << 4);
  *(uint4*)(base + off) = make_uint4(v0, v1, v2, v3);
}
__device__ __forceinline__ void ldsm4(uint32_t& r0, uint32_t& r1, uint32_t& r2,
                                      uint32_t& r3, uint32_t addr) {
  asm volatile("ldmatrix.sync.aligned.m8n8.x4.shared.b16 {%0,%1,%2,%3}, [%4];"
               : "=r"(r0), "=r"(r1), "=r"(r2), "=r"(r3) : "r"(addr));
}
__device__ __forceinline__ void stmat4(uint32_t addr, const uint32_t* r) {
  asm volatile("stmatrix.sync.aligned.m8n8.x4.shared.b16 [%0], {%1,%2,%3,%4};"
               :: "r"(addr), "r"(r[0]), "r"(r[1]), "r"(r[2]), "r"(r[3]) : "memory");
}
__device__ __forceinline__ void mma16816(float* c, const uint32_t* a, const uint32_t* b) {
  asm volatile(
      "mma.sync.aligned.m16n8k16.row.col.f32.bf16.bf16.f32 "
      "{%0,%1,%2,%3}, {%4,%5,%6,%7}, {%8,%9}, {%0,%1,%2,%3};"
      : "+f"(c[0]), "+f"(c[1]), "+f"(c[2]), "+f"(c[3])
      : "r"(a[0]), "r"(a[1]), "r"(a[2]), "r"(a[3]), "r"(b[0]), "r"(b[1]));
}

// Warp GEMM: C[32x32] += A[32rows x 64k] @ B[32rows x 64k]^T, 3-term hi/lo bf16.
// k-step outermost: Ah/Bh fragments loaded ONCE per k-step (8 ldsm4/k-step).
__device__ __forceinline__ void warp_gemm_32x32(float c[2][4][4], uint32_t aH, uint32_t aL,
                                                uint32_t bH, uint32_t bL, int m0, int n0,
                                                int lane) {
  const int r = lane & 7, sel = lane >> 3;
  const int arow = r + (sel & 1) * 8, ach = sel >> 1;
  const int brow = r + (sel >> 1) * 8, bch = sel & 1;
#pragma unroll
  for (int mt = 0; mt < 2; mt++)
#pragma unroll
    for (int nt = 0; nt < 4; nt++)
#pragma unroll
      for (int i = 0; i < 4; i++) c[mt][nt][i] = 0.0f;

#pragma unroll
  for (int ks = 0; ks < 4; ks++) {
    const int cha = 2 * ks + ach;
    const int chb = 2 * ks + bch;
    uint32_t ah[2][4], al[2][4], bh[2][4], bl[2][4];
#pragma unroll
    for (int mt = 0; mt < 2; mt++) {
      int rowa = m0 + mt * 16 + arow;
      ldsm4(ah[mt][0], ah[mt][1], ah[mt][2], ah[mt][3],
            aH + rowa * 128 + (((cha ^ rowa) & 7) << 4));
    }
#pragma unroll
    for (int nb = 0; nb < 2; nb++) {
      int rowb = n0 + nb * 16 + brow;
      ldsm4(bh[nb][0], bh[nb][1], bh[nb][2], bh[nb][3],
            bH + rowb * 128 + (((chb ^ rowb) & 7) << 4));
    }
#pragma unroll
    for (int mt = 0; mt < 2; mt++)
#pragma unroll
      for (int nt = 0; nt < 4; nt++)
        mma16816(c[mt][nt], ah[mt], &bh[nt >> 1][(nt & 1) * 2]);
#pragma unroll
    for (int nb = 0; nb < 2; nb++) {
      int rowb = n0 + nb * 16 + brow;
      ldsm4(bl[nb][0], bl[nb][1], bl[nb][2], bl[nb][3],
            bL + rowb * 128 + (((chb ^ rowb) & 7) << 4));
    }
#pragma unroll
    for (int mt = 0; mt < 2; mt++)
#pragma unroll
      for (int nt = 0; nt < 4; nt++)
        mma16816(c[mt][nt], ah[mt], &bl[nt >> 1][(nt & 1) * 2]);
#pragma unroll
    for (int mt = 0; mt < 2; mt++) {
      int rowa = m0 + mt * 16 + arow;
      ldsm4(al[mt][0], al[mt][1], al[mt][2], al[mt][3],
            aL + rowa * 128 + (((cha ^ rowa) & 7) << 4));
    }
#pragma unroll
    for (int mt = 0; mt < 2; mt++)
#pragma unroll
      for (int nt = 0; nt < 4; nt++)
        mma16816(c[mt][nt], al[mt], &bh[nt >> 1][(nt & 1) * 2]);
  }
}

// Split 8 floats and store one hi + one lo 16B chunk.
__device__ __forceinline__ void build_oct(char* hiB, char* loB, int row, int col8,
                                          const float* v) {
  float h[8], l[8];
#pragma unroll
  for (int j = 0; j < 8; j++) split2(v[j], h[j], l[j]);
  st_oct(hiB, row, col8, pack_bf16(h[0], h[1]), pack_bf16(h[2], h[3]),
         pack_bf16(h[4], h[5]), pack_bf16(h[6], h[7]));
  st_oct(loB, row, col8, pack_bf16(l[0], l[1]), pack_bf16(l[2], l[3]),
         pack_bf16(l[4], l[5]), pack_bf16(l[6], l[7]));
}

// ---------------- K_P (mma.sync): P = i2e @ W_r1a^T ----------------
#define PB_AH 0
#define PB_AL 16384
#define PB_WH 32768
#define PB_WL 40960
#define PB_TOTAL 49152

__global__ __launch_bounds__(256, 2) void k_P_mma(
    const float* __restrict__ i2e, const float* __restrict__ wr1) {
  extern __shared__ char smc[];
  const int t = threadIdx.x;
  const int lane = t & 31, w = t >> 5;
  uint32_t sb = smem_u32(smc);

  for (int i = t; i < 2048; i += 256) {
    int n = i >> 5, c2 = i & 31;
    float h0, l0, h1, l1;
    split2(wr1[n * 128 + 2 * c2], h0, l0);
    split2(wr1[n * 128 + 2 * c2 + 1], h1, l1);
    st_pair(smc + PB_WH, n, c2, pack_bf16(h0, h1));
    st_pair(smc + PB_WL, n, c2, pack_bf16(l0, l1));
  }
  __syncthreads();

  const int rowi = t & 127;
  const int chalf = t >> 7;
  const int mh = w & 3, nh = w >> 2;
  const int m0 = mh * 32, n0 = nh * 32;
  const int g = lane >> 2, q = lane & 3;
  float* gP = (float*)g_P;

  for (int tile = blockIdx.x; tile < N_P_TILES; tile += gridDim.x) {
    const long blk0 = (long)tile * 128;
    {
      long row = blk0 + rowi;
      long rc = (row < N_ITEMS) ? row : (N_ITEMS - 1);
      const float4* Ep = (const float4*)&i2e[rc * 64] + chalf * 8;
#pragma unroll
      for (int i = 0; i < 4; i++) {
        float4 p0 = Ep[2 * i], p1 = Ep[2 * i + 1];
        float v[8] = {p0.x, p0.y, p0.z, p0.w, p1.x, p1.y, p1.z, p1.w};
        build_oct(smc + PB_AH, smc + PB_AL, rowi, chalf * 32 + 8 * i, v);
      }
    }
    __syncthreads();

    float c[2][4][4];
    warp_gemm_32x32(c, sb + PB_AH, sb + PB_AL, sb + PB_WH, sb + PB_WL, m0, n0, lane);
#pragma unroll
    for (int mt = 0; mt < 2; mt++)
#pragma unroll
      for (int half = 0; half < 2; half++) {
        int lr = m0 + mt * 16 + g + half * 8;
        long rowg = blk0 + lr;
        if (rowg < N_ITEMS) {
#pragma unroll
          for (int nt = 0; nt < 4; nt++) {
            int col = n0 + nt * 8 + q * 2;
            *(float2*)&gP[rowg * 64 + col] =
                make_float2(c[mt][nt][half * 2 + 0], c[mt][nt][half * 2 + 1]);
          }
        }
      }
    __syncthreads();
  }
}

// ---------------- K_R ----------------
__global__ void k_rproj(const float* __restrict__ wr1,
                        const float* __restrict__ wr1b,
                        const float* __restrict__ r2e) {
  int t = threadIdx.x;
  if (t < N_R * 64) {
    int r = t >> 6, d = t & 63;
    float acc = wr1b[d];
#pragma unroll
    for (int k = 0; k < 64; k++)
      acc = fmaf(wr1[d * 128 + 64 + k], r2e[r * 64 + k], acc);
    g_rproj[r * 64 + d] = acc;
  }
}

// ---------------- K_U ----------------
__global__ __launch_bounds__(256) void k_utab(
    const int* __restrict__ nodes, const float* __restrict__ u2e,
    const float* __restrict__ att1, const float* __restrict__ att1b,
    const float* __restrict__ lin1, const float* __restrict__ lin1b) {
  __shared__ float a_s[64 * 65];
  __shared__ float l_s[64 * 65];
  __shared__ float u_s[4 * 64];
  const int t = threadIdx.x;

  for (int i = t; i < 4096; i += 256) {
    int d = i >> 6, k = i & 63;
    a_s[d * 65 + k] = att1[d * 128 + 64 + k];
    l_s[d * 65 + k] = lin1[d * 128 + k];
  }
  const int b0 = blockIdx.x * 64;
  const int bb = t >> 6, d = t & 63;
  for (int it = 0; it < 16; it++) {
    __syncthreads();
    {
      int b = b0 + it * 4 + bb;
      u_s[t] = u2e[(long)nodes[b] * 64 + d];
    }
    __syncthreads();
    const float* uu = &u_s[bb * 64];
    float au = att1b[d], lu = lin1b[d];
#pragma unroll
    for (int k = 0; k < 64; k++) {
      float uv = uu[k];
      au = fmaf(a_s[d * 65 + k], uv, au);
      lu = fmaf(l_s[d * 65 + k], uv, lu);
    }
    int b = b0 + it * 4 + bb;
    g_uatt[b * 64 + d] = au;
    g_ulin[b * 64 + d] = lu;
  }
}

// ---------------- K_TAB (mma.sync, persistent, stmatrix epilogue) ----------------
#define TB_AH 0
#define TB_AL 16384
#define TB_OH 32768
#define TB_OL 49152
#define TB_W1H 65536
#define TB_W1L 73728
#define TB_W2H 81920
#define TB_W2L 90112
#define TB_RP 98304
#define TB_B2 99584
#define TB_TOTAL 99840

__global__ __launch_bounds__(256, 2) void k_tab_mma(
    const float* __restrict__ wr2, const float* __restrict__ wr2b,
    const float* __restrict__ att1) {
  extern __shared__ char smc[];
  const int t = threadIdx.x;
  const int lane = t & 31, w = t >> 5;
  uint32_t sb = smem_u32(smc);

  for (int i = t; i < 2048; i += 256) {
    int n = i >> 5, c2 = i & 31;
    float h0, l0, h1, l1;
    split2(wr2[n * 64 + 2 * c2], h0, l0);
    split2(wr2[n * 64 + 2 * c2 + 1], h1, l1);
    st_pair(smc + TB_W1H, n, c2, pack_bf16(h0, h1));
    st_pair(smc + TB_W1L, n, c2, pack_bf16(l0, l1));
    split2(att1[n * 128 + 2 * c2], h0, l0);
    split2(att1[n * 128 + 2 * c2 + 1], h1, l1);
    st_pair(smc + TB_W2H, n, c2, pack_bf16(h0, h1));
    st_pair(smc + TB_W2L, n, c2, pack_bf16(l0, l1));
  }
  for (int i = t; i < N_R * 64; i += 256) ((float*)(smc + TB_RP))[i] = g_rproj[i];
  if (t < 64) ((float*)(smc + TB_B2))[t] = wr2b[t];
  __syncthreads();

  const int rowi = t & 127;
  const int chalf = t >> 7;
  const int mh = w & 3, nh = w >> 2;
  const int m0 = mh * 32, n0 = nh * 32;
  const int g = lane >> 2, q = lane & 3;
  const float* b2 = (const float*)(smc + TB_B2);
  float* ot = (float*)g_otab;
  float* at = (float*)g_a1tab;
  const int sm_nt = lane >> 3, sm_r = lane & 7;

  for (int tile = blockIdx.x; tile < N_TAB_TILES; tile += gridDim.x) {
    const long blk0 = (long)tile * 128;
    {
      long row = blk0 + rowi;
      long rc = (row < N_PAIRS) ? row : (N_PAIRS - 1);
      int item = (int)(rc / 5);
      int rr_ = (int)(rc - (long)item * 5);
      const float4* Pp = &g_P[(long)item * 16 + chalf * 8];
      const float* rp = (const float*)(smc + TB_RP) + rr_ * 64 + chalf * 32;
#pragma unroll
      for (int i = 0; i < 4; i++) {
        float4 p0 = Pp[2 * i], p1 = Pp[2 * i + 1];
        const float* rpp = rp + 8 * i;
        float v[8] = {fmaxf(p0.x + rpp[0], 0.f), fmaxf(p0.y + rpp[1], 0.f),
                      fmaxf(p0.z + rpp[2], 0.f), fmaxf(p0.w + rpp[3], 0.f),
                      fmaxf(p1.x + rpp[4], 0.f), fmaxf(p1.y + rpp[5], 0.f),
                      fmaxf(p1.z + rpp[6], 0.f), fmaxf(p1.w + rpp[7], 0.f)};
        build_oct(smc + TB_AH, smc + TB_AL, rowi, chalf * 32 + 8 * i, v);
      }
    }
    __syncthreads();

    float c[2][4][4];
    warp_gemm_32x32(c, sb + TB_AH, sb + TB_AL, sb + TB_W1H, sb + TB_W1L, m0, n0, lane);

    // epilogue 1: gmem otab + stmatrix into O tiles
#pragma unroll
    for (int mt = 0; mt < 2; mt++)
#pragma unroll
      for (int half = 0; half < 2; half++) {
        int lr = m0 + mt * 16 + g + half * 8;
        long rowg = blk0 + lr;
        uint32_t hi4[4], lo4[4];
#pragma unroll
        for (int nt = 0; nt < 4; nt++) {
          int col = n0 + nt * 8 + q * 2;
          float v0 = fmaxf(c[mt][nt][half * 2 + 0] + b2[col], 0.f);
          float v1 = fmaxf(c[mt][nt][half * 2 + 1] + b2[col + 1], 0.f);
          if (rowg < N_PAIRS)
            *(float2*)&ot[rowg * 64 + col] = make_float2(v0, v1);
          float h0, l0, h1, l1;
          split2(v0, h0, l0); split2(v1, h1, l1);
          hi4[nt] = pack_bf16(h0, h1);
          lo4[nt] = pack_bf16(l0, l1);
        }
        int srow = m0 + mt * 16 + half * 8 + sm_r;
        int ch = (n0 >> 3) + sm_nt;
        uint32_t off = srow * 128 + (((ch ^ srow) & 7) << 4);
        stmat4(sb + TB_OH + off, hi4);
        stmat4(sb + TB_OL + off, lo4);
      }
    __syncthreads();

    warp_gemm_32x32(c, sb + TB_OH, sb + TB_OL, sb + TB_W2H, sb + TB_W2L, m0, n0, lane);
#pragma unroll
    for (int mt = 0; mt < 2; mt++)
#pragma unroll
      for (int half = 0; half < 2; half++) {
        int lr = m0 + mt * 16 + g + half * 8;
        long rowg = blk0 + lr;
        if (rowg < N_PAIRS) {
#pragma unroll
          for (int nt = 0; nt < 4; nt++) {
            int col = n0 + nt * 8 + q * 2;
            *(float2*)&at[rowg * 64 + col] =
                make_float2(c[mt][nt][half * 2 + 0], c[mt][nt][half * 2 + 1]);
          }
        }
      }
  }
}

// ---------------- K_LOGIT (mma.sync, persistent, DOUBLE-BUFFERED A tiles) ----------------
// A tiles: buf0 hi@0 lo@16384; buf1 hi@32768 lo@49152
#define LB_WH 65536
#define LB_WL 73728
#define LB_A3 81920
#define LB_A2B 82176
#define LB_A3B 82432
#define LB_PART 82448     // 2 buffers x 256 floats = 2048 B
#define LB_TOTAL 84496

__device__ __forceinline__ void logit_build(char* smc, uint32_t aoff, int tile,
                                            int rowi, int chalf,
                                            const int* __restrict__ hui,
                                            const int* __restrict__ hr) {
  const int e = tile * 128 + rowi;
  int b = e / HH;
  long ir = (long)hui[e] * 5 + hr[e];
  const float4* Ag = &g_a1tab[ir * 16 + chalf * 8];
  const float4* Ug = (const float4*)&g_uatt[b * 64] + chalf * 8;
#pragma unroll
  for (int i = 0; i < 4; i++) {
    float4 p0 = Ag[2 * i], p1 = Ag[2 * i + 1];
    float4 q0 = Ug[2 * i], q1 = Ug[2 * i + 1];
    float v[8] = {fmaxf(p0.x + q0.x, 0.f), fmaxf(p0.y + q0.y, 0.f),
                  fmaxf(p0.z + q0.z, 0.f), fmaxf(p0.w + q0.w, 0.f),
                  fmaxf(p1.x + q1.x, 0.f), fmaxf(p1.y + q1.y, 0.f),
                  fmaxf(p1.z + q1.z, 0.f), fmaxf(p1.w + q1.w, 0.f)};
    build_oct(smc + aoff, smc + aoff + 16384, rowi, chalf * 32 + 8 * i, v);
  }
}

__global__ __launch_bounds__(256, 2) void k_logit_mma(
    const int* __restrict__ hui, const int* __restrict__ hr,
    const float* __restrict__ att2w, const float* __restrict__ att2b_,
    const float* __restrict__ att3w, const float* __restrict__ att3b_) {
  extern __shared__ char smc[];
  const int t = threadIdx.x;
  const int lane = t & 31, w = t >> 5;
  uint32_t sb = smem_u32(smc);

  for (int i = t; i < 2048; i += 256) {
    int n = i >> 5, c2 = i & 31;
    float h0, l0, h1, l1;
    split2(att2w[n * 64 + 2 * c2], h0, l0);
    split2(att2w[n * 64 + 2 * c2 + 1], h1, l1);
    st_pair(smc + LB_WH, n, c2, pack_bf16(h0, h1));
    st_pair(smc + LB_WL, n, c2, pack_bf16(l0, l1));
  }
  if (t < 64) {
    ((float*)(smc + LB_A3))[t] = att3w[t];
    ((float*)(smc + LB_A2B))[t] = att2b_[t];
  }
  if (t == 0) *(float*)(smc + LB_A3B) = att3b_[0];

  const int rowi = t & 127;
  const int chalf = t >> 7;
  const int mh = w & 3, nh = w >> 2;
  const int m0 = mh * 32, n0 = nh * 32;
  const int g = lane >> 2, q = lane & 3;
  const float* a3 = (const float*)(smc + LB_A3);
  const float* a2b = (const float*)(smc + LB_A2B);

  // prologue: build first tile into buffer 0
  logit_build(smc, 0, blockIdx.x, rowi, chalf, hui, hr);
  __syncthreads();
  const float a3b = *(const float*)(smc + LB_A3B);

  int idx = 0;
  for (int tile = blockIdx.x; tile < N_LOG_TILES; tile += gridDim.x, idx++) {
    const int cur = idx & 1;
    const uint32_t aoff = cur ? 32768u : 0u;
    float* partc = (float*)(smc + LB_PART) + cur * 256;

    float c[2][4][4];
    warp_gemm_32x32(c, sb + aoff, sb + aoff + 16384, sb + LB_WH, sb + LB_WL,
                    m0, n0, lane);

#pragma unroll
    for (int mt = 0; mt < 2; mt++)
#pragma unroll
      for (int half = 0; half < 2; half++) {
        int lr = m0 + mt * 16 + g + half * 8;
        float pt = 0.0f;
#pragma unroll
        for (int nt = 0; nt < 4; nt++) {
          int col = n0 + nt * 8 + q * 2;
          pt = fmaf(a3[col], fmaxf(c[mt][nt][half * 2 + 0] + a2b[col], 0.f), pt);
          pt = fmaf(a3[col + 1], fmaxf(c[mt][nt][half * 2 + 1] + a2b[col + 1], 0.f), pt);
        }
        pt += __shfl_xor_sync(0xffffffffu, pt, 1);
        pt += __shfl_xor_sync(0xffffffffu, pt, 2);
        if (q == 0) partc[lr * 2 + nh] = pt;
      }

    // build NEXT tile into the other buffer (overlaps with other warps' MMA)
    int ntile = tile + gridDim.x;
    if (ntile < N_LOG_TILES)
      logit_build(smc, cur ? 0u : 32768u, ntile, rowi, chalf, hui, hr);

    __syncthreads();   // part[cur] ready; next A buffer ready; buf[cur^1] GEMM done

    if (t < 128)
      g_logit[tile * 128 + t] = partc[t * 2] + partc[t * 2 + 1] + a3b;
  }
}

// ---------------- K_AGG: softmax + weighted o-sum + final linear ----------------
__global__ __launch_bounds__(256) void k_agg(
    const int* __restrict__ hui, const int* __restrict__ hr,
    const float* __restrict__ lin1, float* __restrict__ out) {
  __shared__ float s_lin[64 * 65];
  __shared__ float s_lg[AGG_NB * HH];
  __shared__ float s_pp[AGG_NB * HH];
  __shared__ int   s_ir[AGG_NB * HH];
  __shared__ float s_inv[AGG_NB];
  __shared__ float s_ng[AGG_NB * 64];
  __shared__ float s_ul[AGG_NB * 64];

  const int t = threadIdx.x;
  const int b0 = blockIdx.x * AGG_NB;

  for (int i = t; i < 4096; i += 256) {
    int d = i >> 6, k = i & 63;
    s_lin[d * 65 + k] = lin1[d * 128 + 64 + k];
  }
  for (int i = t; i < AGG_NB * HH; i += 256) {
    int e = b0 * HH + i;
    s_lg[i] = g_logit[e];
    s_ir[i] = hui[e] * 5 + hr[e];
  }
  for (int i = t; i < AGG_NB * 64; i += 256) s_ul[i] = g_ulin[b0 * 64 + i];
  __syncthreads();

  {
    const int wid = t >> 5, lane = t & 31;
#pragma unroll
    for (int rr = 0; rr < 2; rr++) {
      int rowb = wid * 2 + rr;
      const float* L = &s_lg[rowb * HH];
      float v1 = L[lane];
      float v2 = (lane < HH - 32) ? L[32 + lane] : -1e30f;
      float m = fmaxf(v1, v2);
#pragma unroll
      for (int off = 16; off > 0; off >>= 1)
        m = fmaxf(m, __shfl_xor_sync(0xffffffffu, m, off));
      float e1 = __expf(v1 - m);
      float e2 = (lane < HH - 32) ? __expf(v2 - m) : 0.0f;
      s_pp[rowb * HH + lane] = e1;
      if (lane < HH - 32) s_pp[rowb * HH + 32 + lane] = e2;
      float s = e1 + e2;
#pragma unroll
      for (int off = 16; off > 0; off >>= 1)
        s += __shfl_xor_sync(0xffffffffu, s, off);
      if (lane == 0) s_inv[rowb] = 1.0f / s;
    }
  }
  __syncthreads();

  const float2* ot2 = (const float2*)g_otab;
  for (int oi = t; oi < AGG_NB * 32; oi += 256) {
    int bl = oi >> 5, dp = oi & 31;
    const float* pr = &s_pp[bl * HH];
    const int* irr = &s_ir[bl * HH];
    float ax = 0.0f, ay = 0.0f;
#pragma unroll 10
    for (int h = 0; h < HH; h++) {
      float2 v = ot2[(long)irr[h] * 32 + dp];
      float p = pr[h];
      ax = fmaf(p, v.x, ax);
      ay = fmaf(p, v.y, ay);
    }
    float inv = s_inv[bl];
    s_ng[bl * 64 + dp * 2] = ax * inv;
    s_ng[bl * 64 + dp * 2 + 1] = ay * inv;
  }
  __syncthreads();

  for (int oi = t; oi < AGG_NB * 64; oi += 256) {
    int bl = oi >> 6, d = oi & 63;
    float acc = s_ul[oi];
    const float* ng = &s_ng[bl * 64];
#pragma unroll
    for (int k = 0; k < 64; k++)
      acc = fmaf(s_lin[d * 65 + k], ng[k], acc);
    out[(long)(b0 + bl) * 64 + d] = fmaxf(acc, 0.0f);
  }
}

extern "C" void kernel_launch(void* const* d_in, const int* in_sizes, int n_in,
                              void* d_out, int out_size) {
  const int*   nodes = (const int*)d_in[0];
  const int*   hui   = (const int*)d_in[1];
  const int*   hr    = (const int*)d_in[2];
  const float* u2e   = (const float*)d_in[3];
  const float* i2e   = (const float*)d_in[4];
  const float* r2e   = (const float*)d_in[5];
  const float* wr1   = (const float*)d_in[6];
  const float* wr1b  = (const float*)d_in[7];
  const float* wr2   = (const float*)d_in[8];
  const float* wr2b  = (const float*)d_in[9];
  const float* att1  = (const float*)d_in[10];
  const float* att1b = (const float*)d_in[11];
  const float* att2  = (const float*)d_in[12];
  const float* att2b = (const float*)d_in[13];
  const float* att3  = (const float*)d_in[14];
  const float* att3b = (const float*)d_in[15];
  const float* lin1  = (const float*)d_in[16];
  const float* lin1b = (const float*)d_in[17];
  float* out = (float*)d_out;

  cudaFuncSetAttribute(k_P_mma, cudaFuncAttributeMaxDynamicSharedMemorySize, PB_TOTAL);
  cudaFuncSetAttribute(k_tab_mma, cudaFuncAttributeMaxDynamicSharedMemorySize, TB_TOTAL);
  cudaFuncSetAttribute(k_logit_mma, cudaFuncAttributeMaxDynamicSharedMemorySize, LB_TOTAL);

  k_P_mma<<<PERSIST_GRID, 256, PB_TOTAL>>>(i2e, wr1);
  k_rproj<<<1, 320>>>(wr1, wr1b, r2e);
  k_utab<<<BB / 64, 256>>>(nodes, u2e, att1, att1b, lin1, lin1b);
  k_tab_mma<<<PERSIST_GRID, 256, TB_TOTAL>>>(wr2, wr2b, att1);
  k_logit_mma<<<PERSIST_GRID, 256, LB_TOTAL>>>(hui, hr, att2, att2b, att3, att3b);
  k_agg<<<BB / AGG_NB, 256>>>(hui, hr, lin1, out);
}

// round 17
// speedup vs baseline: 4.2784x; 1.1084x over previous
#include <cuda_runtime.h>
#include <cuda_bf16.h>
#include <cstdint>

#define BB 16384
#define HH 50
#define N_ITEMS 100000
#define N_R 5
#define N_PAIRS (N_ITEMS * N_R)
#define N_EDGES (BB * HH)
#define AGG_NB 16
#define N_TAB_TILES ((N_PAIRS + 127) / 128)
#define N_LOG_TILES (N_EDGES / 128)
#define N_P_TILES ((N_ITEMS + 127) / 128)
#define N_U_TILES (BB / 128)
#define PERSIST_GRID 296

// ---------------- persistent device tables ----------------
__device__ float4 g_P[N_ITEMS * 16];       // W_r1a @ i2e[item]
__device__ float4 g_otab[N_PAIRS * 16];    // o per (item,r)
__device__ float4 g_a1tab[N_PAIRS * 16];   // att1a @ o per (item,r)
__device__ float  g_uatt[BB * 64];
__device__ float  g_ulin[BB * 64];
__device__ float  g_rproj[N_R * 64];
__device__ float  g_logit[N_EDGES];

// ---------------- helpers ----------------
__device__ __forceinline__ uint32_t smem_u32(const void* p) {
  uint32_t a;
  asm("{ .reg .u64 t; cvta.to.shared.u64 t, %1; cvt.u32.u64 %0, t; }" : "=r"(a) : "l"(p));
  return a;
}
__device__ __forceinline__ void split2(float x, float& hi, float& lo) {
  __nv_bfloat16 h = __float2bfloat16_rn(x);
  hi = __bfloat162float(h);
  lo = x - hi;
}
__device__ __forceinline__ uint32_t pack_bf16(float a, float b) {
  __nv_bfloat162 h = __floats2bfloat162_rn(a, b);
  return *(uint32_t*)&h;
}
// bf16 tile rows: 64 cols = 128B = 8 chunks of 16B; swizzle chunk ^= (row&7)
__device__ __forceinline__ void st_pair(char* base, int row, int cp, uint32_t v) {
  int col = cp * 2;
  uint32_t off = row * 128 + ((((col >> 3) ^ row) & 7) << 4) + ((col & 7) << 1);
  *(uint32_t*)(base + off) = v;
}
// 16-byte store of one full swizzle chunk (8 bf16 cols, col8 % 8 == 0)
__device__ __forceinline__ void st_oct(char* base, int row, int col8,
                                       uint32_t v0, uint32_t v1,
                                       uint32_t v2, uint32_t v3) {
  uint32_t off = row * 128 + ((((col8 >> 3) ^ row) & 7) << 4);
  *(uint4*)(base + off) = make_uint4(v0, v1, v2, v3);
}
__device__ __forceinline__ void ldsm4(uint32_t& r0, uint32_t& r1, uint32_t& r2,
                                      uint32_t& r3, uint32_t addr) {
  asm volatile("ldmatrix.sync.aligned.m8n8.x4.shared.b16 {%0,%1,%2,%3}, [%4];"
               : "=r"(r0), "=r"(r1), "=r"(r2), "=r"(r3) : "r"(addr));
}
__device__ __forceinline__ void stmat4(uint32_t addr, const uint32_t* r) {
  asm volatile("stmatrix.sync.aligned.m8n8.x4.shared.b16 [%0], {%1,%2,%3,%4};"
               :: "r"(addr), "r"(r[0]), "r"(r[1]), "r"(r[2]), "r"(r[3]) : "memory");
}
__device__ __forceinline__ void mma16816(float* c, const uint32_t* a, const uint32_t* b) {
  asm volatile(
      "mma.sync.aligned.m16n8k16.row.col.f32.bf16.bf16.f32 "
      "{%0,%1,%2,%3}, {%4,%5,%6,%7}, {%8,%9}, {%0,%1,%2,%3};"
      : "+f"(c[0]), "+f"(c[1]), "+f"(c[2]), "+f"(c[3])
      : "r"(a[0]), "r"(a[1]), "r"(a[2]), "r"(a[3]), "r"(b[0]), "r"(b[1]));
}

// Warp GEMM: C[32x32] += A[32rows x 64k] @ B[32rows x 64k]^T, 3-term hi/lo bf16.
// k-step outermost: Ah/Bh fragments loaded ONCE per k-step (8 ldsm4/k-step).
__device__ __forceinline__ void warp_gemm_32x32(float c[2][4][4], uint32_t aH, uint32_t aL,
                                                uint32_t bH, uint32_t bL, int m0, int n0,
                                                int lane) {
  const int r = lane & 7, sel = lane >> 3;
  const int arow = r + (sel & 1) * 8, ach = sel >> 1;
  const int brow = r + (sel >> 1) * 8, bch = sel & 1;
#pragma unroll
  for (int mt = 0; mt < 2; mt++)
#pragma unroll
    for (int nt = 0; nt < 4; nt++)
#pragma unroll
      for (int i = 0; i < 4; i++) c[mt][nt][i] = 0.0f;

#pragma unroll
  for (int ks = 0; ks < 4; ks++) {
    const int cha = 2 * ks + ach;
    const int chb = 2 * ks + bch;
    uint32_t ah[2][4], al[2][4], bh[2][4], bl[2][4];
#pragma unroll
    for (int mt = 0; mt < 2; mt++) {
      int rowa = m0 + mt * 16 + arow;
      ldsm4(ah[mt][0], ah[mt][1], ah[mt][2], ah[mt][3],
            aH + rowa * 128 + (((cha ^ rowa) & 7) << 4));
    }
#pragma unroll
    for (int nb = 0; nb < 2; nb++) {
      int rowb = n0 + nb * 16 + brow;
      ldsm4(bh[nb][0], bh[nb][1], bh[nb][2], bh[nb][3],
            bH + rowb * 128 + (((chb ^ rowb) & 7) << 4));
    }
#pragma unroll
    for (int mt = 0; mt < 2; mt++)
#pragma unroll
      for (int nt = 0; nt < 4; nt++)
        mma16816(c[mt][nt], ah[mt], &bh[nt >> 1][(nt & 1) * 2]);
#pragma unroll
    for (int nb = 0; nb < 2; nb++) {
      int rowb = n0 + nb * 16 + brow;
      ldsm4(bl[nb][0], bl[nb][1], bl[nb][2], bl[nb][3],
            bL + rowb * 128 + (((chb ^ rowb) & 7) << 4));
    }
#pragma unroll
    for (int mt = 0; mt < 2; mt++)
#pragma unroll
      for (int nt = 0; nt < 4; nt++)
        mma16816(c[mt][nt], ah[mt], &bl[nt >> 1][(nt & 1) * 2]);
#pragma unroll
    for (int mt = 0; mt < 2; mt++) {
      int rowa = m0 + mt * 16 + arow;
      ldsm4(al[mt][0], al[mt][1], al[mt][2], al[mt][3],
            aL + rowa * 128 + (((cha ^ rowa) & 7) << 4));
    }
#pragma unroll
    for (int mt = 0; mt < 2; mt++)
#pragma unroll
      for (int nt = 0; nt < 4; nt++)
        mma16816(c[mt][nt], al[mt], &bh[nt >> 1][(nt & 1) * 2]);
  }
}

// Split 8 floats and store one hi + one lo 16B chunk.
__device__ __forceinline__ void build_oct(char* hiB, char* loB, int row, int col8,
                                          const float* v) {
  float h[8], l[8];
#pragma unroll
  for (int j = 0; j < 8; j++) split2(v[j], h[j], l[j]);
  st_oct(hiB, row, col8, pack_bf16(h[0], h[1]), pack_bf16(h[2], h[3]),
         pack_bf16(h[4], h[5]), pack_bf16(h[6], h[7]));
  st_oct(loB, row, col8, pack_bf16(l[0], l[1]), pack_bf16(l[2], l[3]),
         pack_bf16(l[4], l[5]), pack_bf16(l[6], l[7]));
}

// ---------------- K_P (mma.sync): P = i2e @ W_r1a^T  (+ rproj in block 0) ----------------
#define PB_AH 0
#define PB_AL 16384
#define PB_WH 32768
#define PB_WL 40960
#define PB_TOTAL 49152

__global__ __launch_bounds__(256, 2) void k_P_mma(
    const float* __restrict__ i2e, const float* __restrict__ wr1,
    const float* __restrict__ wr1b, const float* __restrict__ r2e) {
  extern __shared__ char smc[];
  const int t = threadIdx.x;
  const int lane = t & 31, w = t >> 5;
  uint32_t sb = smem_u32(smc);

  for (int i = t; i < 2048; i += 256) {
    int n = i >> 5, c2 = i & 31;
    float h0, l0, h1, l1;
    split2(wr1[n * 128 + 2 * c2], h0, l0);
    split2(wr1[n * 128 + 2 * c2 + 1], h1, l1);
    st_pair(smc + PB_WH, n, c2, pack_bf16(h0, h1));
    st_pair(smc + PB_WL, n, c2, pack_bf16(l0, l1));
  }
  __syncthreads();

  const int rowi = t & 127;
  const int chalf = t >> 7;
  const int mh = w & 3, nh = w >> 2;
  const int m0 = mh * 32, n0 = nh * 32;
  const int g = lane >> 2, q = lane & 3;
  float* gP = (float*)g_P;

  for (int tile = blockIdx.x; tile < N_P_TILES; tile += gridDim.x) {
    const long blk0 = (long)tile * 128;
    {
      long row = blk0 + rowi;
      long rc = (row < N_ITEMS) ? row : (N_ITEMS - 1);
      const float4* Ep = (const float4*)&i2e[rc * 64] + chalf * 8;
#pragma unroll
      for (int i = 0; i < 4; i++) {
        float4 p0 = Ep[2 * i], p1 = Ep[2 * i + 1];
        float v[8] = {p0.x, p0.y, p0.z, p0.w, p1.x, p1.y, p1.z, p1.w};
        build_oct(smc + PB_AH, smc + PB_AL, rowi, chalf * 32 + 8 * i, v);
      }
    }
    __syncthreads();

    float c[2][4][4];
    warp_gemm_32x32(c, sb + PB_AH, sb + PB_AL, sb + PB_WH, sb + PB_WL, m0, n0, lane);
#pragma unroll
    for (int mt = 0; mt < 2; mt++)
#pragma unroll
      for (int half = 0; half < 2; half++) {
        int lr = m0 + mt * 16 + g + half * 8;
        long rowg = blk0 + lr;
        if (rowg < N_ITEMS) {
#pragma unroll
          for (int nt = 0; nt < 4; nt++) {
            int col = n0 + nt * 8 + q * 2;
            *(float2*)&gP[rowg * 64 + col] =
                make_float2(c[mt][nt][half * 2 + 0], c[mt][nt][half * 2 + 1]);
          }
        }
      }
    __syncthreads();
  }

  // block 0: rproj[r][d] = W_r1b @ r2e[r] + b1 (scalar, tiny; consumed by later k_tab launch)
  if (blockIdx.x == 0) {
    for (int i = t; i < N_R * 64; i += 256) {
      int r = i >> 6, d = i & 63;
      float acc = wr1b[d];
#pragma unroll
      for (int k = 0; k < 64; k++)
        acc = fmaf(wr1[d * 128 + 64 + k], r2e[r * 64 + k], acc);
      g_rproj[i] = acc;
    }
  }
}

// ---------------- K_UTAB (mma.sync): uatt/ulin = u2e[nodes] @ {att1bh, lin1a}^T ----------------
#define UB_AH 0
#define UB_AL 16384
#define UB_W1H 32768
#define UB_W1L 40960
#define UB_W2H 49152
#define UB_W2L 57344
#define UB_B1 65536      // att1b (256 B)
#define UB_B2 65792      // lin1b (256 B)
#define UB_TOTAL 66048

__global__ __launch_bounds__(256, 2) void k_utab_mma(
    const int* __restrict__ nodes, const float* __restrict__ u2e,
    const float* __restrict__ att1, const float* __restrict__ att1b,
    const float* __restrict__ lin1, const float* __restrict__ lin1b) {
  extern __shared__ char smc[];
  const int t = threadIdx.x;
  const int lane = t & 31, w = t >> 5;
  uint32_t sb = smem_u32(smc);

  // W1 = att1[:, 64:128], W2 = lin1[:, 0:64]
  for (int i = t; i < 2048; i += 256) {
    int n = i >> 5, c2 = i & 31;
    float h0, l0, h1, l1;
    split2(att1[n * 128 + 64 + 2 * c2], h0, l0);
    split2(att1[n * 128 + 64 + 2 * c2 + 1], h1, l1);
    st_pair(smc + UB_W1H, n, c2, pack_bf16(h0, h1));
    st_pair(smc + UB_W1L, n, c2, pack_bf16(l0, l1));
    split2(lin1[n * 128 + 2 * c2], h0, l0);
    split2(lin1[n * 128 + 2 * c2 + 1], h1, l1);
    st_pair(smc + UB_W2H, n, c2, pack_bf16(h0, h1));
    st_pair(smc + UB_W2L, n, c2, pack_bf16(l0, l1));
  }
  if (t < 64) {
    ((float*)(smc + UB_B1))[t] = att1b[t];
    ((float*)(smc + UB_B2))[t] = lin1b[t];
  }
  __syncthreads();

  const int rowi = t & 127;
  const int chalf = t >> 7;
  const int mh = w & 3, nh = w >> 2;
  const int m0 = mh * 32, n0 = nh * 32;
  const int g = lane >> 2, q = lane & 3;
  const float* b1 = (const float*)(smc + UB_B1);
  const float* b2 = (const float*)(smc + UB_B2);

  for (int tile = blockIdx.x; tile < N_U_TILES; tile += gridDim.x) {
    const int blk0 = tile * 128;
    {
      int row = blk0 + rowi;
      long node = nodes[row];
      const float4* Up = (const float4*)&u2e[node * 64] + chalf * 8;
#pragma unroll
      for (int i = 0; i < 4; i++) {
        float4 p0 = Up[2 * i], p1 = Up[2 * i + 1];
        float v[8] = {p0.x, p0.y, p0.z, p0.w, p1.x, p1.y, p1.z, p1.w};
        build_oct(smc + UB_AH, smc + UB_AL, rowi, chalf * 32 + 8 * i, v);
      }
    }
    __syncthreads();

    float c[2][4][4];
    // GEMM1: uatt = u @ att1bh^T + att1b   (no relu)
    warp_gemm_32x32(c, sb + UB_AH, sb + UB_AL, sb + UB_W1H, sb + UB_W1L, m0, n0, lane);
#pragma unroll
    for (int mt = 0; mt < 2; mt++)
#pragma unroll
      for (int half = 0; half < 2; half++) {
        int lr = m0 + mt * 16 + g + half * 8;
        int rowg = blk0 + lr;
#pragma unroll
        for (int nt = 0; nt < 4; nt++) {
          int col = n0 + nt * 8 + q * 2;
          *(float2*)&g_uatt[rowg * 64 + col] =
              make_float2(c[mt][nt][half * 2 + 0] + b1[col],
                          c[mt][nt][half * 2 + 1] + b1[col + 1]);
        }
      }
    // GEMM2: ulin = u @ lin1a^T + lin1b  (same A tile — no barrier needed)
    warp_gemm_32x32(c, sb + UB_AH, sb + UB_AL, sb + UB_W2H, sb + UB_W2L, m0, n0, lane);
#pragma unroll
    for (int mt = 0; mt < 2; mt++)
#pragma unroll
      for (int half = 0; half < 2; half++) {
        int lr = m0 + mt * 16 + g + half * 8;
        int rowg = blk0 + lr;
#pragma unroll
        for (int nt = 0; nt < 4; nt++) {
          int col = n0 + nt * 8 + q * 2;
          *(float2*)&g_ulin[rowg * 64 + col] =
              make_float2(c[mt][nt][half * 2 + 0] + b2[col],
                          c[mt][nt][half * 2 + 1] + b2[col + 1]);
        }
      }
    __syncthreads();   // all GEMM reads of A done before next tile's build
  }
}

// ---------------- K_TAB (mma.sync, persistent, stmatrix epilogue) ----------------
#define TB_AH 0
#define TB_AL 16384
#define TB_OH 32768
#define TB_OL 49152
#define TB_W1H 65536
#define TB_W1L 73728
#define TB_W2H 81920
#define TB_W2L 90112
#define TB_RP 98304
#define TB_B2 99584
#define TB_TOTAL 99840

__global__ __launch_bounds__(256, 2) void k_tab_mma(
    const float* __restrict__ wr2, const float* __restrict__ wr2b,
    const float* __restrict__ att1) {
  extern __shared__ char smc[];
  const int t = threadIdx.x;
  const int lane = t & 31, w = t >> 5;
  uint32_t sb = smem_u32(smc);

  for (int i = t; i < 2048; i += 256) {
    int n = i >> 5, c2 = i & 31;
    float h0, l0, h1, l1;
    split2(wr2[n * 64 + 2 * c2], h0, l0);
    split2(wr2[n * 64 + 2 * c2 + 1], h1, l1);
    st_pair(smc + TB_W1H, n, c2, pack_bf16(h0, h1));
    st_pair(smc + TB_W1L, n, c2, pack_bf16(l0, l1));
    split2(att1[n * 128 + 2 * c2], h0, l0);
    split2(att1[n * 128 + 2 * c2 + 1], h1, l1);
    st_pair(smc + TB_W2H, n, c2, pack_bf16(h0, h1));
    st_pair(smc + TB_W2L, n, c2, pack_bf16(l0, l1));
  }
  for (int i = t; i < N_R * 64; i += 256) ((float*)(smc + TB_RP))[i] = g_rproj[i];
  if (t < 64) ((float*)(smc + TB_B2))[t] = wr2b[t];
  __syncthreads();

  const int rowi = t & 127;
  const int chalf = t >> 7;
  const int mh = w & 3, nh = w >> 2;
  const int m0 = mh * 32, n0 = nh * 32;
  const int g = lane >> 2, q = lane & 3;
  const float* b2 = (const float*)(smc + TB_B2);
  float* ot = (float*)g_otab;
  float* at = (float*)g_a1tab;
  const int sm_nt = lane >> 3, sm_r = lane & 7;

  for (int tile = blockIdx.x; tile < N_TAB_TILES; tile += gridDim.x) {
    const long blk0 = (long)tile * 128;
    {
      long row = blk0 + rowi;
      long rc = (row < N_PAIRS) ? row : (N_PAIRS - 1);
      int item = (int)(rc / 5);
      int rr_ = (int)(rc - (long)item * 5);
      const float4* Pp = &g_P[(long)item * 16 + chalf * 8];
      const float* rp = (const float*)(smc + TB_RP) + rr_ * 64 + chalf * 32;
#pragma unroll
      for (int i = 0; i < 4; i++) {
        float4 p0 = Pp[2 * i], p1 = Pp[2 * i + 1];
        const float* rpp = rp + 8 * i;
        float v[8] = {fmaxf(p0.x + rpp[0], 0.f), fmaxf(p0.y + rpp[1], 0.f),
                      fmaxf(p0.z + rpp[2], 0.f), fmaxf(p0.w + rpp[3], 0.f),
                      fmaxf(p1.x + rpp[4], 0.f), fmaxf(p1.y + rpp[5], 0.f),
                      fmaxf(p1.z + rpp[6], 0.f), fmaxf(p1.w + rpp[7], 0.f)};
        build_oct(smc + TB_AH, smc + TB_AL, rowi, chalf * 32 + 8 * i, v);
      }
    }
    __syncthreads();

    float c[2][4][4];
    warp_gemm_32x32(c, sb + TB_AH, sb + TB_AL, sb + TB_W1H, sb + TB_W1L, m0, n0, lane);

    // epilogue 1: gmem otab + stmatrix into O tiles
#pragma unroll
    for (int mt = 0; mt < 2; mt++)
#pragma unroll
      for (int half = 0; half < 2; half++) {
        int lr = m0 + mt * 16 + g + half * 8;
        long rowg = blk0 + lr;
        uint32_t hi4[4], lo4[4];
#pragma unroll
        for (int nt = 0; nt < 4; nt++) {
          int col = n0 + nt * 8 + q * 2;
          float v0 = fmaxf(c[mt][nt][half * 2 + 0] + b2[col], 0.f);
          float v1 = fmaxf(c[mt][nt][half * 2 + 1] + b2[col + 1], 0.f);
          if (rowg < N_PAIRS)
            *(float2*)&ot[rowg * 64 + col] = make_float2(v0, v1);
          float h0, l0, h1, l1;
          split2(v0, h0, l0); split2(v1, h1, l1);
          hi4[nt] = pack_bf16(h0, h1);
          lo4[nt] = pack_bf16(l0, l1);
        }
        int srow = m0 + mt * 16 + half * 8 + sm_r;
        int ch = (n0 >> 3) + sm_nt;
        uint32_t off = srow * 128 + (((ch ^ srow) & 7) << 4);
        stmat4(sb + TB_OH + off, hi4);
        stmat4(sb + TB_OL + off, lo4);
      }
    __syncthreads();

    warp_gemm_32x32(c, sb + TB_OH, sb + TB_OL, sb + TB_W2H, sb + TB_W2L, m0, n0, lane);
#pragma unroll
    for (int mt = 0; mt < 2; mt++)
#pragma unroll
      for (int half = 0; half < 2; half++) {
        int lr = m0 + mt * 16 + g + half * 8;
        long rowg = blk0 + lr;
        if (rowg < N_PAIRS) {
#pragma unroll
          for (int nt = 0; nt < 4; nt++) {
            int col = n0 + nt * 8 + q * 2;
            *(float2*)&at[rowg * 64 + col] =
                make_float2(c[mt][nt][half * 2 + 0], c[mt][nt][half * 2 + 1]);
          }
        }
      }
  }
}

// ---------------- K_LOGIT (mma.sync, persistent, double-buffered A tiles) ----------------
#define LB_WH 65536
#define LB_WL 73728
#define LB_A3 81920
#define LB_A2B 82176
#define LB_A3B 82432
#define LB_PART 82448
#define LB_TOTAL 84496

__device__ __forceinline__ void logit_build(char* smc, uint32_t aoff, int tile,
                                            int rowi, int chalf,
                                            const int* __restrict__ hui,
                                            const int* __restrict__ hr) {
  const int e = tile * 128 + rowi;
  int b = e / HH;
  long ir = (long)hui[e] * 5 + hr[e];
  const float4* Ag = &g_a1tab[ir * 16 + chalf * 8];
  const float4* Ug = (const float4*)&g_uatt[b * 64] + chalf * 8;
#pragma unroll
  for (int i = 0; i < 4; i++) {
    float4 p0 = Ag[2 * i], p1 = Ag[2 * i + 1];
    float4 q0 = Ug[2 * i], q1 = Ug[2 * i + 1];
    float v[8] = {fmaxf(p0.x + q0.x, 0.f), fmaxf(p0.y + q0.y, 0.f),
                  fmaxf(p0.z + q0.z, 0.f), fmaxf(p0.w + q0.w, 0.f),
                  fmaxf(p1.x + q1.x, 0.f), fmaxf(p1.y + q1.y, 0.f),
                  fmaxf(p1.z + q1.z, 0.f), fmaxf(p1.w + q1.w, 0.f)};
    build_oct(smc + aoff, smc + aoff + 16384, rowi, chalf * 32 + 8 * i, v);
  }
}

__global__ __launch_bounds__(256, 2) void k_logit_mma(
    const int* __restrict__ hui, const int* __restrict__ hr,
    const float* __restrict__ att2w, const float* __restrict__ att2b_,
    const float* __restrict__ att3w, const float* __restrict__ att3b_) {
  extern __shared__ char smc[];
  const int t = threadIdx.x;
  const int lane = t & 31, w = t >> 5;
  uint32_t sb = smem_u32(smc);

  for (int i = t; i < 2048; i += 256) {
    int n = i >> 5, c2 = i & 31;
    float h0, l0, h1, l1;
    split2(att2w[n * 64 + 2 * c2], h0, l0);
    split2(att2w[n * 64 + 2 * c2 + 1], h1, l1);
    st_pair(smc + LB_WH, n, c2, pack_bf16(h0, h1));
    st_pair(smc + LB_WL, n, c2, pack_bf16(l0, l1));
  }
  if (t < 64) {
    ((float*)(smc + LB_A3))[t] = att3w[t];
    ((float*)(smc + LB_A2B))[t] = att2b_[t];
  }
  if (t == 0) *(float*)(smc + LB_A3B) = att3b_[0];

  const int rowi = t & 127;
  const int chalf = t >> 7;
  const int mh = w & 3, nh = w >> 2;
  const int m0 = mh * 32, n0 = nh * 32;
  const int g = lane >> 2, q = lane & 3;
  const float* a3 = (const float*)(smc + LB_A3);
  const float* a2b = (const float*)(smc + LB_A2B);

  logit_build(smc, 0, blockIdx.x, rowi, chalf, hui, hr);
  __syncthreads();
  const float a3b = *(const float*)(smc + LB_A3B);

  int idx = 0;
  for (int tile = blockIdx.x; tile < N_LOG_TILES; tile += gridDim.x, idx++) {
    const int cur = idx & 1;
    const uint32_t aoff = cur ? 32768u : 0u;
    float* partc = (float*)(smc + LB_PART) + cur * 256;

    float c[2][4][4];
    warp_gemm_32x32(c, sb + aoff, sb + aoff + 16384, sb + LB_WH, sb + LB_WL,
                    m0, n0, lane);

#pragma unroll
    for (int mt = 0; mt < 2; mt++)
#pragma unroll
      for (int half = 0; half < 2; half++) {
        int lr = m0 + mt * 16 + g + half * 8;
        float pt = 0.0f;
#pragma unroll
        for (int nt = 0; nt < 4; nt++) {
          int col = n0 + nt * 8 + q * 2;
          pt = fmaf(a3[col], fmaxf(c[mt][nt][half * 2 + 0] + a2b[col], 0.f), pt);
          pt = fmaf(a3[col + 1], fmaxf(c[mt][nt][half * 2 + 1] + a2b[col + 1], 0.f), pt);
        }
        pt += __shfl_xor_sync(0xffffffffu, pt, 1);
        pt += __shfl_xor_sync(0xffffffffu, pt, 2);
        if (q == 0) partc[lr * 2 + nh] = pt;
      }

    int ntile = tile + gridDim.x;
    if (ntile < N_LOG_TILES)
      logit_build(smc, cur ? 0u : 32768u, ntile, rowi, chalf, hui, hr);

    __syncthreads();

    if (t < 128)
      g_logit[tile * 128 + t] = partc[t * 2] + partc[t * 2 + 1] + a3b;
  }
}

// ---------------- K_AGG: softmax + weighted o-sum + final linear ----------------
__global__ __launch_bounds__(256) void k_agg(
    const int* __restrict__ hui, const int* __restrict__ hr,
    const float* __restrict__ lin1, float* __restrict__ out) {
  __shared__ float s_lin[64 * 65];
  __shared__ float s_lg[AGG_NB * HH];
  __shared__ float s_pp[AGG_NB * HH];
  __shared__ int   s_ir[AGG_NB * HH];
  __shared__ float s_inv[AGG_NB];
  __shared__ float s_ng[AGG_NB * 64];
  __shared__ float s_ul[AGG_NB * 64];

  const int t = threadIdx.x;
  const int b0 = blockIdx.x * AGG_NB;

  for (int i = t; i < 4096; i += 256) {
    int d = i >> 6, k = i & 63;
    s_lin[d * 65 + k] = lin1[d * 128 + 64 + k];
  }
  for (int i = t; i < AGG_NB * HH; i += 256) {
    int e = b0 * HH + i;
    s_lg[i] = g_logit[e];
    s_ir[i] = hui[e] * 5 + hr[e];
  }
  for (int i = t; i < AGG_NB * 64; i += 256) s_ul[i] = g_ulin[b0 * 64 + i];
  __syncthreads();

  {
    const int wid = t >> 5, lane = t & 31;
#pragma unroll
    for (int rr = 0; rr < 2; rr++) {
      int rowb = wid * 2 + rr;
      const float* L = &s_lg[rowb * HH];
      float v1 = L[lane];
      float v2 = (lane < HH - 32) ? L[32 + lane] : -1e30f;
      float m = fmaxf(v1, v2);
#pragma unroll
      for (int off = 16; off > 0; off >>= 1)
        m = fmaxf(m, __shfl_xor_sync(0xffffffffu, m, off));
      float e1 = __expf(v1 - m);
      float e2 = (lane < HH - 32) ? __expf(v2 - m) : 0.0f;
      s_pp[rowb * HH + lane] = e1;
      if (lane < HH - 32) s_pp[rowb * HH + 32 + lane] = e2;
      float s = e1 + e2;
#pragma unroll
      for (int off = 16; off > 0; off >>= 1)
        s += __shfl_xor_sync(0xffffffffu, s, off);
      if (lane == 0) s_inv[rowb] = 1.0f / s;
    }
  }
  __syncthreads();

  // neigh: each thread owns a 4-col chunk (float4 gathers -> 4x payload per load)
  const float4* ot4 = (const float4*)g_otab;
  for (int oi = t; oi < AGG_NB * 16; oi += 256) {
    int bl = oi >> 4, dq = oi & 15;
    const float* pr = &s_pp[bl * HH];
    const int* irr = &s_ir[bl * HH];
    float a0 = 0.f, a1 = 0.f, a2 = 0.f, a3 = 0.f;
#pragma unroll 10
    for (int h = 0; h < HH; h++) {
      float4 v = ot4[(long)irr[h] * 16 + dq];
      float p = pr[h];
      a0 = fmaf(p, v.x, a0);
      a1 = fmaf(p, v.y, a1);
      a2 = fmaf(p, v.z, a2);
      a3 = fmaf(p, v.w, a3);
    }
    float inv = s_inv[bl];
    *(float4*)&s_ng[bl * 64 + dq * 4] =
        make_float4(a0 * inv, a1 * inv, a2 * inv, a3 * inv);
  }
  __syncthreads();

  for (int oi = t; oi < AGG_NB * 64; oi += 256) {
    int bl = oi >> 6, d = oi & 63;
    float acc = s_ul[oi];
    const float* ng = &s_ng[bl * 64];
#pragma unroll
    for (int k = 0; k < 64; k++)
      acc = fmaf(s_lin[d * 65 + k], ng[k], acc);
    out[(long)(b0 + bl) * 64 + d] = fmaxf(acc, 0.0f);
  }
}

extern "C" void kernel_launch(void* const* d_in, const int* in_sizes, int n_in,
                              void* d_out, int out_size) {
  const int*   nodes = (const int*)d_in[0];
  const int*   hui   = (const int*)d_in[1];
  const int*   hr    = (const int*)d_in[2];
  const float* u2e   = (const float*)d_in[3];
  const float* i2e   = (const float*)d_in[4];
  const float* r2e   = (const float*)d_in[5];
  const float* wr1   = (const float*)d_in[6];
  const float* wr1b  = (const float*)d_in[7];
  const float* wr2   = (const float*)d_in[8];
  const float* wr2b  = (const float*)d_in[9];
  const float* att1  = (const float*)d_in[10];
  const float* att1b = (const float*)d_in[11];
  const float* att2  = (const float*)d_in[12];
  const float* att2b = (const float*)d_in[13];
  const float* att3  = (const float*)d_in[14];
  const float* att3b = (const float*)d_in[15];
  const float* lin1  = (const float*)d_in[16];
  const float* lin1b = (const float*)d_in[17];
  float* out = (float*)d_out;

  cudaFuncSetAttribute(k_P_mma, cudaFuncAttributeMaxDynamicSharedMemorySize, PB_TOTAL);
  cudaFuncSetAttribute(k_utab_mma, cudaFuncAttributeMaxDynamicSharedMemorySize, UB_TOTAL);
  cudaFuncSetAttribute(k_tab_mma, cudaFuncAttributeMaxDynamicSharedMemorySize, TB_TOTAL);
  cudaFuncSetAttribute(k_logit_mma, cudaFuncAttributeMaxDynamicSharedMemorySize, LB_TOTAL);

  k_P_mma<<<PERSIST_GRID, 256, PB_TOTAL>>>(i2e, wr1, wr1b, r2e);
  k_utab_mma<<<N_U_TILES, 256, UB_TOTAL>>>(nodes, u2e, att1, att1b, lin1, lin1b);
  k_tab_mma<<<PERSIST_GRID, 256, TB_TOTAL>>>(wr2, wr2b, att1);
  k_logit_mma<<<PERSIST_GRID, 256, LB_TOTAL>>>(hui, hr, att2, att2b, att3, att3b);
  k_agg<<<BB / AGG_NB, 256>>>(hui, hr, lin1, out);
}